// round 2
// baseline (speedup 1.0000x reference)
#include <cuda_runtime.h>
#include <math.h>

// ---------------- problem constants ----------------
#define B_SZ   4
#define LEN    4096
#define HID    1024
#define STATE  16
#define KCONV  4
#define INNER  2048
#define M_TOT  (B_SZ * LEN)      // 16384
#define NC     16                // scan chunks
#define LC     256               // chunk length (NC*LC == LEN)

// ---------------- scratch (no cudaMalloc allowed) ----------------
__device__ float g_xz   [(size_t)M_TOT * 2 * INNER];   // in-proj output (x_part | z)
__device__ float g_xconv[(size_t)M_TOT * INNER];       // conv+silu output
__device__ float g_dt   [(size_t)M_TOT * INNER];       // softplus(dt)
__device__ float g_Bm   [(size_t)M_TOT * STATE];
__device__ float g_Cm   [(size_t)M_TOT * STATE];
__device__ float g_y    [(size_t)M_TOT * INNER];       // gated scan output
__device__ float g_P    [(size_t)B_SZ * NC * STATE * INNER];
__device__ float g_S    [(size_t)B_SZ * NC * STATE * INNER];
__device__ float g_H0   [(size_t)B_SZ * NC * STATE * INNER];

// ---------------- helpers ----------------
__device__ __forceinline__ float2 ffma2(float2 a, float2 b, float2 c) {
    float2 d;
    asm("fma.rn.f32x2 %0, %1, %2, %3;"
        : "=l"(*reinterpret_cast<unsigned long long*>(&d))
        : "l"(*reinterpret_cast<unsigned long long*>(&a)),
          "l"(*reinterpret_cast<unsigned long long*>(&b)),
          "l"(*reinterpret_cast<unsigned long long*>(&c)));
    return d;
}
__device__ __forceinline__ float2 dup2(float a) {
    float2 d;
    asm("mov.b64 %0, {%1, %1};"
        : "=l"(*reinterpret_cast<unsigned long long*>(&d)) : "f"(a));
    return d;
}
__device__ __forceinline__ float softplusf(float v) {
    return v > 20.f ? v : log1pf(__expf(v));
}
__device__ __forceinline__ float siluf(float v) {
    return v / (1.f + __expf(-v));
}

// ---------------- generic NT SGEMM: C[M,N] = A[M,K] * Bw[N,K]^T + bias ----------------
// EPI: 0 = bias, 1 = bias + softplus
template <int EPI>
__global__ void __launch_bounds__(256, 2) sgemm_nt(
    const float* __restrict__ A, const float* __restrict__ Bw,
    const float* __restrict__ bias, float* __restrict__ C,
    int M, int N, int Kd)
{
    const int BM = 128, BN = 128, BK = 16;
    __shared__ float As[2][BK][BM];
    __shared__ float Bs[2][BK][BN];

    const int tid  = threadIdx.x;
    const int bm   = blockIdx.y * BM;
    const int bn   = blockIdx.x * BN;
    const int lrow = tid & 127;
    const int lkv  = tid >> 7;       // 0/1
    const int tx   = tid & 15;
    const int ty   = tid >> 4;
    const int K4   = Kd >> 2;
    const float4* A4 = reinterpret_cast<const float4*>(A);
    const float4* B4 = reinterpret_cast<const float4*>(Bw);

    float2 acc[8][4];
#pragma unroll
    for (int i = 0; i < 8; i++)
#pragma unroll
        for (int j = 0; j < 4; j++) acc[i][j] = make_float2(0.f, 0.f);

    float4 ra[2], rb[2];
#pragma unroll
    for (int i = 0; i < 2; i++) {
        ra[i] = A4[(size_t)(bm + lrow) * K4 + (lkv + 2 * i)];
        rb[i] = B4[(size_t)(bn + lrow) * K4 + (lkv + 2 * i)];
    }
#pragma unroll
    for (int i = 0; i < 2; i++) {
        int kv = lkv + 2 * i;
        As[0][kv * 4 + 0][lrow] = ra[i].x; As[0][kv * 4 + 1][lrow] = ra[i].y;
        As[0][kv * 4 + 2][lrow] = ra[i].z; As[0][kv * 4 + 3][lrow] = ra[i].w;
        Bs[0][kv * 4 + 0][lrow] = rb[i].x; Bs[0][kv * 4 + 1][lrow] = rb[i].y;
        Bs[0][kv * 4 + 2][lrow] = rb[i].z; Bs[0][kv * 4 + 3][lrow] = rb[i].w;
    }
    __syncthreads();

    const int KT = Kd / BK;
    int buf = 0;
    for (int kt = 0; kt < KT; ++kt) {
        if (kt + 1 < KT) {
#pragma unroll
            for (int i = 0; i < 2; i++) {
                ra[i] = A4[(size_t)(bm + lrow) * K4 + (kt + 1) * 4 + (lkv + 2 * i)];
                rb[i] = B4[(size_t)(bn + lrow) * K4 + (kt + 1) * 4 + (lkv + 2 * i)];
            }
        }
#pragma unroll
        for (int k = 0; k < BK; k++) {
            float4 a0 = *(const float4*)&As[buf][k][ty * 4];
            float4 a1 = *(const float4*)&As[buf][k][64 + ty * 4];
            float4 b0 = *(const float4*)&Bs[buf][k][tx * 4];
            float4 b1 = *(const float4*)&Bs[buf][k][64 + tx * 4];
            float  av[8] = {a0.x, a0.y, a0.z, a0.w, a1.x, a1.y, a1.z, a1.w};
            float2 bv[4] = {make_float2(b0.x, b0.y), make_float2(b0.z, b0.w),
                            make_float2(b1.x, b1.y), make_float2(b1.z, b1.w)};
#pragma unroll
            for (int i = 0; i < 8; i++) {
                float2 aa = dup2(av[i]);
#pragma unroll
                for (int j = 0; j < 4; j++) acc[i][j] = ffma2(aa, bv[j], acc[i][j]);
            }
        }
        if (kt + 1 < KT) {
            int nb = buf ^ 1;
#pragma unroll
            for (int i = 0; i < 2; i++) {
                int kv = lkv + 2 * i;
                As[nb][kv * 4 + 0][lrow] = ra[i].x; As[nb][kv * 4 + 1][lrow] = ra[i].y;
                As[nb][kv * 4 + 2][lrow] = ra[i].z; As[nb][kv * 4 + 3][lrow] = ra[i].w;
                Bs[nb][kv * 4 + 0][lrow] = rb[i].x; Bs[nb][kv * 4 + 1][lrow] = rb[i].y;
                Bs[nb][kv * 4 + 2][lrow] = rb[i].z; Bs[nb][kv * 4 + 3][lrow] = rb[i].w;
            }
            __syncthreads();
            buf = nb;
        }
    }

    // epilogue
#pragma unroll
    for (int i = 0; i < 8; i++) {
        int row = bm + ((i < 4) ? (ty * 4 + i) : (64 + ty * 4 + (i - 4)));
#pragma unroll
        for (int j = 0; j < 4; j++) {
            int col = bn + ((j < 2) ? (tx * 4 + j * 2) : (64 + tx * 4 + (j - 2) * 2));
            float v0 = acc[i][j].x + bias[col];
            float v1 = acc[i][j].y + bias[col + 1];
            if (EPI == 1) { v0 = softplusf(v0); v1 = softplusf(v1); }
            *reinterpret_cast<float2*>(&C[(size_t)row * N + col]) = make_float2(v0, v1);
        }
    }
}

// ---------------- causal depthwise conv (K=4) + SiLU ----------------
// grid (INNER/256, LEN/128, B), block 256
__global__ void __launch_bounds__(256) conv_silu_kernel(
    const float* __restrict__ conv_w, const float* __restrict__ conv_b)
{
    const int d  = blockIdx.x * 256 + threadIdx.x;
    const int l0 = blockIdx.y * 128;
    const int b  = blockIdx.z;

    const float w0 = conv_w[d * 4 + 0];
    const float w1 = conv_w[d * 4 + 1];
    const float w2 = conv_w[d * 4 + 2];
    const float w3 = conv_w[d * 4 + 3];
    const float cb = conv_b[d];

    const float* xp = g_xz + (size_t)(b * LEN) * (2 * INNER) + d;   // x_part column d
    float m3, m2, m1;
    if (l0 == 0) { m3 = m2 = m1 = 0.f; }
    else {
        m3 = xp[(size_t)(l0 - 3) * (2 * INNER)];
        m2 = xp[(size_t)(l0 - 2) * (2 * INNER)];
        m1 = xp[(size_t)(l0 - 1) * (2 * INNER)];
    }
    float* xc = g_xconv + (size_t)(b * LEN + l0) * INNER + d;
#pragma unroll 4
    for (int i = 0; i < 128; ++i) {
        float cur = xp[(size_t)(l0 + i) * (2 * INNER)];
        float v = w0 * m3 + w1 * m2 + w2 * m1 + w3 * cur + cb;
        xc[(size_t)i * INNER] = siluf(v);
        m3 = m2; m2 = m1; m1 = cur;
    }
}

// ---------------- B/C projection: [M,32] = xconv[M,2048] @ [Bw;Cw]^T ----------------
// grid M/32, block 256
__global__ void __launch_bounds__(256) bc_gemm(
    const float* __restrict__ Bw, const float* __restrict__ Cw,
    const float* __restrict__ Bb, const float* __restrict__ Cb)
{
    __shared__ float As[32][65];
    __shared__ float Ws[32][65];
    const int tid = threadIdx.x;
    const int m0  = blockIdx.x * 32;
    const int r   = tid >> 3;          // row 0..31
    const int og  = (tid & 7) * 4;     // out base 0..28

    float acc0 = 0.f, acc1 = 0.f, acc2 = 0.f, acc3 = 0.f;
    for (int kc = 0; kc < INNER / 64; ++kc) {
        for (int i = tid; i < 32 * 64; i += 256)
            As[i >> 6][i & 63] = g_xconv[(size_t)(m0 + (i >> 6)) * INNER + kc * 64 + (i & 63)];
        for (int i = tid; i < 16 * 64; i += 256) {
            Ws[i >> 6][i & 63]        = Bw[(size_t)(i >> 6) * INNER + kc * 64 + (i & 63)];
            Ws[16 + (i >> 6)][i & 63] = Cw[(size_t)(i >> 6) * INNER + kc * 64 + (i & 63)];
        }
        __syncthreads();
#pragma unroll 8
        for (int k = 0; k < 64; ++k) {
            float a = As[r][k];
            acc0 = fmaf(a, Ws[og + 0][k], acc0);
            acc1 = fmaf(a, Ws[og + 1][k], acc1);
            acc2 = fmaf(a, Ws[og + 2][k], acc2);
            acc3 = fmaf(a, Ws[og + 3][k], acc3);
        }
        __syncthreads();
    }
    float accs[4] = {acc0, acc1, acc2, acc3};
#pragma unroll
    for (int j = 0; j < 4; ++j) {
        int o = og + j;
        if (o < 16) g_Bm[(size_t)(m0 + r) * STATE + o]        = accs[j] + Bb[o];
        else        g_Cm[(size_t)(m0 + r) * STATE + (o - 16)] = accs[j] + Cb[o - 16];
    }
}

// ---------------- chunked selective scan ----------------
// pass A: per-chunk decay product P and local end-state S (h0 = 0)
// grid (INNER/128, NC, B), block 128
__global__ void __launch_bounds__(128) scanA_kernel(const float* __restrict__ A_log)
{
    __shared__ float sB[LC * STATE];
    const int d = blockIdx.x * 128 + threadIdx.x;
    const int c = blockIdx.y;
    const int b = blockIdx.z;
    const int base_l = c * LC;

    for (int i = threadIdx.x; i < LC * STATE; i += 128)
        sB[i] = g_Bm[(size_t)(b * LEN + base_l) * STATE + i];
    __syncthreads();

    float Ar[STATE];
#pragma unroll
    for (int s = 0; s < STATE; s++) Ar[s] = -expf(A_log[d * STATE + s]);

    float h[STATE], Pr[STATE];
#pragma unroll
    for (int s = 0; s < STATE; s++) { h[s] = 0.f; Pr[s] = 1.f; }

    const float* dtp = g_dt    + (size_t)(b * LEN + base_l) * INNER + d;
    const float* xcp = g_xconv + (size_t)(b * LEN + base_l) * INNER + d;
    for (int l = 0; l < LC; ++l) {
        float dtv = dtp[(size_t)l * INNER];
        float xv  = xcp[(size_t)l * INNER];
        float dtx = dtv * xv;
#pragma unroll
        for (int s = 0; s < STATE; s++) {
            float dA = __expf(dtv * Ar[s]);
            Pr[s] *= dA;
            h[s] = fmaf(dA, h[s], sB[l * STATE + s] * dtx);
        }
    }
    size_t ob = (size_t)(b * NC + c) * STATE * INNER + d;
#pragma unroll
    for (int s = 0; s < STATE; s++) {
        g_P[ob + (size_t)s * INNER] = Pr[s];
        g_S[ob + (size_t)s * INNER] = h[s];
    }
}

// pass B: stitch chunk boundary states. one thread per (b, s, d)
__global__ void __launch_bounds__(256) scanB_kernel()
{
    int g = blockIdx.x * 256 + threadIdx.x;              // 0 .. B*STATE*INNER-1
    int b = g / (STATE * INNER);
    int r = g - b * (STATE * INNER);
    float h = 0.f;
    for (int c = 0; c < NC; ++c) {
        size_t idx = (size_t)(b * NC + c) * STATE * INNER + r;
        g_H0[idx] = h;
        h = g_P[idx] * h + g_S[idx];
    }
}

// pass C: replay with correct h0, produce gated output
// grid (INNER/128, NC, B), block 128
__global__ void __launch_bounds__(128) scanC_kernel(
    const float* __restrict__ A_log, const float* __restrict__ Dv)
{
    __shared__ float sB[LC * STATE];
    __shared__ float sC[LC * STATE];
    const int d = blockIdx.x * 128 + threadIdx.x;
    const int c = blockIdx.y;
    const int b = blockIdx.z;
    const int base_l = c * LC;

    for (int i = threadIdx.x; i < LC * STATE; i += 128) {
        sB[i] = g_Bm[(size_t)(b * LEN + base_l) * STATE + i];
        sC[i] = g_Cm[(size_t)(b * LEN + base_l) * STATE + i];
    }
    __syncthreads();

    float Ar[STATE];
#pragma unroll
    for (int s = 0; s < STATE; s++) Ar[s] = -expf(A_log[d * STATE + s]);
    const float Dd = Dv[d];

    float h[STATE];
    size_t ob = (size_t)(b * NC + c) * STATE * INNER + d;
#pragma unroll
    for (int s = 0; s < STATE; s++) h[s] = g_H0[ob + (size_t)s * INNER];

    const float* dtp = g_dt    + (size_t)(b * LEN + base_l) * INNER + d;
    const float* xcp = g_xconv + (size_t)(b * LEN + base_l) * INNER + d;
    const float* zp  = g_xz    + (size_t)(b * LEN + base_l) * (2 * INNER) + INNER + d;
    float*       yp  = g_y     + (size_t)(b * LEN + base_l) * INNER + d;

    for (int l = 0; l < LC; ++l) {
        float dtv = dtp[(size_t)l * INNER];
        float xv  = xcp[(size_t)l * INNER];
        float zv  = zp[(size_t)l * (2 * INNER)];
        float dtx = dtv * xv;
        float acc = Dd * xv;
#pragma unroll
        for (int s = 0; s < STATE; s++) {
            float dA = __expf(dtv * Ar[s]);
            h[s] = fmaf(dA, h[s], sB[l * STATE + s] * dtx);
            acc  = fmaf(sC[l * STATE + s], h[s], acc);
        }
        yp[(size_t)l * INNER] = acc * siluf(zv);
    }
}

// ---------------- launch ----------------
extern "C" void kernel_launch(void* const* d_in, const int* in_sizes, int n_in,
                              void* d_out, int out_size)
{
    const float* x      = (const float*)d_in[0];
    const float* in_w   = (const float*)d_in[1];
    const float* in_b   = (const float*)d_in[2];
    const float* conv_w = (const float*)d_in[3];
    const float* conv_b = (const float*)d_in[4];
    const float* dt_w   = (const float*)d_in[5];
    const float* dt_b   = (const float*)d_in[6];
    const float* A_log  = (const float*)d_in[7];
    const float* B_w    = (const float*)d_in[8];
    const float* B_b    = (const float*)d_in[9];
    const float* C_w    = (const float*)d_in[10];
    const float* C_b    = (const float*)d_in[11];
    const float* Dv     = (const float*)d_in[12];
    const float* out_w  = (const float*)d_in[13];
    const float* out_b  = (const float*)d_in[14];
    float* out = (float*)d_out;

    float *xz, *xc, *dt, *y;
    cudaGetSymbolAddress((void**)&xz, g_xz);
    cudaGetSymbolAddress((void**)&xc, g_xconv);
    cudaGetSymbolAddress((void**)&dt, g_dt);
    cudaGetSymbolAddress((void**)&y,  g_y);

    // 1) in-proj: xz = x @ in_w^T + in_b          (16384 x 4096 x 1024)
    sgemm_nt<0><<<dim3(4096 / 128, M_TOT / 128), 256>>>(x, in_w, in_b, xz, M_TOT, 4096, HID);

    // 2) causal depthwise conv + silu
    conv_silu_kernel<<<dim3(INNER / 256, LEN / 128, B_SZ), 256>>>(conv_w, conv_b);

    // 3) dt = softplus(xconv @ dt_w^T + dt_b)     (16384 x 2048 x 2048)
    sgemm_nt<1><<<dim3(INNER / 128, M_TOT / 128), 256>>>(xc, dt_w, dt_b, dt, M_TOT, INNER, INNER);

    // 4) B/C projections (N = 32)
    bc_gemm<<<M_TOT / 32, 256>>>(B_w, C_w, B_b, C_b);

    // 5) chunked selective scan + z-gating
    scanA_kernel<<<dim3(INNER / 128, NC, B_SZ), 128>>>(A_log);
    scanB_kernel<<<(B_SZ * STATE * INNER) / 256, 256>>>();
    scanC_kernel<<<dim3(INNER / 128, NC, B_SZ), 128>>>(A_log, Dv);

    // 6) out-proj: out = y @ out_w^T + out_b      (16384 x 1024 x 2048)
    sgemm_nt<0><<<dim3(HID / 128, M_TOT / 128), 256>>>(y, out_w, out_b, out, M_TOT, HID, INNER);
}

// round 4
// speedup vs baseline: 2.5730x; 2.5730x over previous
#include <cuda_runtime.h>
#include <cuda_bf16.h>
#include <math.h>
#include <stdint.h>

#define B_SZ   4
#define LEN    4096
#define HID    1024
#define STATE  16
#define INNER  2048
#define M_TOT  (B_SZ * LEN)
#define NC     16
#define LC     256

// ---------------- scratch ----------------
__device__ __align__(1024) float g_xz   [(size_t)M_TOT * 2 * INNER];
__device__ __align__(1024) float g_xconv[(size_t)M_TOT * INNER];
__device__ __align__(1024) float g_dt   [(size_t)M_TOT * INNER];
__device__ __align__(1024) float g_Bm   [(size_t)M_TOT * STATE];
__device__ __align__(1024) float g_Cm   [(size_t)M_TOT * STATE];
__device__ __align__(1024) float g_P [(size_t)B_SZ * NC * STATE * INNER];
__device__ __align__(1024) float g_S [(size_t)B_SZ * NC * STATE * INNER];
__device__ __align__(1024) float g_H0[(size_t)B_SZ * NC * STATE * INNER];
__device__ __align__(1024) __nv_bfloat16 g_x0 [(size_t)M_TOT * HID];
__device__ __align__(1024) __nv_bfloat16 g_x1 [(size_t)M_TOT * HID];
__device__ __align__(1024) __nv_bfloat16 g_w0 [(size_t)2 * INNER * HID];
__device__ __align__(1024) __nv_bfloat16 g_w1 [(size_t)2 * INNER * HID];
__device__ __align__(1024) __nv_bfloat16 g_dtw0[(size_t)INNER * INNER];
__device__ __align__(1024) __nv_bfloat16 g_xc0 [(size_t)M_TOT * INNER];
__device__ __align__(1024) __nv_bfloat16 g_y0  [(size_t)M_TOT * INNER];
__device__ __align__(1024) __nv_bfloat16 g_y1  [(size_t)M_TOT * INNER];
__device__ __align__(1024) __nv_bfloat16 g_ow0 [(size_t)HID * INNER];
__device__ __align__(1024) __nv_bfloat16 g_ow1 [(size_t)HID * INNER];

// ---------------- PTX helpers ----------------
__device__ __forceinline__ uint32_t smem_u32(const void* p) {
    uint32_t a;
    asm("{ .reg .u64 t; cvta.to.shared.u64 t, %1; cvt.u32.u64 %0, t; }" : "=r"(a) : "l"(p));
    return a;
}
__device__ __forceinline__ void cp_async16(uint32_t dst, const void* src) {
    asm volatile("cp.async.cg.shared.global [%0], [%1], 16;" :: "r"(dst), "l"(src) : "memory");
}
#define CP_COMMIT() asm volatile("cp.async.commit_group;" ::: "memory")
#define CP_WAIT1()  asm volatile("cp.async.wait_group 1;" ::: "memory")

__device__ __forceinline__ void ldm_x4(uint32_t* r, uint32_t addr) {
    asm volatile("ldmatrix.sync.aligned.m8n8.x4.shared.b16 {%0,%1,%2,%3}, [%4];"
        : "=r"(r[0]), "=r"(r[1]), "=r"(r[2]), "=r"(r[3]) : "r"(addr));
}
__device__ __forceinline__ void mma16816(float* d, const uint32_t* a, const uint32_t* b) {
    asm volatile("mma.sync.aligned.m16n8k16.row.col.f32.bf16.bf16.f32 "
        "{%0,%1,%2,%3}, {%4,%5,%6,%7}, {%8,%9}, {%0,%1,%2,%3};"
        : "+f"(d[0]), "+f"(d[1]), "+f"(d[2]), "+f"(d[3])
        : "r"(a[0]), "r"(a[1]), "r"(a[2]), "r"(a[3]), "r"(b[0]), "r"(b[1]));
}
__device__ __forceinline__ float softplusf(float v) { return v > 20.f ? v : log1pf(__expf(v)); }
__device__ __forceinline__ float siluf(float v)     { return v / (1.f + __expf(-v)); }

// ---------------- bf16 mma.sync GEMM: C[M,N] = sum_p A_p[M,K] @ B_p[N,K]^T + bias ----------------
// BM=128, BN=256, BK=64 (128B SW128 rows), 8 warps of 64x64 tiles, 3-stage cp.async.
#define GBM 128
#define GBN 256
#define GAST (GBM * 128)            // 16KB A per stage
#define GSTG (GAST + GBN * 128)     // 48KB per stage
#define GSMEM (3 * GSTG)            // 144KB

template <int PASSES, int EPI>
__global__ void __launch_bounds__(256, 1) gemm_mma(
    const __nv_bfloat16* __restrict__ Ap0, const __nv_bfloat16* __restrict__ Ap1,
    const __nv_bfloat16* __restrict__ Ap2,
    const __nv_bfloat16* __restrict__ Bp0, const __nv_bfloat16* __restrict__ Bp1,
    const __nv_bfloat16* __restrict__ Bp2,
    const float* __restrict__ bias, float* __restrict__ C, int N, int K)
{
    extern __shared__ char smraw[];
    const uint32_t sbase = smem_u32(smraw);
    const int tid  = threadIdx.x;
    const int wid  = tid >> 5;
    const int lane = tid & 31;
    const int bm0  = blockIdx.y * GBM;
    const int bn0  = blockIdx.x * GBN;

    const int KT0 = K >> 6;
    const int KTT = KT0 * PASSES;
    const size_t lda = (size_t)K * 2;
    const char* APS[3] = {(const char*)Ap0, (const char*)Ap1, (const char*)Ap2};
    const char* BPS[3] = {(const char*)Bp0, (const char*)Bp1, (const char*)Bp2};

    auto load_stage = [&](int kt, int s) {
        const int p  = (PASSES == 3) ? (kt / KT0) : 0;
        const int kc = kt - p * KT0;
        const char* Ap = APS[p];
        const char* Bp = BPS[p];
        const uint32_t sa = sbase + s * GSTG;
        const uint32_t sb = sa + GAST;
#pragma unroll
        for (int i = 0; i < 4; ++i) {                   // A: 1024 16B chunks
            int idx = tid + i * 256, r = idx >> 3, c = idx & 7;
            cp_async16(sa + r * 128 + ((c ^ (r & 7)) << 4),
                       Ap + (size_t)(bm0 + r) * lda + (size_t)kc * 128 + c * 16);
        }
#pragma unroll
        for (int i = 0; i < 8; ++i) {                   // B: 2048 chunks
            int idx = tid + i * 256, r = idx >> 3, c = idx & 7;
            cp_async16(sb + r * 128 + ((c ^ (r & 7)) << 4),
                       Bp + (size_t)(bn0 + r) * lda + (size_t)kc * 128 + c * 16);
        }
    };

    float acc[4][8][4];
#pragma unroll
    for (int mt = 0; mt < 4; ++mt)
#pragma unroll
        for (int nt = 0; nt < 8; ++nt)
#pragma unroll
            for (int q = 0; q < 4; ++q) acc[mt][nt][q] = 0.f;

    load_stage(0, 0); CP_COMMIT();
    load_stage(1, 1); CP_COMMIT();

    // warp tile coords and lane-level ldmatrix addressing
    const int wm0 = (wid >> 2) * 64;                    // 0 / 64
    const int wn0 = (wid & 3) * 64;                     // 0..192
    const int aRow = wm0 + ((lane >> 3) & 1) * 8 + (lane & 7);
    const int bRow = wn0 + ((lane >> 4) & 1) * 8 + (lane & 7);
    const int swzX = (lane & 7) << 4;
    const int aKs  = (lane >> 4) << 4;                  // 0 / 16
    const int bKs  = ((lane >> 3) & 1) << 4;            // 0 / 16

    for (int kt = 0; kt < KTT; ++kt) {
        const int s = kt % 3;
        CP_WAIT1();
        __syncthreads();
        if (kt + 2 < KTT) { load_stage(kt + 2, (kt + 2) % 3); CP_COMMIT(); }

        const uint32_t Ab = sbase + s * GSTG;
        const uint32_t Bb = Ab + GAST;
#pragma unroll
        for (int ks = 0; ks < 4; ++ks) {
            const int swA = (ks * 32 + aKs) ^ swzX;
            const int swB = (ks * 32 + bKs) ^ swzX;
            uint32_t a[4][4], b[4][4];
#pragma unroll
            for (int mt = 0; mt < 4; ++mt) ldm_x4(a[mt], Ab + (aRow + mt * 16) * 128 + swA);
#pragma unroll
            for (int np = 0; np < 4; ++np) ldm_x4(b[np], Bb + (bRow + np * 16) * 128 + swB);
#pragma unroll
            for (int mt = 0; mt < 4; ++mt)
#pragma unroll
                for (int nt = 0; nt < 8; ++nt)
                    mma16816(acc[mt][nt], a[mt], &b[nt >> 1][(nt & 1) * 2]);
        }
    }

    // epilogue
#pragma unroll
    for (int nt = 0; nt < 8; ++nt) {
        const int col = bn0 + wn0 + nt * 8 + (lane & 3) * 2;
        const float b0v = bias[col], b1v = bias[col + 1];
#pragma unroll
        for (int mt = 0; mt < 4; ++mt) {
            const int row = bm0 + wm0 + mt * 16 + (lane >> 2);
            float v0 = acc[mt][nt][0] + b0v, v1 = acc[mt][nt][1] + b1v;
            float v2 = acc[mt][nt][2] + b0v, v3 = acc[mt][nt][3] + b1v;
            if (EPI == 1) {
                v0 = softplusf(v0); v1 = softplusf(v1);
                v2 = softplusf(v2); v3 = softplusf(v3);
            }
            *reinterpret_cast<float2*>(&C[(size_t)row * N + col])       = make_float2(v0, v1);
            *reinterpret_cast<float2*>(&C[(size_t)(row + 8) * N + col]) = make_float2(v2, v3);
        }
    }
}

// ---------------- bf16 conversion kernels ----------------
__global__ void __launch_bounds__(256) split2_kernel(
    const float* __restrict__ in, __nv_bfloat16* __restrict__ o0,
    __nv_bfloat16* __restrict__ o1, size_t n4)
{
    for (size_t i = (size_t)blockIdx.x * 256 + threadIdx.x; i < n4; i += (size_t)gridDim.x * 256) {
        float4 v = reinterpret_cast<const float4*>(in)[i];
        __nv_bfloat16 a0 = __float2bfloat16(v.x), b0 = __float2bfloat16(v.y);
        __nv_bfloat16 c0 = __float2bfloat16(v.z), d0 = __float2bfloat16(v.w);
        ((ushort4*)o0)[i] = make_ushort4(__bfloat16_as_ushort(a0), __bfloat16_as_ushort(b0),
                                         __bfloat16_as_ushort(c0), __bfloat16_as_ushort(d0));
        ((ushort4*)o1)[i] = make_ushort4(
            __bfloat16_as_ushort(__float2bfloat16(v.x - __bfloat162float(a0))),
            __bfloat16_as_ushort(__float2bfloat16(v.y - __bfloat162float(b0))),
            __bfloat16_as_ushort(__float2bfloat16(v.z - __bfloat162float(c0))),
            __bfloat16_as_ushort(__float2bfloat16(v.w - __bfloat162float(d0))));
    }
}
__global__ void __launch_bounds__(256) cvt1_kernel(
    const float* __restrict__ in, __nv_bfloat16* __restrict__ o0, size_t n4)
{
    for (size_t i = (size_t)blockIdx.x * 256 + threadIdx.x; i < n4; i += (size_t)gridDim.x * 256) {
        float4 v = reinterpret_cast<const float4*>(in)[i];
        ((ushort4*)o0)[i] = make_ushort4(
            __bfloat16_as_ushort(__float2bfloat16(v.x)), __bfloat16_as_ushort(__float2bfloat16(v.y)),
            __bfloat16_as_ushort(__float2bfloat16(v.z)), __bfloat16_as_ushort(__float2bfloat16(v.w)));
    }
}

// ---------------- causal depthwise conv (K=4) + SiLU ----------------
__global__ void __launch_bounds__(256) conv_silu_kernel(
    const float* __restrict__ conv_w, const float* __restrict__ conv_b)
{
    const int d  = blockIdx.x * 256 + threadIdx.x;
    const int l0 = blockIdx.y * 128;
    const int b  = blockIdx.z;
    const float w0 = conv_w[d * 4 + 0], w1 = conv_w[d * 4 + 1];
    const float w2 = conv_w[d * 4 + 2], w3 = conv_w[d * 4 + 3];
    const float cb = conv_b[d];
    const float* xp = g_xz + (size_t)(b * LEN) * (2 * INNER) + d;
    float m3, m2, m1;
    if (l0 == 0) { m3 = m2 = m1 = 0.f; }
    else {
        m3 = xp[(size_t)(l0 - 3) * (2 * INNER)];
        m2 = xp[(size_t)(l0 - 2) * (2 * INNER)];
        m1 = xp[(size_t)(l0 - 1) * (2 * INNER)];
    }
    float*         xc = g_xconv + (size_t)(b * LEN + l0) * INNER + d;
    __nv_bfloat16* xb = g_xc0   + (size_t)(b * LEN + l0) * INNER + d;
#pragma unroll 4
    for (int i = 0; i < 128; ++i) {
        float cur = xp[(size_t)(l0 + i) * (2 * INNER)];
        float v = siluf(w0 * m3 + w1 * m2 + w2 * m1 + w3 * cur + cb);
        xc[(size_t)i * INNER] = v;
        xb[(size_t)i * INNER] = __float2bfloat16(v);
        m3 = m2; m2 = m1; m1 = cur;
    }
}

// ---------------- B/C projection (fp32, N=32) ----------------
__global__ void __launch_bounds__(256) bc_gemm(
    const float* __restrict__ Bw, const float* __restrict__ Cw,
    const float* __restrict__ Bb, const float* __restrict__ Cb)
{
    __shared__ float As[32][65];
    __shared__ float Ws[32][65];
    const int tid = threadIdx.x;
    const int m0  = blockIdx.x * 32;
    const int r   = tid >> 3;
    const int og  = (tid & 7) * 4;
    float a0 = 0.f, a1 = 0.f, a2 = 0.f, a3 = 0.f;
    for (int kc = 0; kc < INNER / 64; ++kc) {
        for (int i = tid; i < 32 * 64; i += 256)
            As[i >> 6][i & 63] = g_xconv[(size_t)(m0 + (i >> 6)) * INNER + kc * 64 + (i & 63)];
        for (int i = tid; i < 16 * 64; i += 256) {
            Ws[i >> 6][i & 63]        = Bw[(size_t)(i >> 6) * INNER + kc * 64 + (i & 63)];
            Ws[16 + (i >> 6)][i & 63] = Cw[(size_t)(i >> 6) * INNER + kc * 64 + (i & 63)];
        }
        __syncthreads();
#pragma unroll 8
        for (int k = 0; k < 64; ++k) {
            float a = As[r][k];
            a0 = fmaf(a, Ws[og + 0][k], a0); a1 = fmaf(a, Ws[og + 1][k], a1);
            a2 = fmaf(a, Ws[og + 2][k], a2); a3 = fmaf(a, Ws[og + 3][k], a3);
        }
        __syncthreads();
    }
    float accs[4] = {a0, a1, a2, a3};
#pragma unroll
    for (int j = 0; j < 4; ++j) {
        int o = og + j;
        if (o < 16) g_Bm[(size_t)(m0 + r) * STATE + o]        = accs[j] + Bb[o];
        else        g_Cm[(size_t)(m0 + r) * STATE + (o - 16)] = accs[j] + Cb[o - 16];
    }
}

// ---------------- chunked selective scan ----------------
__global__ void __launch_bounds__(128) scanA_kernel(const float* __restrict__ A_log)
{
    __shared__ float sB[LC * STATE];
    const int d = blockIdx.x * 128 + threadIdx.x;
    const int c = blockIdx.y;
    const int b = blockIdx.z;
    const int base_l = c * LC;
    for (int i = threadIdx.x; i < LC * STATE; i += 128)
        sB[i] = g_Bm[(size_t)(b * LEN + base_l) * STATE + i];
    __syncthreads();
    float Ar[STATE];
#pragma unroll
    for (int s = 0; s < STATE; s++) Ar[s] = -expf(A_log[d * STATE + s]);
    float h[STATE], Pr[STATE];
#pragma unroll
    for (int s = 0; s < STATE; s++) { h[s] = 0.f; Pr[s] = 1.f; }
    const float* dtp = g_dt    + (size_t)(b * LEN + base_l) * INNER + d;
    const float* xcp = g_xconv + (size_t)(b * LEN + base_l) * INNER + d;
    for (int l = 0; l < LC; ++l) {
        float dtv = dtp[(size_t)l * INNER];
        float dtx = dtv * xcp[(size_t)l * INNER];
#pragma unroll
        for (int s = 0; s < STATE; s++) {
            float dA = __expf(dtv * Ar[s]);
            Pr[s] *= dA;
            h[s] = fmaf(dA, h[s], sB[l * STATE + s] * dtx);
        }
    }
    size_t ob = (size_t)(b * NC + c) * STATE * INNER + d;
#pragma unroll
    for (int s = 0; s < STATE; s++) {
        g_P[ob + (size_t)s * INNER] = Pr[s];
        g_S[ob + (size_t)s * INNER] = h[s];
    }
}

__global__ void __launch_bounds__(256) scanB_kernel()
{
    int g = blockIdx.x * 256 + threadIdx.x;
    int b = g / (STATE * INNER);
    int r = g - b * (STATE * INNER);
    float h = 0.f;
    for (int c = 0; c < NC; ++c) {
        size_t idx = (size_t)(b * NC + c) * STATE * INNER + r;
        g_H0[idx] = h;
        h = g_P[idx] * h + g_S[idx];
    }
}

__global__ void __launch_bounds__(128) scanC_kernel(
    const float* __restrict__ A_log, const float* __restrict__ Dv)
{
    __shared__ float sB[LC * STATE];
    __shared__ float sC[LC * STATE];
    const int d = blockIdx.x * 128 + threadIdx.x;
    const int c = blockIdx.y;
    const int b = blockIdx.z;
    const int base_l = c * LC;
    for (int i = threadIdx.x; i < LC * STATE; i += 128) {
        sB[i] = g_Bm[(size_t)(b * LEN + base_l) * STATE + i];
        sC[i] = g_Cm[(size_t)(b * LEN + base_l) * STATE + i];
    }
    __syncthreads();
    float Ar[STATE];
#pragma unroll
    for (int s = 0; s < STATE; s++) Ar[s] = -expf(A_log[d * STATE + s]);
    const float Dd = Dv[d];
    float h[STATE];
    size_t ob = (size_t)(b * NC + c) * STATE * INNER + d;
#pragma unroll
    for (int s = 0; s < STATE; s++) h[s] = g_H0[ob + (size_t)s * INNER];
    const float* dtp = g_dt    + (size_t)(b * LEN + base_l) * INNER + d;
    const float* xcp = g_xconv + (size_t)(b * LEN + base_l) * INNER + d;
    const float* zp  = g_xz    + (size_t)(b * LEN + base_l) * (2 * INNER) + INNER + d;
    __nv_bfloat16* y0p = g_y0 + (size_t)(b * LEN + base_l) * INNER + d;
    __nv_bfloat16* y1p = g_y1 + (size_t)(b * LEN + base_l) * INNER + d;
    for (int l = 0; l < LC; ++l) {
        float dtv = dtp[(size_t)l * INNER];
        float xv  = xcp[(size_t)l * INNER];
        float zv  = zp[(size_t)l * (2 * INNER)];
        float dtx = dtv * xv;
        float acc = Dd * xv;
#pragma unroll
        for (int s = 0; s < STATE; s++) {
            float dA = __expf(dtv * Ar[s]);
            h[s] = fmaf(dA, h[s], sB[l * STATE + s] * dtx);
            acc  = fmaf(sC[l * STATE + s], h[s], acc);
        }
        float v = acc * siluf(zv);
        __nv_bfloat16 v0 = __float2bfloat16(v);
        y0p[(size_t)l * INNER] = v0;
        y1p[(size_t)l * INNER] = __float2bfloat16(v - __bfloat162float(v0));
    }
}

// ---------------- launch ----------------
extern "C" void kernel_launch(void* const* d_in, const int* in_sizes, int n_in,
                              void* d_out, int out_size)
{
    const float* x      = (const float*)d_in[0];
    const float* in_w   = (const float*)d_in[1];
    const float* in_b   = (const float*)d_in[2];
    const float* conv_w = (const float*)d_in[3];
    const float* conv_b = (const float*)d_in[4];
    const float* dt_w   = (const float*)d_in[5];
    const float* dt_b   = (const float*)d_in[6];
    const float* A_log  = (const float*)d_in[7];
    const float* B_w    = (const float*)d_in[8];
    const float* B_b    = (const float*)d_in[9];
    const float* C_w    = (const float*)d_in[10];
    const float* C_b    = (const float*)d_in[11];
    const float* Dv     = (const float*)d_in[12];
    const float* out_w  = (const float*)d_in[13];
    const float* out_b  = (const float*)d_in[14];
    float* out = (float*)d_out;

    float *xz, *dt;
    __nv_bfloat16 *x0, *x1, *w0, *w1, *dtw0, *xc0, *y0, *y1, *ow0, *ow1;
    cudaGetSymbolAddress((void**)&xz, g_xz);
    cudaGetSymbolAddress((void**)&dt, g_dt);
    cudaGetSymbolAddress((void**)&x0, g_x0);   cudaGetSymbolAddress((void**)&x1, g_x1);
    cudaGetSymbolAddress((void**)&w0, g_w0);   cudaGetSymbolAddress((void**)&w1, g_w1);
    cudaGetSymbolAddress((void**)&dtw0, g_dtw0);
    cudaGetSymbolAddress((void**)&xc0, g_xc0);
    cudaGetSymbolAddress((void**)&y0, g_y0);   cudaGetSymbolAddress((void**)&y1, g_y1);
    cudaGetSymbolAddress((void**)&ow0, g_ow0); cudaGetSymbolAddress((void**)&ow1, g_ow1);

    cudaFuncSetAttribute(gemm_mma<3, 0>, cudaFuncAttributeMaxDynamicSharedMemorySize, GSMEM);
    cudaFuncSetAttribute(gemm_mma<1, 1>, cudaFuncAttributeMaxDynamicSharedMemorySize, GSMEM);

    // 0) bf16 conversions / splits
    split2_kernel<<<2048, 256>>>(x, x0, x1, (size_t)M_TOT * HID / 4);
    split2_kernel<<<1024, 256>>>(in_w, w0, w1, (size_t)2 * INNER * HID / 4);
    cvt1_kernel<<<1024, 256>>>(dt_w, dtw0, (size_t)INNER * INNER / 4);
    split2_kernel<<<512, 256>>>(out_w, ow0, ow1, (size_t)HID * INNER / 4);

    // 1) in-proj (3-term split): xz = x @ in_w^T + in_b     (16384 x 4096 x 1024)
    gemm_mma<3, 0><<<dim3(4096 / GBN, M_TOT / GBM), 256, GSMEM>>>(
        x0, x0, x1, w0, w1, w0, in_b, xz, 4096, HID);

    // 2) conv + silu
    conv_silu_kernel<<<dim3(INNER / 256, LEN / 128, B_SZ), 256>>>(conv_w, conv_b);

    // 3) dt = softplus(xconv @ dt_w^T + dt_b)               (16384 x 2048 x 2048)
    gemm_mma<1, 1><<<dim3(INNER / GBN, M_TOT / GBM), 256, GSMEM>>>(
        xc0, xc0, xc0, dtw0, dtw0, dtw0, dt_b, dt, INNER, INNER);

    // 4) B/C projections (fp32)
    bc_gemm<<<M_TOT / 32, 256>>>(B_w, C_w, B_b, C_b);

    // 5) chunked selective scan + gating
    scanA_kernel<<<dim3(INNER / 128, NC, B_SZ), 128>>>(A_log);
    scanB_kernel<<<(B_SZ * STATE * INNER) / 256, 256>>>();
    scanC_kernel<<<dim3(INNER / 128, NC, B_SZ), 128>>>(A_log, Dv);

    // 6) out-proj (3-term split): out = y @ out_w^T + out_b (16384 x 1024 x 2048)
    gemm_mma<3, 0><<<dim3(HID / GBN, M_TOT / GBM), 256, GSMEM>>>(
        y0, y0, y1, ow0, ow1, ow0, out_b, out, HID, INNER);
}

// round 5
// speedup vs baseline: 3.3948x; 1.3194x over previous
#include <cuda_runtime.h>
#include <cuda_fp16.h>
#include <math.h>
#include <stdint.h>

#define B_SZ   4
#define LEN    4096
#define HID    1024
#define STATE  16
#define INNER  2048
#define M_TOT  (B_SZ * LEN)
#define NC     16
#define LC     256

// ---------------- scratch ----------------
__device__ __align__(1024) float g_xz   [(size_t)M_TOT * 2 * INNER];
__device__ __align__(1024) float g_xconv[(size_t)M_TOT * INNER];
__device__ __align__(1024) float g_dt   [(size_t)M_TOT * INNER];
__device__ __align__(1024) float g_Bm   [(size_t)M_TOT * STATE];
__device__ __align__(1024) float g_Cm   [(size_t)M_TOT * STATE];
__device__ __align__(1024) float g_P [(size_t)B_SZ * NC * STATE * INNER];
__device__ __align__(1024) float g_S [(size_t)B_SZ * NC * STATE * INNER];
__device__ __align__(1024) float g_H0[(size_t)B_SZ * NC * STATE * INNER];
__device__ __align__(1024) __half g_x0h [(size_t)M_TOT * HID];
__device__ __align__(1024) __half g_x1h [(size_t)M_TOT * HID];
__device__ __align__(1024) __half g_wh  [(size_t)2 * INNER * HID];
__device__ __align__(1024) __half g_dtwh[(size_t)INNER * INNER];
__device__ __align__(1024) __half g_xch [(size_t)M_TOT * INNER];
__device__ __align__(1024) __half g_y0h [(size_t)M_TOT * INNER];
__device__ __align__(1024) __half g_y1h [(size_t)M_TOT * INNER];
__device__ __align__(1024) __half g_owh [(size_t)HID * INNER];
__device__ __align__(1024) __half g_wbch[32 * INNER];

// ---------------- PTX helpers ----------------
__device__ __forceinline__ uint32_t smem_u32(const void* p) {
    uint32_t a;
    asm("{ .reg .u64 t; cvta.to.shared.u64 t, %1; cvt.u32.u64 %0, t; }" : "=r"(a) : "l"(p));
    return a;
}
__device__ __forceinline__ void cp_async16(uint32_t dst, const void* src) {
    asm volatile("cp.async.cg.shared.global [%0], [%1], 16;" :: "r"(dst), "l"(src) : "memory");
}
#define CP_COMMIT() asm volatile("cp.async.commit_group;" ::: "memory")
#define CP_WAIT1()  asm volatile("cp.async.wait_group 1;" ::: "memory")

__device__ __forceinline__ void ldm_x4(uint32_t* r, uint32_t addr) {
    asm volatile("ldmatrix.sync.aligned.m8n8.x4.shared.b16 {%0,%1,%2,%3}, [%4];"
        : "=r"(r[0]), "=r"(r[1]), "=r"(r[2]), "=r"(r[3]) : "r"(addr));
}
__device__ __forceinline__ void mma16816h(float* d, const uint32_t* a, const uint32_t* b) {
    asm volatile("mma.sync.aligned.m16n8k16.row.col.f32.f16.f16.f32 "
        "{%0,%1,%2,%3}, {%4,%5,%6,%7}, {%8,%9}, {%0,%1,%2,%3};"
        : "+f"(d[0]), "+f"(d[1]), "+f"(d[2]), "+f"(d[3])
        : "r"(a[0]), "r"(a[1]), "r"(a[2]), "r"(a[3]), "r"(b[0]), "r"(b[1]));
}
__device__ __forceinline__ float softplusf(float v) { return v > 20.f ? v : log1pf(__expf(v)); }
__device__ __forceinline__ float siluf(float v)     { return v / (1.f + __expf(-v)); }

// ---------------- fp16 mma.sync GEMM: C[M,N] = sum_p A_p[M,K] @ B_p[N,K]^T + bias ----------------
// BM=128, BN=256, BK=64 (128B SW128 rows), 8 warps of 64x64 tiles, 3-stage cp.async.
#define GBM 128
#define GBN 256
#define GAST (GBM * 128)
#define GSTG (GAST + GBN * 128)
#define GSMEM (3 * GSTG)

template <int PASSES, int EPI>
__global__ void __launch_bounds__(256, 1) gemm_mma(
    const __half* __restrict__ Ap0, const __half* __restrict__ Ap1,
    const __half* __restrict__ Bp0, const __half* __restrict__ Bp1,
    const float* __restrict__ bias, float* __restrict__ C, int N, int K)
{
    extern __shared__ char smraw[];
    const uint32_t sbase = smem_u32(smraw);
    const int tid  = threadIdx.x;
    const int wid  = tid >> 5;
    const int lane = tid & 31;
    const int bm0  = blockIdx.y * GBM;
    const int bn0  = blockIdx.x * GBN;

    const int KT0 = K >> 6;
    const int KTT = KT0 * PASSES;
    const size_t lda = (size_t)K * 2;
    const char* APS[2] = {(const char*)Ap0, (const char*)Ap1};
    const char* BPS[2] = {(const char*)Bp0, (const char*)Bp1};

    auto load_stage = [&](int kt, int s) {
        const int p  = (PASSES == 2) ? (kt / KT0) : 0;
        const int kc = kt - p * KT0;
        const char* Ap = APS[p];
        const char* Bp = BPS[p];
        const uint32_t sa = sbase + s * GSTG;
        const uint32_t sb = sa + GAST;
#pragma unroll
        for (int i = 0; i < 4; ++i) {
            int idx = tid + i * 256, r = idx >> 3, c = idx & 7;
            cp_async16(sa + r * 128 + ((c ^ (r & 7)) << 4),
                       Ap + (size_t)(bm0 + r) * lda + (size_t)kc * 128 + c * 16);
        }
#pragma unroll
        for (int i = 0; i < 8; ++i) {
            int idx = tid + i * 256, r = idx >> 3, c = idx & 7;
            cp_async16(sb + r * 128 + ((c ^ (r & 7)) << 4),
                       Bp + (size_t)(bn0 + r) * lda + (size_t)kc * 128 + c * 16);
        }
    };

    float acc[4][8][4];
#pragma unroll
    for (int mt = 0; mt < 4; ++mt)
#pragma unroll
        for (int nt = 0; nt < 8; ++nt)
#pragma unroll
            for (int q = 0; q < 4; ++q) acc[mt][nt][q] = 0.f;

    load_stage(0, 0); CP_COMMIT();
    load_stage(1, 1); CP_COMMIT();

    const int wm0 = (wid >> 2) * 64;
    const int wn0 = (wid & 3) * 64;
    const int aRow = wm0 + ((lane >> 3) & 1) * 8 + (lane & 7);
    const int bRow = wn0 + ((lane >> 4) & 1) * 8 + (lane & 7);
    const int swzX = (lane & 7) << 4;
    const int aKs  = (lane >> 4) << 4;
    const int bKs  = ((lane >> 3) & 1) << 4;

    for (int kt = 0; kt < KTT; ++kt) {
        const int s = kt % 3;
        CP_WAIT1();
        __syncthreads();
        if (kt + 2 < KTT) { load_stage(kt + 2, (kt + 2) % 3); CP_COMMIT(); }

        const uint32_t Ab = sbase + s * GSTG;
        const uint32_t Bb = Ab + GAST;
#pragma unroll
        for (int ks = 0; ks < 4; ++ks) {
            const int swA = (ks * 32 + aKs) ^ swzX;
            const int swB = (ks * 32 + bKs) ^ swzX;
            uint32_t a[4][4], b[4][4];
#pragma unroll
            for (int mt = 0; mt < 4; ++mt) ldm_x4(a[mt], Ab + (aRow + mt * 16) * 128 + swA);
#pragma unroll
            for (int np = 0; np < 4; ++np) ldm_x4(b[np], Bb + (bRow + np * 16) * 128 + swB);
#pragma unroll
            for (int mt = 0; mt < 4; ++mt)
#pragma unroll
                for (int nt = 0; nt < 8; ++nt)
                    mma16816h(acc[mt][nt], a[mt], &b[nt >> 1][(nt & 1) * 2]);
        }
    }

#pragma unroll
    for (int nt = 0; nt < 8; ++nt) {
        const int col = bn0 + wn0 + nt * 8 + (lane & 3) * 2;
        const float b0v = bias[col], b1v = bias[col + 1];
#pragma unroll
        for (int mt = 0; mt < 4; ++mt) {
            const int row = bm0 + wm0 + mt * 16 + (lane >> 2);
            float v0 = acc[mt][nt][0] + b0v, v1 = acc[mt][nt][1] + b1v;
            float v2 = acc[mt][nt][2] + b0v, v3 = acc[mt][nt][3] + b1v;
            if (EPI == 1) {
                v0 = softplusf(v0); v1 = softplusf(v1);
                v2 = softplusf(v2); v3 = softplusf(v3);
            }
            *reinterpret_cast<float2*>(&C[(size_t)row * N + col])       = make_float2(v0, v1);
            *reinterpret_cast<float2*>(&C[(size_t)(row + 8) * N + col]) = make_float2(v2, v3);
        }
    }
}

// ---------------- B/C projection via mma: out[M,32] = xch[M,2048] @ Wbc[32,2048]^T ----------------
// BM=128 (8 warps x 16 rows), BN=32, BK=64, 3-stage cp.async. 20KB/stage.
#define BCAST (128 * 128)
#define BCSTG (BCAST + 32 * 128)
#define BCSMEM (3 * BCSTG)
__global__ void __launch_bounds__(256, 1) bc_mma(
    const __half* __restrict__ A, const __half* __restrict__ W,
    const float* __restrict__ Bb, const float* __restrict__ Cb)
{
    extern __shared__ char smraw[];
    const uint32_t sbase = smem_u32(smraw);
    const int tid  = threadIdx.x;
    const int wid  = tid >> 5;
    const int lane = tid & 31;
    const int bm0  = blockIdx.x * 128;
    const size_t lda = (size_t)INNER * 2;

    auto load_stage = [&](int kt, int s) {
        const uint32_t sa = sbase + s * BCSTG;
        const uint32_t sb = sa + BCAST;
#pragma unroll
        for (int i = 0; i < 4; ++i) {
            int idx = tid + i * 256, r = idx >> 3, c = idx & 7;
            cp_async16(sa + r * 128 + ((c ^ (r & 7)) << 4),
                       (const char*)A + (size_t)(bm0 + r) * lda + (size_t)kt * 128 + c * 16);
        }
        {
            int r = tid >> 3, c = tid & 7;   // 256 threads cover 32 rows x 8 chunks
            cp_async16(sb + r * 128 + ((c ^ (r & 7)) << 4),
                       (const char*)W + (size_t)r * lda + (size_t)kt * 128 + c * 16);
        }
    };

    float acc[4][4];
#pragma unroll
    for (int nt = 0; nt < 4; ++nt)
#pragma unroll
        for (int q = 0; q < 4; ++q) acc[nt][q] = 0.f;

    load_stage(0, 0); CP_COMMIT();
    load_stage(1, 1); CP_COMMIT();

    const int aRow = wid * 16 + ((lane >> 3) & 1) * 8 + (lane & 7);
    const int bRow = ((lane >> 4) & 1) * 8 + (lane & 7);
    const int swzX = (lane & 7) << 4;
    const int aKs  = (lane >> 4) << 4;
    const int bKs  = ((lane >> 3) & 1) << 4;

    const int KT = INNER / 64;
    for (int kt = 0; kt < KT; ++kt) {
        const int s = kt % 3;
        CP_WAIT1();
        __syncthreads();
        if (kt + 2 < KT) { load_stage(kt + 2, (kt + 2) % 3); CP_COMMIT(); }

        const uint32_t Ab = sbase + s * BCSTG;
        const uint32_t Bb_ = Ab + BCAST;
#pragma unroll
        for (int ks = 0; ks < 4; ++ks) {
            const int swA = (ks * 32 + aKs) ^ swzX;
            const int swB = (ks * 32 + bKs) ^ swzX;
            uint32_t a[4], b[2][4];
            ldm_x4(a, Ab + aRow * 128 + swA);
#pragma unroll
            for (int np = 0; np < 2; ++np) ldm_x4(b[np], Bb_ + (bRow + np * 16) * 128 + swB);
#pragma unroll
            for (int nt = 0; nt < 4; ++nt)
                mma16816h(acc[nt], a, &b[nt >> 1][(nt & 1) * 2]);
        }
    }

#pragma unroll
    for (int nt = 0; nt < 4; ++nt) {
        const int col = nt * 8 + (lane & 3) * 2;
        const int row = bm0 + wid * 16 + (lane >> 2);
        if (col < 16) {
            const float c0 = Bb[col], c1 = Bb[col + 1];
            *reinterpret_cast<float2*>(&g_Bm[(size_t)row * 16 + col]) =
                make_float2(acc[nt][0] + c0, acc[nt][1] + c1);
            *reinterpret_cast<float2*>(&g_Bm[(size_t)(row + 8) * 16 + col]) =
                make_float2(acc[nt][2] + c0, acc[nt][3] + c1);
        } else {
            const int cc = col - 16;
            const float c0 = Cb[cc], c1 = Cb[cc + 1];
            *reinterpret_cast<float2*>(&g_Cm[(size_t)row * 16 + cc]) =
                make_float2(acc[nt][0] + c0, acc[nt][1] + c1);
            *reinterpret_cast<float2*>(&g_Cm[(size_t)(row + 8) * 16 + cc]) =
                make_float2(acc[nt][2] + c0, acc[nt][3] + c1);
        }
    }
}

// ---------------- conversion kernels ----------------
__global__ void __launch_bounds__(256) split2h_kernel(
    const float* __restrict__ in, __half* __restrict__ o0, __half* __restrict__ o1, size_t n4)
{
    for (size_t i = (size_t)blockIdx.x * 256 + threadIdx.x; i < n4; i += (size_t)gridDim.x * 256) {
        float4 v = reinterpret_cast<const float4*>(in)[i];
        __half a0 = __float2half_rn(v.x), b0 = __float2half_rn(v.y);
        __half c0 = __float2half_rn(v.z), d0 = __float2half_rn(v.w);
        ((ushort4*)o0)[i] = make_ushort4(__half_as_ushort(a0), __half_as_ushort(b0),
                                         __half_as_ushort(c0), __half_as_ushort(d0));
        ((ushort4*)o1)[i] = make_ushort4(
            __half_as_ushort(__float2half_rn(v.x - __half2float(a0))),
            __half_as_ushort(__float2half_rn(v.y - __half2float(b0))),
            __half_as_ushort(__float2half_rn(v.z - __half2float(c0))),
            __half_as_ushort(__float2half_rn(v.w - __half2float(d0))));
    }
}
__global__ void __launch_bounds__(256) cvt1h_kernel(
    const float* __restrict__ in, __half* __restrict__ o0, size_t n4)
{
    for (size_t i = (size_t)blockIdx.x * 256 + threadIdx.x; i < n4; i += (size_t)gridDim.x * 256) {
        float4 v = reinterpret_cast<const float4*>(in)[i];
        ((ushort4*)o0)[i] = make_ushort4(
            __half_as_ushort(__float2half_rn(v.x)), __half_as_ushort(__float2half_rn(v.y)),
            __half_as_ushort(__float2half_rn(v.z)), __half_as_ushort(__float2half_rn(v.w)));
    }
}
__global__ void __launch_bounds__(256) cvtbc_kernel(
    const float* __restrict__ Bw, const float* __restrict__ Cw, __half* __restrict__ o)
{
    int i = blockIdx.x * 256 + threadIdx.x;            // 0 .. 32*2048-1
    int r = i / INNER, k = i - r * INNER;
    float v = (r < 16) ? Bw[(size_t)r * INNER + k] : Cw[(size_t)(r - 16) * INNER + k];
    o[i] = __float2half_rn(v);
}

// ---------------- causal depthwise conv (K=4) + SiLU ----------------
__global__ void __launch_bounds__(256) conv_silu_kernel(
    const float* __restrict__ conv_w, const float* __restrict__ conv_b)
{
    const int d  = blockIdx.x * 256 + threadIdx.x;
    const int l0 = blockIdx.y * 128;
    const int b  = blockIdx.z;
    const float w0 = conv_w[d * 4 + 0], w1 = conv_w[d * 4 + 1];
    const float w2 = conv_w[d * 4 + 2], w3 = conv_w[d * 4 + 3];
    const float cb = conv_b[d];
    const float* xp = g_xz + (size_t)(b * LEN) * (2 * INNER) + d;
    float m3, m2, m1;
    if (l0 == 0) { m3 = m2 = m1 = 0.f; }
    else {
        m3 = xp[(size_t)(l0 - 3) * (2 * INNER)];
        m2 = xp[(size_t)(l0 - 2) * (2 * INNER)];
        m1 = xp[(size_t)(l0 - 1) * (2 * INNER)];
    }
    float*  xc = g_xconv + (size_t)(b * LEN + l0) * INNER + d;
    __half* xh = g_xch   + (size_t)(b * LEN + l0) * INNER + d;
#pragma unroll 4
    for (int i = 0; i < 128; ++i) {
        float cur = xp[(size_t)(l0 + i) * (2 * INNER)];
        float v = siluf(w0 * m3 + w1 * m2 + w2 * m1 + w3 * cur + cb);
        xc[(size_t)i * INNER] = v;
        xh[(size_t)i * INNER] = __float2half_rn(v);
        m3 = m2; m2 = m1; m1 = cur;
    }
}

// ---------------- chunked selective scan ----------------
__global__ void __launch_bounds__(128) scanA_kernel(const float* __restrict__ A_log)
{
    __shared__ float sB[LC * STATE];
    const int d = blockIdx.x * 128 + threadIdx.x;
    const int c = blockIdx.y;
    const int b = blockIdx.z;
    const int base_l = c * LC;
    for (int i = threadIdx.x; i < LC * STATE; i += 128)
        sB[i] = g_Bm[(size_t)(b * LEN + base_l) * STATE + i];
    __syncthreads();
    float Ar[STATE];
#pragma unroll
    for (int s = 0; s < STATE; s++) Ar[s] = -expf(A_log[d * STATE + s]);
    float h[STATE], Pr[STATE];
#pragma unroll
    for (int s = 0; s < STATE; s++) { h[s] = 0.f; Pr[s] = 1.f; }
    const float* dtp = g_dt    + (size_t)(b * LEN + base_l) * INNER + d;
    const float* xcp = g_xconv + (size_t)(b * LEN + base_l) * INNER + d;
    for (int l = 0; l < LC; ++l) {
        float dtv = dtp[(size_t)l * INNER];
        float dtx = dtv * xcp[(size_t)l * INNER];
#pragma unroll
        for (int s = 0; s < STATE; s++) {
            float dA = __expf(dtv * Ar[s]);
            Pr[s] *= dA;
            h[s] = fmaf(dA, h[s], sB[l * STATE + s] * dtx);
        }
    }
    size_t ob = (size_t)(b * NC + c) * STATE * INNER + d;
#pragma unroll
    for (int s = 0; s < STATE; s++) {
        g_P[ob + (size_t)s * INNER] = Pr[s];
        g_S[ob + (size_t)s * INNER] = h[s];
    }
}

__global__ void __launch_bounds__(256) scanB_kernel()
{
    int g = blockIdx.x * 256 + threadIdx.x;
    int b = g / (STATE * INNER);
    int r = g - b * (STATE * INNER);
    float h = 0.f;
    for (int c = 0; c < NC; ++c) {
        size_t idx = (size_t)(b * NC + c) * STATE * INNER + r;
        g_H0[idx] = h;
        h = g_P[idx] * h + g_S[idx];
    }
}

__global__ void __launch_bounds__(128) scanC_kernel(
    const float* __restrict__ A_log, const float* __restrict__ Dv)
{
    __shared__ float sB[LC * STATE];
    __shared__ float sC[LC * STATE];
    const int d = blockIdx.x * 128 + threadIdx.x;
    const int c = blockIdx.y;
    const int b = blockIdx.z;
    const int base_l = c * LC;
    for (int i = threadIdx.x; i < LC * STATE; i += 128) {
        sB[i] = g_Bm[(size_t)(b * LEN + base_l) * STATE + i];
        sC[i] = g_Cm[(size_t)(b * LEN + base_l) * STATE + i];
    }
    __syncthreads();
    float Ar[STATE];
#pragma unroll
    for (int s = 0; s < STATE; s++) Ar[s] = -expf(A_log[d * STATE + s]);
    const float Dd = Dv[d];
    float h[STATE];
    size_t ob = (size_t)(b * NC + c) * STATE * INNER + d;
#pragma unroll
    for (int s = 0; s < STATE; s++) h[s] = g_H0[ob + (size_t)s * INNER];
    const float* dtp = g_dt    + (size_t)(b * LEN + base_l) * INNER + d;
    const float* xcp = g_xconv + (size_t)(b * LEN + base_l) * INNER + d;
    const float* zp  = g_xz    + (size_t)(b * LEN + base_l) * (2 * INNER) + INNER + d;
    __half* y0p = g_y0h + (size_t)(b * LEN + base_l) * INNER + d;
    __half* y1p = g_y1h + (size_t)(b * LEN + base_l) * INNER + d;
    for (int l = 0; l < LC; ++l) {
        float dtv = dtp[(size_t)l * INNER];
        float xv  = xcp[(size_t)l * INNER];
        float zv  = zp[(size_t)l * (2 * INNER)];
        float dtx = dtv * xv;
        float acc = Dd * xv;
#pragma unroll
        for (int s = 0; s < STATE; s++) {
            float dA = __expf(dtv * Ar[s]);
            h[s] = fmaf(dA, h[s], sB[l * STATE + s] * dtx);
            acc  = fmaf(sC[l * STATE + s], h[s], acc);
        }
        float v = acc * siluf(zv);
        __half v0 = __float2half_rn(v);
        y0p[(size_t)l * INNER] = v0;
        y1p[(size_t)l * INNER] = __float2half_rn(v - __half2float(v0));
    }
}

// ---------------- launch ----------------
extern "C" void kernel_launch(void* const* d_in, const int* in_sizes, int n_in,
                              void* d_out, int out_size)
{
    const float* x      = (const float*)d_in[0];
    const float* in_w   = (const float*)d_in[1];
    const float* in_b   = (const float*)d_in[2];
    const float* conv_w = (const float*)d_in[3];
    const float* conv_b = (const float*)d_in[4];
    const float* dt_w   = (const float*)d_in[5];
    const float* dt_b   = (const float*)d_in[6];
    const float* A_log  = (const float*)d_in[7];
    const float* B_w    = (const float*)d_in[8];
    const float* B_b    = (const float*)d_in[9];
    const float* C_w    = (const float*)d_in[10];
    const float* C_b    = (const float*)d_in[11];
    const float* Dv     = (const float*)d_in[12];
    const float* out_w  = (const float*)d_in[13];
    const float* out_b  = (const float*)d_in[14];
    float* out = (float*)d_out;

    float *xz, *dt;
    __half *x0h, *x1h, *wh, *dtwh, *xch, *y0h, *y1h, *owh, *wbch;
    cudaGetSymbolAddress((void**)&xz, g_xz);
    cudaGetSymbolAddress((void**)&dt, g_dt);
    cudaGetSymbolAddress((void**)&x0h, g_x0h);   cudaGetSymbolAddress((void**)&x1h, g_x1h);
    cudaGetSymbolAddress((void**)&wh, g_wh);
    cudaGetSymbolAddress((void**)&dtwh, g_dtwh);
    cudaGetSymbolAddress((void**)&xch, g_xch);
    cudaGetSymbolAddress((void**)&y0h, g_y0h);   cudaGetSymbolAddress((void**)&y1h, g_y1h);
    cudaGetSymbolAddress((void**)&owh, g_owh);
    cudaGetSymbolAddress((void**)&wbch, g_wbch);

    cudaFuncSetAttribute(gemm_mma<2, 0>, cudaFuncAttributeMaxDynamicSharedMemorySize, GSMEM);
    cudaFuncSetAttribute(gemm_mma<1, 1>, cudaFuncAttributeMaxDynamicSharedMemorySize, GSMEM);
    cudaFuncSetAttribute(bc_mma, cudaFuncAttributeMaxDynamicSharedMemorySize, BCSMEM);

    // 0) fp16 conversions / splits
    split2h_kernel<<<2048, 256>>>(x, x0h, x1h, (size_t)M_TOT * HID / 4);
    cvt1h_kernel<<<1024, 256>>>(in_w, wh, (size_t)2 * INNER * HID / 4);
    cvt1h_kernel<<<1024, 256>>>(dt_w, dtwh, (size_t)INNER * INNER / 4);
    cvt1h_kernel<<<512, 256>>>(out_w, owh, (size_t)HID * INNER / 4);
    cvtbc_kernel<<<(32 * INNER) / 256, 256>>>(B_w, C_w, wbch);

    // 1) in-proj, 2-pass fp16: xz = x @ in_w^T + in_b       (16384 x 4096 x 1024)
    gemm_mma<2, 0><<<dim3(4096 / GBN, M_TOT / GBM), 256, GSMEM>>>(
        x0h, x1h, wh, wh, in_b, xz, 4096, HID);

    // 2) conv + silu
    conv_silu_kernel<<<dim3(INNER / 256, LEN / 128, B_SZ), 256>>>(conv_w, conv_b);

    // 3) dt = softplus(xconv @ dt_w^T + dt_b), 1-pass fp16  (16384 x 2048 x 2048)
    gemm_mma<1, 1><<<dim3(INNER / GBN, M_TOT / GBM), 256, GSMEM>>>(
        xch, xch, dtwh, dtwh, dt_b, dt, INNER, INNER);

    // 4) B/C projections via mma (N = 32)
    bc_mma<<<M_TOT / 128, 256, BCSMEM>>>(xch, wbch, B_b, C_b);

    // 5) chunked selective scan + gating
    scanA_kernel<<<dim3(INNER / 128, NC, B_SZ), 128>>>(A_log);
    scanB_kernel<<<(B_SZ * STATE * INNER) / 256, 256>>>();
    scanC_kernel<<<dim3(INNER / 128, NC, B_SZ), 128>>>(A_log, Dv);

    // 6) out-proj, 2-pass fp16: out = y @ out_w^T + out_b   (16384 x 1024 x 2048)
    gemm_mma<2, 0><<<dim3(HID / GBN, M_TOT / GBM), 256, GSMEM>>>(
        y0h, y1h, owh, owh, out_b, out, HID, INNER);
}

// round 6
// speedup vs baseline: 3.6607x; 1.0783x over previous
#include <cuda_runtime.h>
#include <cuda_fp16.h>
#include <math.h>
#include <stdint.h>

#define B_SZ   4
#define LEN    4096
#define HID    1024
#define STATE  16
#define INNER  2048
#define M_TOT  (B_SZ * LEN)
#define NC     16
#define LC     256

// ---------------- scratch ----------------
__device__ __align__(1024) float g_xz   [(size_t)M_TOT * 2 * INNER];
__device__ __align__(1024) float g_xconv[(size_t)M_TOT * INNER];
__device__ __align__(1024) float g_dt   [(size_t)M_TOT * INNER];
__device__ __align__(1024) float g_Bm   [(size_t)M_TOT * STATE];
__device__ __align__(1024) float g_Cm   [(size_t)M_TOT * STATE];
__device__ __align__(1024) float g_P [(size_t)B_SZ * NC * STATE * INNER];
__device__ __align__(1024) float g_S [(size_t)B_SZ * NC * STATE * INNER];
__device__ __align__(1024) float g_H0[(size_t)B_SZ * NC * STATE * INNER];
__device__ __align__(1024) __half g_x0h [(size_t)M_TOT * HID];
__device__ __align__(1024) __half g_x1h [(size_t)M_TOT * HID];
__device__ __align__(1024) __half g_wh  [(size_t)2 * INNER * HID];
__device__ __align__(1024) __half g_dtwh[(size_t)INNER * INNER];
__device__ __align__(1024) __half g_xch [(size_t)M_TOT * INNER];
__device__ __align__(1024) __half g_y0h [(size_t)M_TOT * INNER];
__device__ __align__(1024) __half g_y1h [(size_t)M_TOT * INNER];
__device__ __align__(1024) __half g_owh [(size_t)HID * INNER];
__device__ __align__(1024) __half g_wbch[32 * INNER];

// ---------------- PTX helpers ----------------
__device__ __forceinline__ uint32_t smem_u32(const void* p) {
    uint32_t a;
    asm("{ .reg .u64 t; cvta.to.shared.u64 t, %1; cvt.u32.u64 %0, t; }" : "=r"(a) : "l"(p));
    return a;
}
__device__ __forceinline__ void cp_async16(uint32_t dst, const void* src) {
    asm volatile("cp.async.cg.shared.global [%0], [%1], 16;" :: "r"(dst), "l"(src) : "memory");
}
#define CP_COMMIT() asm volatile("cp.async.commit_group;" ::: "memory")
#define CP_WAIT1()  asm volatile("cp.async.wait_group 1;" ::: "memory")

__device__ __forceinline__ void ldm_x4(uint32_t* r, uint32_t addr) {
    asm volatile("ldmatrix.sync.aligned.m8n8.x4.shared.b16 {%0,%1,%2,%3}, [%4];"
        : "=r"(r[0]), "=r"(r[1]), "=r"(r[2]), "=r"(r[3]) : "r"(addr));
}
__device__ __forceinline__ void mma16816h(float* d, const uint32_t* a, const uint32_t* b) {
    asm volatile("mma.sync.aligned.m16n8k16.row.col.f32.f16.f16.f32 "
        "{%0,%1,%2,%3}, {%4,%5,%6,%7}, {%8,%9}, {%0,%1,%2,%3};"
        : "+f"(d[0]), "+f"(d[1]), "+f"(d[2]), "+f"(d[3])
        : "r"(a[0]), "r"(a[1]), "r"(a[2]), "r"(a[3]), "r"(b[0]), "r"(b[1]));
}
__device__ __forceinline__ float softplusf(float v) { return v > 20.f ? v : log1pf(__expf(v)); }
__device__ __forceinline__ float siluf(float v)     { return v / (1.f + __expf(-v)); }

// ---------------- fp16 mma.sync GEMM: C[M,N] = sum_p A_p[M,K] @ B_p[N,K]^T + bias ----------------
// BM=128, BN=256, BK=64 (128B SW128 rows), 8 warps of 64x64 tiles, 3-stage cp.async.
// NOTE: Cstride is the row stride of C; the grid covers gridDim.x*GBN output columns
// starting at the C/bias/B pointers (enables column-block splits of one logical GEMM).
#define GBM 128
#define GBN 256
#define GAST (GBM * 128)
#define GSTG (GAST + GBN * 128)
#define GSMEM (3 * GSTG)

template <int PASSES, int EPI>
__global__ void __launch_bounds__(256, 1) gemm_mma(
    const __half* __restrict__ Ap0, const __half* __restrict__ Ap1,
    const __half* __restrict__ Bp0, const __half* __restrict__ Bp1,
    const float* __restrict__ bias, float* __restrict__ C, int Cstride, int K)
{
    extern __shared__ char smraw[];
    const uint32_t sbase = smem_u32(smraw);
    const int tid  = threadIdx.x;
    const int wid  = tid >> 5;
    const int lane = tid & 31;
    const int bm0  = blockIdx.y * GBM;
    const int bn0  = blockIdx.x * GBN;

    const int KT0 = K >> 6;
    const int KTT = KT0 * PASSES;
    const size_t lda = (size_t)K * 2;
    const char* APS[2] = {(const char*)Ap0, (const char*)Ap1};
    const char* BPS[2] = {(const char*)Bp0, (const char*)Bp1};

    auto load_stage = [&](int kt, int s) {
        const int p  = (PASSES == 2) ? (kt / KT0) : 0;
        const int kc = kt - p * KT0;
        const char* Ap = APS[p];
        const char* Bp = BPS[p];
        const uint32_t sa = sbase + s * GSTG;
        const uint32_t sb = sa + GAST;
#pragma unroll
        for (int i = 0; i < 4; ++i) {
            int idx = tid + i * 256, r = idx >> 3, c = idx & 7;
            cp_async16(sa + r * 128 + ((c ^ (r & 7)) << 4),
                       Ap + (size_t)(bm0 + r) * lda + (size_t)kc * 128 + c * 16);
        }
#pragma unroll
        for (int i = 0; i < 8; ++i) {
            int idx = tid + i * 256, r = idx >> 3, c = idx & 7;
            cp_async16(sb + r * 128 + ((c ^ (r & 7)) << 4),
                       Bp + (size_t)(bn0 + r) * lda + (size_t)kc * 128 + c * 16);
        }
    };

    float acc[4][8][4];
#pragma unroll
    for (int mt = 0; mt < 4; ++mt)
#pragma unroll
        for (int nt = 0; nt < 8; ++nt)
#pragma unroll
            for (int q = 0; q < 4; ++q) acc[mt][nt][q] = 0.f;

    load_stage(0, 0); CP_COMMIT();
    load_stage(1, 1); CP_COMMIT();

    const int wm0 = (wid >> 2) * 64;
    const int wn0 = (wid & 3) * 64;
    const int aRow = wm0 + ((lane >> 3) & 1) * 8 + (lane & 7);
    const int bRow = wn0 + ((lane >> 4) & 1) * 8 + (lane & 7);
    const int swzX = (lane & 7) << 4;
    const int aKs  = (lane >> 4) << 4;
    const int bKs  = ((lane >> 3) & 1) << 4;

    for (int kt = 0; kt < KTT; ++kt) {
        const int s = kt % 3;
        CP_WAIT1();
        __syncthreads();
        if (kt + 2 < KTT) { load_stage(kt + 2, (kt + 2) % 3); CP_COMMIT(); }

        const uint32_t Ab = sbase + s * GSTG;
        const uint32_t Bb = Ab + GAST;
#pragma unroll
        for (int ks = 0; ks < 4; ++ks) {
            const int swA = (ks * 32 + aKs) ^ swzX;
            const int swB = (ks * 32 + bKs) ^ swzX;
            uint32_t a[4][4], b[4][4];
#pragma unroll
            for (int mt = 0; mt < 4; ++mt) ldm_x4(a[mt], Ab + (aRow + mt * 16) * 128 + swA);
#pragma unroll
            for (int np = 0; np < 4; ++np) ldm_x4(b[np], Bb + (bRow + np * 16) * 128 + swB);
#pragma unroll
            for (int mt = 0; mt < 4; ++mt)
#pragma unroll
                for (int nt = 0; nt < 8; ++nt)
                    mma16816h(acc[mt][nt], a[mt], &b[nt >> 1][(nt & 1) * 2]);
        }
    }

#pragma unroll
    for (int nt = 0; nt < 8; ++nt) {
        const int col = bn0 + wn0 + nt * 8 + (lane & 3) * 2;
        const float b0v = bias[col], b1v = bias[col + 1];
#pragma unroll
        for (int mt = 0; mt < 4; ++mt) {
            const int row = bm0 + wm0 + mt * 16 + (lane >> 2);
            float v0 = acc[mt][nt][0] + b0v, v1 = acc[mt][nt][1] + b1v;
            float v2 = acc[mt][nt][2] + b0v, v3 = acc[mt][nt][3] + b1v;
            if (EPI == 1) {
                v0 = softplusf(v0); v1 = softplusf(v1);
                v2 = softplusf(v2); v3 = softplusf(v3);
            }
            *reinterpret_cast<float2*>(&C[(size_t)row * Cstride + col])       = make_float2(v0, v1);
            *reinterpret_cast<float2*>(&C[(size_t)(row + 8) * Cstride + col]) = make_float2(v2, v3);
        }
    }
}

// ---------------- B/C projection via mma: out[M,32] = xch[M,2048] @ Wbc[32,2048]^T ----------------
#define BCAST (128 * 128)
#define BCSTG (BCAST + 32 * 128)
#define BCSMEM (3 * BCSTG)
__global__ void __launch_bounds__(256, 1) bc_mma(
    const __half* __restrict__ A, const __half* __restrict__ W,
    const float* __restrict__ Bb, const float* __restrict__ Cb)
{
    extern __shared__ char smraw[];
    const uint32_t sbase = smem_u32(smraw);
    const int tid  = threadIdx.x;
    const int wid  = tid >> 5;
    const int lane = tid & 31;
    const int bm0  = blockIdx.x * 128;
    const size_t lda = (size_t)INNER * 2;

    auto load_stage = [&](int kt, int s) {
        const uint32_t sa = sbase + s * BCSTG;
        const uint32_t sb = sa + BCAST;
#pragma unroll
        for (int i = 0; i < 4; ++i) {
            int idx = tid + i * 256, r = idx >> 3, c = idx & 7;
            cp_async16(sa + r * 128 + ((c ^ (r & 7)) << 4),
                       (const char*)A + (size_t)(bm0 + r) * lda + (size_t)kt * 128 + c * 16);
        }
        {
            int r = tid >> 3, c = tid & 7;
            cp_async16(sb + r * 128 + ((c ^ (r & 7)) << 4),
                       (const char*)W + (size_t)r * lda + (size_t)kt * 128 + c * 16);
        }
    };

    float acc[4][4];
#pragma unroll
    for (int nt = 0; nt < 4; ++nt)
#pragma unroll
        for (int q = 0; q < 4; ++q) acc[nt][q] = 0.f;

    load_stage(0, 0); CP_COMMIT();
    load_stage(1, 1); CP_COMMIT();

    const int aRow = wid * 16 + ((lane >> 3) & 1) * 8 + (lane & 7);
    const int bRow = ((lane >> 4) & 1) * 8 + (lane & 7);
    const int swzX = (lane & 7) << 4;
    const int aKs  = (lane >> 4) << 4;
    const int bKs  = ((lane >> 3) & 1) << 4;

    const int KT = INNER / 64;
    for (int kt = 0; kt < KT; ++kt) {
        const int s = kt % 3;
        CP_WAIT1();
        __syncthreads();
        if (kt + 2 < KT) { load_stage(kt + 2, (kt + 2) % 3); CP_COMMIT(); }

        const uint32_t Ab = sbase + s * BCSTG;
        const uint32_t Bb_ = Ab + BCAST;
#pragma unroll
        for (int ks = 0; ks < 4; ++ks) {
            const int swA = (ks * 32 + aKs) ^ swzX;
            const int swB = (ks * 32 + bKs) ^ swzX;
            uint32_t a[4], b[2][4];
            ldm_x4(a, Ab + aRow * 128 + swA);
#pragma unroll
            for (int np = 0; np < 2; ++np) ldm_x4(b[np], Bb_ + (bRow + np * 16) * 128 + swB);
#pragma unroll
            for (int nt = 0; nt < 4; ++nt)
                mma16816h(acc[nt], a, &b[nt >> 1][(nt & 1) * 2]);
        }
    }

#pragma unroll
    for (int nt = 0; nt < 4; ++nt) {
        const int col = nt * 8 + (lane & 3) * 2;
        const int row = bm0 + wid * 16 + (lane >> 2);
        if (col < 16) {
            const float c0 = Bb[col], c1 = Bb[col + 1];
            *reinterpret_cast<float2*>(&g_Bm[(size_t)row * 16 + col]) =
                make_float2(acc[nt][0] + c0, acc[nt][1] + c1);
            *reinterpret_cast<float2*>(&g_Bm[(size_t)(row + 8) * 16 + col]) =
                make_float2(acc[nt][2] + c0, acc[nt][3] + c1);
        } else {
            const int cc = col - 16;
            const float c0 = Cb[cc], c1 = Cb[cc + 1];
            *reinterpret_cast<float2*>(&g_Cm[(size_t)row * 16 + cc]) =
                make_float2(acc[nt][0] + c0, acc[nt][1] + c1);
            *reinterpret_cast<float2*>(&g_Cm[(size_t)(row + 8) * 16 + cc]) =
                make_float2(acc[nt][2] + c0, acc[nt][3] + c1);
        }
    }
}

// ---------------- conversion kernels ----------------
__global__ void __launch_bounds__(256) split2h_kernel(
    const float* __restrict__ in, __half* __restrict__ o0, __half* __restrict__ o1, size_t n4)
{
    for (size_t i = (size_t)blockIdx.x * 256 + threadIdx.x; i < n4; i += (size_t)gridDim.x * 256) {
        float4 v = reinterpret_cast<const float4*>(in)[i];
        __half a0 = __float2half_rn(v.x), b0 = __float2half_rn(v.y);
        __half c0 = __float2half_rn(v.z), d0 = __float2half_rn(v.w);
        ((ushort4*)o0)[i] = make_ushort4(__half_as_ushort(a0), __half_as_ushort(b0),
                                         __half_as_ushort(c0), __half_as_ushort(d0));
        ((ushort4*)o1)[i] = make_ushort4(
            __half_as_ushort(__float2half_rn(v.x - __half2float(a0))),
            __half_as_ushort(__float2half_rn(v.y - __half2float(b0))),
            __half_as_ushort(__float2half_rn(v.z - __half2float(c0))),
            __half_as_ushort(__float2half_rn(v.w - __half2float(d0))));
    }
}
__global__ void __launch_bounds__(256) cvt1h_kernel(
    const float* __restrict__ in, __half* __restrict__ o0, size_t n4)
{
    for (size_t i = (size_t)blockIdx.x * 256 + threadIdx.x; i < n4; i += (size_t)gridDim.x * 256) {
        float4 v = reinterpret_cast<const float4*>(in)[i];
        ((ushort4*)o0)[i] = make_ushort4(
            __half_as_ushort(__float2half_rn(v.x)), __half_as_ushort(__float2half_rn(v.y)),
            __half_as_ushort(__float2half_rn(v.z)), __half_as_ushort(__float2half_rn(v.w)));
    }
}
__global__ void __launch_bounds__(256) cvtbc_kernel(
    const float* __restrict__ Bw, const float* __restrict__ Cw, __half* __restrict__ o)
{
    int i = blockIdx.x * 256 + threadIdx.x;
    int r = i / INNER, k = i - r * INNER;
    float v = (r < 16) ? Bw[(size_t)r * INNER + k] : Cw[(size_t)(r - 16) * INNER + k];
    o[i] = __float2half_rn(v);
}

// ---------------- causal depthwise conv (K=4) + SiLU ----------------
__global__ void __launch_bounds__(256) conv_silu_kernel(
    const float* __restrict__ conv_w, const float* __restrict__ conv_b)
{
    const int d  = blockIdx.x * 256 + threadIdx.x;
    const int l0 = blockIdx.y * 128;
    const int b  = blockIdx.z;
    const float w0 = conv_w[d * 4 + 0], w1 = conv_w[d * 4 + 1];
    const float w2 = conv_w[d * 4 + 2], w3 = conv_w[d * 4 + 3];
    const float cb = conv_b[d];
    const float* xp = g_xz + (size_t)(b * LEN) * (2 * INNER) + d;
    float m3, m2, m1;
    if (l0 == 0) { m3 = m2 = m1 = 0.f; }
    else {
        m3 = xp[(size_t)(l0 - 3) * (2 * INNER)];
        m2 = xp[(size_t)(l0 - 2) * (2 * INNER)];
        m1 = xp[(size_t)(l0 - 1) * (2 * INNER)];
    }
    float*  xc = g_xconv + (size_t)(b * LEN + l0) * INNER + d;
    __half* xh = g_xch   + (size_t)(b * LEN + l0) * INNER + d;
#pragma unroll 4
    for (int i = 0; i < 128; ++i) {
        float cur = xp[(size_t)(l0 + i) * (2 * INNER)];
        float v = siluf(w0 * m3 + w1 * m2 + w2 * m1 + w3 * cur + cb);
        xc[(size_t)i * INNER] = v;
        xh[(size_t)i * INNER] = __float2half_rn(v);
        m3 = m2; m2 = m1; m1 = cur;
    }
}

// ---------------- chunked selective scan ----------------
__global__ void __launch_bounds__(128) scanA_kernel(const float* __restrict__ A_log)
{
    __shared__ float sB[LC * STATE];
    const int d = blockIdx.x * 128 + threadIdx.x;
    const int c = blockIdx.y;
    const int b = blockIdx.z;
    const int base_l = c * LC;
    for (int i = threadIdx.x; i < LC * STATE; i += 128)
        sB[i] = g_Bm[(size_t)(b * LEN + base_l) * STATE + i];
    __syncthreads();
    float Ar[STATE];
#pragma unroll
    for (int s = 0; s < STATE; s++) Ar[s] = -expf(A_log[d * STATE + s]);
    float h[STATE], Pr[STATE];
#pragma unroll
    for (int s = 0; s < STATE; s++) { h[s] = 0.f; Pr[s] = 1.f; }
    const float* dtp = g_dt    + (size_t)(b * LEN + base_l) * INNER + d;
    const float* xcp = g_xconv + (size_t)(b * LEN + base_l) * INNER + d;
    for (int l = 0; l < LC; ++l) {
        float dtv = dtp[(size_t)l * INNER];
        float dtx = dtv * xcp[(size_t)l * INNER];
#pragma unroll
        for (int s = 0; s < STATE; s++) {
            float dA = __expf(dtv * Ar[s]);
            Pr[s] *= dA;
            h[s] = fmaf(dA, h[s], sB[l * STATE + s] * dtx);
        }
    }
    size_t ob = (size_t)(b * NC + c) * STATE * INNER + d;
#pragma unroll
    for (int s = 0; s < STATE; s++) {
        g_P[ob + (size_t)s * INNER] = Pr[s];
        g_S[ob + (size_t)s * INNER] = h[s];
    }
}

__global__ void __launch_bounds__(256) scanB_kernel()
{
    int g = blockIdx.x * 256 + threadIdx.x;
    int b = g / (STATE * INNER);
    int r = g - b * (STATE * INNER);
    float h = 0.f;
    for (int c = 0; c < NC; ++c) {
        size_t idx = (size_t)(b * NC + c) * STATE * INNER + r;
        g_H0[idx] = h;
        h = g_P[idx] * h + g_S[idx];
    }
}

__global__ void __launch_bounds__(128) scanC_kernel(
    const float* __restrict__ A_log, const float* __restrict__ Dv)
{
    __shared__ float sB[LC * STATE];
    __shared__ float sC[LC * STATE];
    const int d = blockIdx.x * 128 + threadIdx.x;
    const int c = blockIdx.y;
    const int b = blockIdx.z;
    const int base_l = c * LC;
    for (int i = threadIdx.x; i < LC * STATE; i += 128) {
        sB[i] = g_Bm[(size_t)(b * LEN + base_l) * STATE + i];
        sC[i] = g_Cm[(size_t)(b * LEN + base_l) * STATE + i];
    }
    __syncthreads();
    float Ar[STATE];
#pragma unroll
    for (int s = 0; s < STATE; s++) Ar[s] = -expf(A_log[d * STATE + s]);
    const float Dd = Dv[d];
    float h[STATE];
    size_t ob = (size_t)(b * NC + c) * STATE * INNER + d;
#pragma unroll
    for (int s = 0; s < STATE; s++) h[s] = g_H0[ob + (size_t)s * INNER];
    const float* dtp = g_dt    + (size_t)(b * LEN + base_l) * INNER + d;
    const float* xcp = g_xconv + (size_t)(b * LEN + base_l) * INNER + d;
    const float* zp  = g_xz    + (size_t)(b * LEN + base_l) * (2 * INNER) + INNER + d;
    __half* y0p = g_y0h + (size_t)(b * LEN + base_l) * INNER + d;
    __half* y1p = g_y1h + (size_t)(b * LEN + base_l) * INNER + d;
    for (int l = 0; l < LC; ++l) {
        float dtv = dtp[(size_t)l * INNER];
        float xv  = xcp[(size_t)l * INNER];
        float zv  = zp[(size_t)l * (2 * INNER)];
        float dtx = dtv * xv;
        float acc = Dd * xv;
#pragma unroll
        for (int s = 0; s < STATE; s++) {
            float dA = __expf(dtv * Ar[s]);
            h[s] = fmaf(dA, h[s], sB[l * STATE + s] * dtx);
            acc  = fmaf(sC[l * STATE + s], h[s], acc);
        }
        float v = acc * siluf(zv);
        __half v0 = __float2half_rn(v);
        y0p[(size_t)l * INNER] = v0;
        y1p[(size_t)l * INNER] = __float2half_rn(v - __half2float(v0));
    }
}

// ---------------- launch ----------------
extern "C" void kernel_launch(void* const* d_in, const int* in_sizes, int n_in,
                              void* d_out, int out_size)
{
    const float* x      = (const float*)d_in[0];
    const float* in_w   = (const float*)d_in[1];
    const float* in_b   = (const float*)d_in[2];
    const float* conv_w = (const float*)d_in[3];
    const float* conv_b = (const float*)d_in[4];
    const float* dt_w   = (const float*)d_in[5];
    const float* dt_b   = (const float*)d_in[6];
    const float* A_log  = (const float*)d_in[7];
    const float* B_w    = (const float*)d_in[8];
    const float* B_b    = (const float*)d_in[9];
    const float* C_w    = (const float*)d_in[10];
    const float* C_b    = (const float*)d_in[11];
    const float* Dv     = (const float*)d_in[12];
    const float* out_w  = (const float*)d_in[13];
    const float* out_b  = (const float*)d_in[14];
    float* out = (float*)d_out;

    float *xz, *dt;
    __half *x0h, *x1h, *wh, *dtwh, *xch, *y0h, *y1h, *owh, *wbch;
    cudaGetSymbolAddress((void**)&xz, g_xz);
    cudaGetSymbolAddress((void**)&dt, g_dt);
    cudaGetSymbolAddress((void**)&x0h, g_x0h);   cudaGetSymbolAddress((void**)&x1h, g_x1h);
    cudaGetSymbolAddress((void**)&wh, g_wh);
    cudaGetSymbolAddress((void**)&dtwh, g_dtwh);
    cudaGetSymbolAddress((void**)&xch, g_xch);
    cudaGetSymbolAddress((void**)&y0h, g_y0h);   cudaGetSymbolAddress((void**)&y1h, g_y1h);
    cudaGetSymbolAddress((void**)&owh, g_owh);
    cudaGetSymbolAddress((void**)&wbch, g_wbch);

    cudaFuncSetAttribute(gemm_mma<2, 0>, cudaFuncAttributeMaxDynamicSharedMemorySize, GSMEM);
    cudaFuncSetAttribute(gemm_mma<1, 0>, cudaFuncAttributeMaxDynamicSharedMemorySize, GSMEM);
    cudaFuncSetAttribute(gemm_mma<1, 1>, cudaFuncAttributeMaxDynamicSharedMemorySize, GSMEM);
    cudaFuncSetAttribute(bc_mma, cudaFuncAttributeMaxDynamicSharedMemorySize, BCSMEM);

    // 0) fp16 conversions / splits
    split2h_kernel<<<2048, 256>>>(x, x0h, x1h, (size_t)M_TOT * HID / 4);
    cvt1h_kernel<<<1024, 256>>>(in_w, wh, (size_t)2 * INNER * HID / 4);
    cvt1h_kernel<<<1024, 256>>>(dt_w, dtwh, (size_t)INNER * INNER / 4);
    cvt1h_kernel<<<512, 256>>>(out_w, owh, (size_t)HID * INNER / 4);
    cvtbc_kernel<<<(32 * INNER) / 256, 256>>>(B_w, C_w, wbch);

    // 1a) in-proj x_part half, 2-pass fp16 (cols 0..2047)   (16384 x 2048 x 1024)
    gemm_mma<2, 0><<<dim3(INNER / GBN, M_TOT / GBM), 256, GSMEM>>>(
        x0h, x1h, wh, wh, in_b, xz, 2 * INNER, HID);
    // 1b) in-proj z half, 1-pass fp16 (cols 2048..4095)     (16384 x 2048 x 1024)
    gemm_mma<1, 0><<<dim3(INNER / GBN, M_TOT / GBM), 256, GSMEM>>>(
        x0h, x0h, wh + (size_t)INNER * HID, wh + (size_t)INNER * HID,
        in_b + INNER, xz + INNER, 2 * INNER, HID);

    // 2) conv + silu
    conv_silu_kernel<<<dim3(INNER / 256, LEN / 128, B_SZ), 256>>>(conv_w, conv_b);

    // 3) B/C projections via mma (N = 32)
    bc_mma<<<M_TOT / 128, 256, BCSMEM>>>(xch, wbch, B_b, C_b);

    // 4) dt = softplus(xconv @ dt_w^T + dt_b), 1-pass fp16  (16384 x 2048 x 2048)
    gemm_mma<1, 1><<<dim3(INNER / GBN, M_TOT / GBM), 256, GSMEM>>>(
        xch, xch, dtwh, dtwh, dt_b, dt, INNER, INNER);

    // 5) chunked selective scan + gating
    scanA_kernel<<<dim3(INNER / 128, NC, B_SZ), 128>>>(A_log);
    scanB_kernel<<<(B_SZ * STATE * INNER) / 256, 256>>>();
    scanC_kernel<<<dim3(INNER / 128, NC, B_SZ), 128>>>(A_log, Dv);

    // 6) out-proj, 2-pass fp16: out = y @ out_w^T + out_b   (16384 x 1024 x 2048)
    gemm_mma<2, 0><<<dim3(HID / GBN, M_TOT / GBM), 256, GSMEM>>>(
        y0h, y1h, owh, owh, out_b, out, HID, INNER);
}

// round 7
// speedup vs baseline: 4.4186x; 1.2070x over previous
#include <cuda_runtime.h>
#include <cuda_fp16.h>
#include <math.h>
#include <stdint.h>

#define B_SZ   4
#define LEN    4096
#define HID    1024
#define STATE  16
#define INNER  2048
#define M_TOT  (B_SZ * LEN)
#define NC     16
#define LC     256

// ---------------- scratch ----------------
__device__ __align__(1024) float g_xz   [(size_t)M_TOT * 2 * INNER];
__device__ __align__(1024) float g_xconv[(size_t)M_TOT * INNER];
__device__ __align__(1024) float g_dt   [(size_t)M_TOT * INNER];
__device__ __align__(1024) float g_Bm   [(size_t)M_TOT * STATE];
__device__ __align__(1024) float g_Cm   [(size_t)M_TOT * STATE];
__device__ __align__(1024) float g_P [(size_t)B_SZ * NC * STATE * INNER];
__device__ __align__(1024) float g_S [(size_t)B_SZ * NC * STATE * INNER];
__device__ __align__(1024) float g_H0[(size_t)B_SZ * NC * STATE * INNER];
__device__ __align__(1024) __half g_x0h [(size_t)M_TOT * HID];
__device__ __align__(1024) __half g_wh  [(size_t)2 * INNER * HID];
__device__ __align__(1024) __half g_dtwh[(size_t)INNER * INNER];
__device__ __align__(1024) __half g_xch [(size_t)M_TOT * INNER];
__device__ __align__(1024) __half g_y0h [(size_t)M_TOT * INNER];
__device__ __align__(1024) __half g_owh [(size_t)HID * INNER];
__device__ __align__(1024) __half g_wbch[32 * INNER];

// ---------------- PTX helpers ----------------
__device__ __forceinline__ uint32_t smem_u32(const void* p) {
    uint32_t a;
    asm("{ .reg .u64 t; cvta.to.shared.u64 t, %1; cvt.u32.u64 %0, t; }" : "=r"(a) : "l"(p));
    return a;
}
__device__ __forceinline__ void cp_async16(uint32_t dst, const void* src) {
    asm volatile("cp.async.cg.shared.global [%0], [%1], 16;" :: "r"(dst), "l"(src) : "memory");
}
#define CP_COMMIT() asm volatile("cp.async.commit_group;" ::: "memory")
#define CP_WAIT1()  asm volatile("cp.async.wait_group 1;" ::: "memory")

__device__ __forceinline__ void ldm_x4(uint32_t* r, uint32_t addr) {
    asm volatile("ldmatrix.sync.aligned.m8n8.x4.shared.b16 {%0,%1,%2,%3}, [%4];"
        : "=r"(r[0]), "=r"(r[1]), "=r"(r[2]), "=r"(r[3]) : "r"(addr));
}
__device__ __forceinline__ void mma16816h(float* d, const uint32_t* a, const uint32_t* b) {
    asm volatile("mma.sync.aligned.m16n8k16.row.col.f32.f16.f16.f32 "
        "{%0,%1,%2,%3}, {%4,%5,%6,%7}, {%8,%9}, {%0,%1,%2,%3};"
        : "+f"(d[0]), "+f"(d[1]), "+f"(d[2]), "+f"(d[3])
        : "r"(a[0]), "r"(a[1]), "r"(a[2]), "r"(a[3]), "r"(b[0]), "r"(b[1]));
}
__device__ __forceinline__ float softplusf(float v) { return v > 20.f ? v : log1pf(__expf(v)); }
__device__ __forceinline__ float siluf(float v)     { return v / (1.f + __expf(-v)); }

// ---------------- fp16 mma.sync GEMM: C[M,N] = A[M,K] @ B[N,K]^T + bias ----------------
// BM=128, BN=256, BK=64 (128B SW128 rows), 8 warps of 64x64 tiles, 3-stage cp.async.
// Cstride = row stride of C (supports column-block views).
#define GBM 128
#define GBN 256
#define GAST (GBM * 128)
#define GSTG (GAST + GBN * 128)
#define GSMEM (3 * GSTG)

template <int EPI>
__global__ void __launch_bounds__(256, 1) gemm_mma(
    const __half* __restrict__ Ap, const __half* __restrict__ Bp,
    const float* __restrict__ bias, float* __restrict__ C, int Cstride, int K)
{
    extern __shared__ char smraw[];
    const uint32_t sbase = smem_u32(smraw);
    const int tid  = threadIdx.x;
    const int wid  = tid >> 5;
    const int lane = tid & 31;
    const int bm0  = blockIdx.y * GBM;
    const int bn0  = blockIdx.x * GBN;

    const int KTT = K >> 6;
    const size_t lda = (size_t)K * 2;

    auto load_stage = [&](int kt, int s) {
        const uint32_t sa = sbase + s * GSTG;
        const uint32_t sb = sa + GAST;
#pragma unroll
        for (int i = 0; i < 4; ++i) {
            int idx = tid + i * 256, r = idx >> 3, c = idx & 7;
            cp_async16(sa + r * 128 + ((c ^ (r & 7)) << 4),
                       (const char*)Ap + (size_t)(bm0 + r) * lda + (size_t)kt * 128 + c * 16);
        }
#pragma unroll
        for (int i = 0; i < 8; ++i) {
            int idx = tid + i * 256, r = idx >> 3, c = idx & 7;
            cp_async16(sb + r * 128 + ((c ^ (r & 7)) << 4),
                       (const char*)Bp + (size_t)(bn0 + r) * lda + (size_t)kt * 128 + c * 16);
        }
    };

    float acc[4][8][4];
#pragma unroll
    for (int mt = 0; mt < 4; ++mt)
#pragma unroll
        for (int nt = 0; nt < 8; ++nt)
#pragma unroll
            for (int q = 0; q < 4; ++q) acc[mt][nt][q] = 0.f;

    load_stage(0, 0); CP_COMMIT();
    load_stage(1, 1); CP_COMMIT();

    const int wm0 = (wid >> 2) * 64;
    const int wn0 = (wid & 3) * 64;
    const int aRow = wm0 + ((lane >> 3) & 1) * 8 + (lane & 7);
    const int bRow = wn0 + ((lane >> 4) & 1) * 8 + (lane & 7);
    const int swzX = (lane & 7) << 4;
    const int aKs  = (lane >> 4) << 4;
    const int bKs  = ((lane >> 3) & 1) << 4;

    for (int kt = 0; kt < KTT; ++kt) {
        const int s = kt % 3;
        CP_WAIT1();
        __syncthreads();
        if (kt + 2 < KTT) { load_stage(kt + 2, (kt + 2) % 3); CP_COMMIT(); }

        const uint32_t Ab = sbase + s * GSTG;
        const uint32_t Bb = Ab + GAST;
#pragma unroll
        for (int ks = 0; ks < 4; ++ks) {
            const int swA = (ks * 32 + aKs) ^ swzX;
            const int swB = (ks * 32 + bKs) ^ swzX;
            uint32_t a[4][4], b[4][4];
#pragma unroll
            for (int mt = 0; mt < 4; ++mt) ldm_x4(a[mt], Ab + (aRow + mt * 16) * 128 + swA);
#pragma unroll
            for (int np = 0; np < 4; ++np) ldm_x4(b[np], Bb + (bRow + np * 16) * 128 + swB);
#pragma unroll
            for (int mt = 0; mt < 4; ++mt)
#pragma unroll
                for (int nt = 0; nt < 8; ++nt)
                    mma16816h(acc[mt][nt], a[mt], &b[nt >> 1][(nt & 1) * 2]);
        }
    }

#pragma unroll
    for (int nt = 0; nt < 8; ++nt) {
        const int col = bn0 + wn0 + nt * 8 + (lane & 3) * 2;
        const float b0v = bias[col], b1v = bias[col + 1];
#pragma unroll
        for (int mt = 0; mt < 4; ++mt) {
            const int row = bm0 + wm0 + mt * 16 + (lane >> 2);
            float v0 = acc[mt][nt][0] + b0v, v1 = acc[mt][nt][1] + b1v;
            float v2 = acc[mt][nt][2] + b0v, v3 = acc[mt][nt][3] + b1v;
            if (EPI == 1) {
                v0 = softplusf(v0); v1 = softplusf(v1);
                v2 = softplusf(v2); v3 = softplusf(v3);
            }
            *reinterpret_cast<float2*>(&C[(size_t)row * Cstride + col])       = make_float2(v0, v1);
            *reinterpret_cast<float2*>(&C[(size_t)(row + 8) * Cstride + col]) = make_float2(v2, v3);
        }
    }
}

// ---------------- B/C projection via mma: out[M,32] = xch[M,2048] @ Wbc[32,2048]^T ----------------
#define BCAST (128 * 128)
#define BCSTG (BCAST + 32 * 128)
#define BCSMEM (3 * BCSTG)
__global__ void __launch_bounds__(256, 1) bc_mma(
    const __half* __restrict__ A, const __half* __restrict__ W,
    const float* __restrict__ Bb, const float* __restrict__ Cb)
{
    extern __shared__ char smraw[];
    const uint32_t sbase = smem_u32(smraw);
    const int tid  = threadIdx.x;
    const int wid  = tid >> 5;
    const int lane = tid & 31;
    const int bm0  = blockIdx.x * 128;
    const size_t lda = (size_t)INNER * 2;

    auto load_stage = [&](int kt, int s) {
        const uint32_t sa = sbase + s * BCSTG;
        const uint32_t sb = sa + BCAST;
#pragma unroll
        for (int i = 0; i < 4; ++i) {
            int idx = tid + i * 256, r = idx >> 3, c = idx & 7;
            cp_async16(sa + r * 128 + ((c ^ (r & 7)) << 4),
                       (const char*)A + (size_t)(bm0 + r) * lda + (size_t)kt * 128 + c * 16);
        }
        {
            int r = tid >> 3, c = tid & 7;
            cp_async16(sb + r * 128 + ((c ^ (r & 7)) << 4),
                       (const char*)W + (size_t)r * lda + (size_t)kt * 128 + c * 16);
        }
    };

    float acc[4][4];
#pragma unroll
    for (int nt = 0; nt < 4; ++nt)
#pragma unroll
        for (int q = 0; q < 4; ++q) acc[nt][q] = 0.f;

    load_stage(0, 0); CP_COMMIT();
    load_stage(1, 1); CP_COMMIT();

    const int aRow = wid * 16 + ((lane >> 3) & 1) * 8 + (lane & 7);
    const int bRow = ((lane >> 4) & 1) * 8 + (lane & 7);
    const int swzX = (lane & 7) << 4;
    const int aKs  = (lane >> 4) << 4;
    const int bKs  = ((lane >> 3) & 1) << 4;

    const int KT = INNER / 64;
    for (int kt = 0; kt < KT; ++kt) {
        const int s = kt % 3;
        CP_WAIT1();
        __syncthreads();
        if (kt + 2 < KT) { load_stage(kt + 2, (kt + 2) % 3); CP_COMMIT(); }

        const uint32_t Ab = sbase + s * BCSTG;
        const uint32_t Bb_ = Ab + BCAST;
#pragma unroll
        for (int ks = 0; ks < 4; ++ks) {
            const int swA = (ks * 32 + aKs) ^ swzX;
            const int swB = (ks * 32 + bKs) ^ swzX;
            uint32_t a[4], b[2][4];
            ldm_x4(a, Ab + aRow * 128 + swA);
#pragma unroll
            for (int np = 0; np < 2; ++np) ldm_x4(b[np], Bb_ + (bRow + np * 16) * 128 + swB);
#pragma unroll
            for (int nt = 0; nt < 4; ++nt)
                mma16816h(acc[nt], a, &b[nt >> 1][(nt & 1) * 2]);
        }
    }

#pragma unroll
    for (int nt = 0; nt < 4; ++nt) {
        const int col = nt * 8 + (lane & 3) * 2;
        const int row = bm0 + wid * 16 + (lane >> 2);
        if (col < 16) {
            const float c0 = Bb[col], c1 = Bb[col + 1];
            *reinterpret_cast<float2*>(&g_Bm[(size_t)row * 16 + col]) =
                make_float2(acc[nt][0] + c0, acc[nt][1] + c1);
            *reinterpret_cast<float2*>(&g_Bm[(size_t)(row + 8) * 16 + col]) =
                make_float2(acc[nt][2] + c0, acc[nt][3] + c1);
        } else {
            const int cc = col - 16;
            const float c0 = Cb[cc], c1 = Cb[cc + 1];
            *reinterpret_cast<float2*>(&g_Cm[(size_t)row * 16 + cc]) =
                make_float2(acc[nt][0] + c0, acc[nt][1] + c1);
            *reinterpret_cast<float2*>(&g_Cm[(size_t)(row + 8) * 16 + cc]) =
                make_float2(acc[nt][2] + c0, acc[nt][3] + c1);
        }
    }
}

// ---------------- conversion kernels ----------------
__global__ void __launch_bounds__(256) cvt1h_kernel(
    const float* __restrict__ in, __half* __restrict__ o0, size_t n4)
{
    for (size_t i = (size_t)blockIdx.x * 256 + threadIdx.x; i < n4; i += (size_t)gridDim.x * 256) {
        float4 v = reinterpret_cast<const float4*>(in)[i];
        ((ushort4*)o0)[i] = make_ushort4(
            __half_as_ushort(__float2half_rn(v.x)), __half_as_ushort(__float2half_rn(v.y)),
            __half_as_ushort(__float2half_rn(v.z)), __half_as_ushort(__float2half_rn(v.w)));
    }
}
__global__ void __launch_bounds__(256) cvtbc_kernel(
    const float* __restrict__ Bw, const float* __restrict__ Cw, __half* __restrict__ o)
{
    int i = blockIdx.x * 256 + threadIdx.x;
    int r = i / INNER, k = i - r * INNER;
    float v = (r < 16) ? Bw[(size_t)r * INNER + k] : Cw[(size_t)(r - 16) * INNER + k];
    o[i] = __float2half_rn(v);
}

// ---------------- causal depthwise conv (K=4) + SiLU ----------------
__global__ void __launch_bounds__(256) conv_silu_kernel(
    const float* __restrict__ conv_w, const float* __restrict__ conv_b)
{
    const int d  = blockIdx.x * 256 + threadIdx.x;
    const int l0 = blockIdx.y * 128;
    const int b  = blockIdx.z;
    const float w0 = conv_w[d * 4 + 0], w1 = conv_w[d * 4 + 1];
    const float w2 = conv_w[d * 4 + 2], w3 = conv_w[d * 4 + 3];
    const float cb = conv_b[d];
    const float* xp = g_xz + (size_t)(b * LEN) * (2 * INNER) + d;
    float m3, m2, m1;
    if (l0 == 0) { m3 = m2 = m1 = 0.f; }
    else {
        m3 = xp[(size_t)(l0 - 3) * (2 * INNER)];
        m2 = xp[(size_t)(l0 - 2) * (2 * INNER)];
        m1 = xp[(size_t)(l0 - 1) * (2 * INNER)];
    }
    float*  xc = g_xconv + (size_t)(b * LEN + l0) * INNER + d;
    __half* xh = g_xch   + (size_t)(b * LEN + l0) * INNER + d;
#pragma unroll 4
    for (int i = 0; i < 128; ++i) {
        float cur = xp[(size_t)(l0 + i) * (2 * INNER)];
        float v = siluf(w0 * m3 + w1 * m2 + w2 * m1 + w3 * cur + cb);
        xc[(size_t)i * INNER] = v;
        xh[(size_t)i * INNER] = __float2half_rn(v);
        m3 = m2; m2 = m1; m1 = cur;
    }
}

// ---------------- chunked selective scan ----------------
__global__ void __launch_bounds__(128) scanA_kernel(const float* __restrict__ A_log)
{
    __shared__ float sB[LC * STATE];
    const int d = blockIdx.x * 128 + threadIdx.x;
    const int c = blockIdx.y;
    const int b = blockIdx.z;
    const int base_l = c * LC;
    for (int i = threadIdx.x; i < LC * STATE; i += 128)
        sB[i] = g_Bm[(size_t)(b * LEN + base_l) * STATE + i];
    __syncthreads();
    float Ar[STATE];
#pragma unroll
    for (int s = 0; s < STATE; s++) Ar[s] = -expf(A_log[d * STATE + s]);
    float h[STATE], Pr[STATE];
#pragma unroll
    for (int s = 0; s < STATE; s++) { h[s] = 0.f; Pr[s] = 1.f; }
    const float* dtp = g_dt    + (size_t)(b * LEN + base_l) * INNER + d;
    const float* xcp = g_xconv + (size_t)(b * LEN + base_l) * INNER + d;
    for (int l = 0; l < LC; ++l) {
        float dtv = dtp[(size_t)l * INNER];
        float dtx = dtv * xcp[(size_t)l * INNER];
#pragma unroll
        for (int s = 0; s < STATE; s++) {
            float dA = __expf(dtv * Ar[s]);
            Pr[s] *= dA;
            h[s] = fmaf(dA, h[s], sB[l * STATE + s] * dtx);
        }
    }
    size_t ob = (size_t)(b * NC + c) * STATE * INNER + d;
#pragma unroll
    for (int s = 0; s < STATE; s++) {
        g_P[ob + (size_t)s * INNER] = Pr[s];
        g_S[ob + (size_t)s * INNER] = h[s];
    }
}

__global__ void __launch_bounds__(256) scanB_kernel()
{
    int g = blockIdx.x * 256 + threadIdx.x;
    int b = g / (STATE * INNER);
    int r = g - b * (STATE * INNER);
    float h = 0.f;
    for (int c = 0; c < NC; ++c) {
        size_t idx = (size_t)(b * NC + c) * STATE * INNER + r;
        g_H0[idx] = h;
        h = g_P[idx] * h + g_S[idx];
    }
}

__global__ void __launch_bounds__(128) scanC_kernel(
    const float* __restrict__ A_log, const float* __restrict__ Dv)
{
    __shared__ float sB[LC * STATE];
    __shared__ float sC[LC * STATE];
    const int d = blockIdx.x * 128 + threadIdx.x;
    const int c = blockIdx.y;
    const int b = blockIdx.z;
    const int base_l = c * LC;
    for (int i = threadIdx.x; i < LC * STATE; i += 128) {
        sB[i] = g_Bm[(size_t)(b * LEN + base_l) * STATE + i];
        sC[i] = g_Cm[(size_t)(b * LEN + base_l) * STATE + i];
    }
    __syncthreads();
    float Ar[STATE];
#pragma unroll
    for (int s = 0; s < STATE; s++) Ar[s] = -expf(A_log[d * STATE + s]);
    const float Dd = Dv[d];
    float h[STATE];
    size_t ob = (size_t)(b * NC + c) * STATE * INNER + d;
#pragma unroll
    for (int s = 0; s < STATE; s++) h[s] = g_H0[ob + (size_t)s * INNER];
    const float* dtp = g_dt    + (size_t)(b * LEN + base_l) * INNER + d;
    const float* xcp = g_xconv + (size_t)(b * LEN + base_l) * INNER + d;
    const float* zp  = g_xz    + (size_t)(b * LEN + base_l) * (2 * INNER) + INNER + d;
    __half* y0p = g_y0h + (size_t)(b * LEN + base_l) * INNER + d;
    for (int l = 0; l < LC; ++l) {
        float dtv = dtp[(size_t)l * INNER];
        float xv  = xcp[(size_t)l * INNER];
        float zv  = zp[(size_t)l * (2 * INNER)];
        float dtx = dtv * xv;
        float acc = Dd * xv;
#pragma unroll
        for (int s = 0; s < STATE; s++) {
            float dA = __expf(dtv * Ar[s]);
            h[s] = fmaf(dA, h[s], sB[l * STATE + s] * dtx);
            acc  = fmaf(sC[l * STATE + s], h[s], acc);
        }
        y0p[(size_t)l * INNER] = __float2half_rn(acc * siluf(zv));
    }
}

// ---------------- launch ----------------
extern "C" void kernel_launch(void* const* d_in, const int* in_sizes, int n_in,
                              void* d_out, int out_size)
{
    const float* x      = (const float*)d_in[0];
    const float* in_w   = (const float*)d_in[1];
    const float* in_b   = (const float*)d_in[2];
    const float* conv_w = (const float*)d_in[3];
    const float* conv_b = (const float*)d_in[4];
    const float* dt_w   = (const float*)d_in[5];
    const float* dt_b   = (const float*)d_in[6];
    const float* A_log  = (const float*)d_in[7];
    const float* B_w    = (const float*)d_in[8];
    const float* B_b    = (const float*)d_in[9];
    const float* C_w    = (const float*)d_in[10];
    const float* C_b    = (const float*)d_in[11];
    const float* Dv     = (const float*)d_in[12];
    const float* out_w  = (const float*)d_in[13];
    const float* out_b  = (const float*)d_in[14];
    float* out = (float*)d_out;

    float *xz, *dt;
    __half *x0h, *wh, *dtwh, *xch, *y0h, *owh, *wbch;
    cudaGetSymbolAddress((void**)&xz, g_xz);
    cudaGetSymbolAddress((void**)&dt, g_dt);
    cudaGetSymbolAddress((void**)&x0h, g_x0h);
    cudaGetSymbolAddress((void**)&wh, g_wh);
    cudaGetSymbolAddress((void**)&dtwh, g_dtwh);
    cudaGetSymbolAddress((void**)&xch, g_xch);
    cudaGetSymbolAddress((void**)&y0h, g_y0h);
    cudaGetSymbolAddress((void**)&owh, g_owh);
    cudaGetSymbolAddress((void**)&wbch, g_wbch);

    cudaFuncSetAttribute(gemm_mma<0>, cudaFuncAttributeMaxDynamicSharedMemorySize, GSMEM);
    cudaFuncSetAttribute(gemm_mma<1>, cudaFuncAttributeMaxDynamicSharedMemorySize, GSMEM);
    cudaFuncSetAttribute(bc_mma, cudaFuncAttributeMaxDynamicSharedMemorySize, BCSMEM);

    // 0) fp16 conversions
    cvt1h_kernel<<<2048, 256>>>(x, x0h, (size_t)M_TOT * HID / 4);
    cvt1h_kernel<<<1024, 256>>>(in_w, wh, (size_t)2 * INNER * HID / 4);
    cvt1h_kernel<<<1024, 256>>>(dt_w, dtwh, (size_t)INNER * INNER / 4);
    cvt1h_kernel<<<512, 256>>>(out_w, owh, (size_t)HID * INNER / 4);
    cvtbc_kernel<<<(32 * INNER) / 256, 256>>>(B_w, C_w, wbch);

    // 1) in-proj, 1-pass fp16: xz = x @ in_w^T + in_b      (16384 x 4096 x 1024)
    gemm_mma<0><<<dim3(2 * INNER / GBN, M_TOT / GBM), 256, GSMEM>>>(
        x0h, wh, in_b, xz, 2 * INNER, HID);

    // 2) conv + silu
    conv_silu_kernel<<<dim3(INNER / 256, LEN / 128, B_SZ), 256>>>(conv_w, conv_b);

    // 3) B/C projections via mma (N = 32)
    bc_mma<<<M_TOT / 128, 256, BCSMEM>>>(xch, wbch, B_b, C_b);

    // 4) dt = softplus(xconv @ dt_w^T + dt_b), 1-pass fp16 (16384 x 2048 x 2048)
    gemm_mma<1><<<dim3(INNER / GBN, M_TOT / GBM), 256, GSMEM>>>(
        xch, dtwh, dt_b, dt, INNER, INNER);

    // 5) chunked selective scan + gating
    scanA_kernel<<<dim3(INNER / 128, NC, B_SZ), 128>>>(A_log);
    scanB_kernel<<<(B_SZ * STATE * INNER) / 256, 256>>>();
    scanC_kernel<<<dim3(INNER / 128, NC, B_SZ), 128>>>(A_log, Dv);

    // 6) out-proj, 1-pass fp16: out = y @ out_w^T + out_b  (16384 x 1024 x 2048)
    gemm_mma<0><<<dim3(HID / GBN, M_TOT / GBM), 256, GSMEM>>>(
        y0h, owh, out_b, out, HID, INNER);
}

// round 8
// speedup vs baseline: 4.5447x; 1.0285x over previous
#include <cuda_runtime.h>
#include <cuda_fp16.h>
#include <math.h>
#include <stdint.h>

#define B_SZ   4
#define LEN    4096
#define HID    1024
#define STATE  16
#define INNER  2048
#define M_TOT  (B_SZ * LEN)
#define NC     16
#define LC     256

// ---------------- scratch ----------------
__device__ __align__(1024) float  g_xp  [(size_t)M_TOT * INNER];   // x_part fp32 (conv input)
__device__ __align__(1024) float  g_Bm  [(size_t)M_TOT * STATE];
__device__ __align__(1024) float  g_Cm  [(size_t)M_TOT * STATE];
__device__ __align__(1024) float  g_P [(size_t)B_SZ * NC * STATE * INNER];
__device__ __align__(1024) float  g_S [(size_t)B_SZ * NC * STATE * INNER];
__device__ __align__(1024) float  g_H0[(size_t)B_SZ * NC * STATE * INNER];
__device__ __align__(1024) __half g_zh  [(size_t)M_TOT * INNER];   // z fp16
__device__ __align__(1024) __half g_dth [(size_t)M_TOT * INNER];   // softplus(dt) fp16
__device__ __align__(1024) __half g_x0h [(size_t)M_TOT * HID];
__device__ __align__(1024) __half g_wh  [(size_t)2 * INNER * HID];
__device__ __align__(1024) __half g_dtwh[(size_t)INNER * INNER];
__device__ __align__(1024) __half g_xch [(size_t)M_TOT * INNER];   // conv+silu fp16
__device__ __align__(1024) __half g_y0h [(size_t)M_TOT * INNER];
__device__ __align__(1024) __half g_owh [(size_t)HID * INNER];
__device__ __align__(1024) __half g_wbch[32 * INNER];

// ---------------- PTX helpers ----------------
__device__ __forceinline__ uint32_t smem_u32(const void* p) {
    uint32_t a;
    asm("{ .reg .u64 t; cvta.to.shared.u64 t, %1; cvt.u32.u64 %0, t; }" : "=r"(a) : "l"(p));
    return a;
}
__device__ __forceinline__ void cp_async16(uint32_t dst, const void* src) {
    asm volatile("cp.async.cg.shared.global [%0], [%1], 16;" :: "r"(dst), "l"(src) : "memory");
}
#define CP_COMMIT() asm volatile("cp.async.commit_group;" ::: "memory")
#define CP_WAIT1()  asm volatile("cp.async.wait_group 1;" ::: "memory")

__device__ __forceinline__ void ldm_x4(uint32_t* r, uint32_t addr) {
    asm volatile("ldmatrix.sync.aligned.m8n8.x4.shared.b16 {%0,%1,%2,%3}, [%4];"
        : "=r"(r[0]), "=r"(r[1]), "=r"(r[2]), "=r"(r[3]) : "r"(addr));
}
__device__ __forceinline__ void mma16816h(float* d, const uint32_t* a, const uint32_t* b) {
    asm volatile("mma.sync.aligned.m16n8k16.row.col.f32.f16.f16.f32 "
        "{%0,%1,%2,%3}, {%4,%5,%6,%7}, {%8,%9}, {%0,%1,%2,%3};"
        : "+f"(d[0]), "+f"(d[1]), "+f"(d[2]), "+f"(d[3])
        : "r"(a[0]), "r"(a[1]), "r"(a[2]), "r"(a[3]), "r"(b[0]), "r"(b[1]));
}
__device__ __forceinline__ float softplusf(float v) { return v > 20.f ? v : log1pf(__expf(v)); }
__device__ __forceinline__ float siluf(float v)     { return v / (1.f + __expf(-v)); }

// ---------------- fp16 mma.sync GEMM: C[M,N] = A[M,K] @ B[N,K]^T + bias ----------------
// BM=128, BN=256, BK=64 (SW128), 8 warps of 64x64 tiles, 3-stage cp.async.
// EPI: 0 = fp32 bias, 1 = fp16 softplus(bias+acc), 2 = fp16 bias+acc.
#define GBM 128
#define GBN 256
#define GAST (GBM * 128)
#define GSTG (GAST + GBN * 128)
#define GSMEM (3 * GSTG)

template <int EPI>
__global__ void __launch_bounds__(256, 1) gemm_mma(
    const __half* __restrict__ Ap, const __half* __restrict__ Bp,
    const float* __restrict__ bias, void* __restrict__ Cv, int Cstride, int K)
{
    extern __shared__ char smraw[];
    const uint32_t sbase = smem_u32(smraw);
    const int tid  = threadIdx.x;
    const int wid  = tid >> 5;
    const int lane = tid & 31;
    const int bm0  = blockIdx.y * GBM;
    const int bn0  = blockIdx.x * GBN;

    const int KTT = K >> 6;
    const size_t lda = (size_t)K * 2;

    auto load_stage = [&](int kt, int s) {
        const uint32_t sa = sbase + s * GSTG;
        const uint32_t sb = sa + GAST;
#pragma unroll
        for (int i = 0; i < 4; ++i) {
            int idx = tid + i * 256, r = idx >> 3, c = idx & 7;
            cp_async16(sa + r * 128 + ((c ^ (r & 7)) << 4),
                       (const char*)Ap + (size_t)(bm0 + r) * lda + (size_t)kt * 128 + c * 16);
        }
#pragma unroll
        for (int i = 0; i < 8; ++i) {
            int idx = tid + i * 256, r = idx >> 3, c = idx & 7;
            cp_async16(sb + r * 128 + ((c ^ (r & 7)) << 4),
                       (const char*)Bp + (size_t)(bn0 + r) * lda + (size_t)kt * 128 + c * 16);
        }
    };

    float acc[4][8][4];
#pragma unroll
    for (int mt = 0; mt < 4; ++mt)
#pragma unroll
        for (int nt = 0; nt < 8; ++nt)
#pragma unroll
            for (int q = 0; q < 4; ++q) acc[mt][nt][q] = 0.f;

    load_stage(0, 0); CP_COMMIT();
    load_stage(1, 1); CP_COMMIT();

    const int wm0 = (wid >> 2) * 64;
    const int wn0 = (wid & 3) * 64;
    const int aRow = wm0 + ((lane >> 3) & 1) * 8 + (lane & 7);
    const int bRow = wn0 + ((lane >> 4) & 1) * 8 + (lane & 7);
    const int swzX = (lane & 7) << 4;
    const int aKs  = (lane >> 4) << 4;
    const int bKs  = ((lane >> 3) & 1) << 4;

    for (int kt = 0; kt < KTT; ++kt) {
        const int s = kt % 3;
        CP_WAIT1();
        __syncthreads();
        if (kt + 2 < KTT) { load_stage(kt + 2, (kt + 2) % 3); CP_COMMIT(); }

        const uint32_t Ab = sbase + s * GSTG;
        const uint32_t Bb = Ab + GAST;
#pragma unroll
        for (int ks = 0; ks < 4; ++ks) {
            const int swA = (ks * 32 + aKs) ^ swzX;
            const int swB = (ks * 32 + bKs) ^ swzX;
            uint32_t a[4][4], b[4][4];
#pragma unroll
            for (int mt = 0; mt < 4; ++mt) ldm_x4(a[mt], Ab + (aRow + mt * 16) * 128 + swA);
#pragma unroll
            for (int np = 0; np < 4; ++np) ldm_x4(b[np], Bb + (bRow + np * 16) * 128 + swB);
#pragma unroll
            for (int mt = 0; mt < 4; ++mt)
#pragma unroll
                for (int nt = 0; nt < 8; ++nt)
                    mma16816h(acc[mt][nt], a[mt], &b[nt >> 1][(nt & 1) * 2]);
        }
    }

#pragma unroll
    for (int nt = 0; nt < 8; ++nt) {
        const int col = bn0 + wn0 + nt * 8 + (lane & 3) * 2;
        const float b0v = bias[col], b1v = bias[col + 1];
#pragma unroll
        for (int mt = 0; mt < 4; ++mt) {
            const int row = bm0 + wm0 + mt * 16 + (lane >> 2);
            float v0 = acc[mt][nt][0] + b0v, v1 = acc[mt][nt][1] + b1v;
            float v2 = acc[mt][nt][2] + b0v, v3 = acc[mt][nt][3] + b1v;
            if (EPI == 1) {
                v0 = softplusf(v0); v1 = softplusf(v1);
                v2 = softplusf(v2); v3 = softplusf(v3);
            }
            if (EPI == 0) {
                float* C = (float*)Cv;
                *reinterpret_cast<float2*>(&C[(size_t)row * Cstride + col])       = make_float2(v0, v1);
                *reinterpret_cast<float2*>(&C[(size_t)(row + 8) * Cstride + col]) = make_float2(v2, v3);
            } else {
                __half* C = (__half*)Cv;
                *reinterpret_cast<__half2*>(&C[(size_t)row * Cstride + col])       = __floats2half2_rn(v0, v1);
                *reinterpret_cast<__half2*>(&C[(size_t)(row + 8) * Cstride + col]) = __floats2half2_rn(v2, v3);
            }
        }
    }
}

// ---------------- B/C projection via mma: out[M,32] = xch[M,2048] @ Wbc[32,2048]^T ----------------
#define BCAST (128 * 128)
#define BCSTG (BCAST + 32 * 128)
#define BCSMEM (3 * BCSTG)
__global__ void __launch_bounds__(256, 1) bc_mma(
    const __half* __restrict__ A, const __half* __restrict__ W,
    const float* __restrict__ Bb, const float* __restrict__ Cb)
{
    extern __shared__ char smraw[];
    const uint32_t sbase = smem_u32(smraw);
    const int tid  = threadIdx.x;
    const int wid  = tid >> 5;
    const int lane = tid & 31;
    const int bm0  = blockIdx.x * 128;
    const size_t lda = (size_t)INNER * 2;

    auto load_stage = [&](int kt, int s) {
        const uint32_t sa = sbase + s * BCSTG;
        const uint32_t sb = sa + BCAST;
#pragma unroll
        for (int i = 0; i < 4; ++i) {
            int idx = tid + i * 256, r = idx >> 3, c = idx & 7;
            cp_async16(sa + r * 128 + ((c ^ (r & 7)) << 4),
                       (const char*)A + (size_t)(bm0 + r) * lda + (size_t)kt * 128 + c * 16);
        }
        {
            int r = tid >> 3, c = tid & 7;
            cp_async16(sb + r * 128 + ((c ^ (r & 7)) << 4),
                       (const char*)W + (size_t)r * lda + (size_t)kt * 128 + c * 16);
        }
    };

    float acc[4][4];
#pragma unroll
    for (int nt = 0; nt < 4; ++nt)
#pragma unroll
        for (int q = 0; q < 4; ++q) acc[nt][q] = 0.f;

    load_stage(0, 0); CP_COMMIT();
    load_stage(1, 1); CP_COMMIT();

    const int aRow = wid * 16 + ((lane >> 3) & 1) * 8 + (lane & 7);
    const int bRow = ((lane >> 4) & 1) * 8 + (lane & 7);
    const int swzX = (lane & 7) << 4;
    const int aKs  = (lane >> 4) << 4;
    const int bKs  = ((lane >> 3) & 1) << 4;

    const int KT = INNER / 64;
    for (int kt = 0; kt < KT; ++kt) {
        const int s = kt % 3;
        CP_WAIT1();
        __syncthreads();
        if (kt + 2 < KT) { load_stage(kt + 2, (kt + 2) % 3); CP_COMMIT(); }

        const uint32_t Ab = sbase + s * BCSTG;
        const uint32_t Bb_ = Ab + BCAST;
#pragma unroll
        for (int ks = 0; ks < 4; ++ks) {
            const int swA = (ks * 32 + aKs) ^ swzX;
            const int swB = (ks * 32 + bKs) ^ swzX;
            uint32_t a[4], b[2][4];
            ldm_x4(a, Ab + aRow * 128 + swA);
#pragma unroll
            for (int np = 0; np < 2; ++np) ldm_x4(b[np], Bb_ + (bRow + np * 16) * 128 + swB);
#pragma unroll
            for (int nt = 0; nt < 4; ++nt)
                mma16816h(acc[nt], a, &b[nt >> 1][(nt & 1) * 2]);
        }
    }

#pragma unroll
    for (int nt = 0; nt < 4; ++nt) {
        const int col = nt * 8 + (lane & 3) * 2;
        const int row = bm0 + wid * 16 + (lane >> 2);
        if (col < 16) {
            const float c0 = Bb[col], c1 = Bb[col + 1];
            *reinterpret_cast<float2*>(&g_Bm[(size_t)row * 16 + col]) =
                make_float2(acc[nt][0] + c0, acc[nt][1] + c1);
            *reinterpret_cast<float2*>(&g_Bm[(size_t)(row + 8) * 16 + col]) =
                make_float2(acc[nt][2] + c0, acc[nt][3] + c1);
        } else {
            const int cc = col - 16;
            const float c0 = Cb[cc], c1 = Cb[cc + 1];
            *reinterpret_cast<float2*>(&g_Cm[(size_t)row * 16 + cc]) =
                make_float2(acc[nt][0] + c0, acc[nt][1] + c1);
            *reinterpret_cast<float2*>(&g_Cm[(size_t)(row + 8) * 16 + cc]) =
                make_float2(acc[nt][2] + c0, acc[nt][3] + c1);
        }
    }
}

// ---------------- conversion kernels ----------------
__global__ void __launch_bounds__(256) cvt1h_kernel(
    const float* __restrict__ in, __half* __restrict__ o0, size_t n4)
{
    for (size_t i = (size_t)blockIdx.x * 256 + threadIdx.x; i < n4; i += (size_t)gridDim.x * 256) {
        float4 v = reinterpret_cast<const float4*>(in)[i];
        ((ushort4*)o0)[i] = make_ushort4(
            __half_as_ushort(__float2half_rn(v.x)), __half_as_ushort(__float2half_rn(v.y)),
            __half_as_ushort(__float2half_rn(v.z)), __half_as_ushort(__float2half_rn(v.w)));
    }
}
__global__ void __launch_bounds__(256) cvtbc_kernel(
    const float* __restrict__ Bw, const float* __restrict__ Cw, __half* __restrict__ o)
{
    int i = blockIdx.x * 256 + threadIdx.x;
    int r = i / INNER, k = i - r * INNER;
    float v = (r < 16) ? Bw[(size_t)r * INNER + k] : Cw[(size_t)(r - 16) * INNER + k];
    o[i] = __float2half_rn(v);
}

// ---------------- causal depthwise conv (K=4) + SiLU -> fp16 ----------------
__global__ void __launch_bounds__(256) conv_silu_kernel(
    const float* __restrict__ conv_w, const float* __restrict__ conv_b)
{
    const int d  = blockIdx.x * 256 + threadIdx.x;
    const int l0 = blockIdx.y * 128;
    const int b  = blockIdx.z;
    const float w0 = conv_w[d * 4 + 0], w1 = conv_w[d * 4 + 1];
    const float w2 = conv_w[d * 4 + 2], w3 = conv_w[d * 4 + 3];
    const float cb = conv_b[d];
    const float* xp = g_xp + (size_t)(b * LEN) * INNER + d;
    float m3, m2, m1;
    if (l0 == 0) { m3 = m2 = m1 = 0.f; }
    else {
        m3 = xp[(size_t)(l0 - 3) * INNER];
        m2 = xp[(size_t)(l0 - 2) * INNER];
        m1 = xp[(size_t)(l0 - 1) * INNER];
    }
    __half* xh = g_xch + (size_t)(b * LEN + l0) * INNER + d;
#pragma unroll 4
    for (int i = 0; i < 128; ++i) {
        float cur = xp[(size_t)(l0 + i) * INNER];
        float v = siluf(w0 * m3 + w1 * m2 + w2 * m1 + w3 * cur + cb);
        xh[(size_t)i * INNER] = __float2half_rn(v);
        m3 = m2; m2 = m1; m1 = cur;
    }
}

// ---------------- chunked selective scan ----------------
__global__ void __launch_bounds__(128) scanA_kernel(const float* __restrict__ A_log)
{
    __shared__ float sB[LC * STATE];
    const int d = blockIdx.x * 128 + threadIdx.x;
    const int c = blockIdx.y;
    const int b = blockIdx.z;
    const int base_l = c * LC;
    for (int i = threadIdx.x; i < LC * STATE; i += 128)
        sB[i] = g_Bm[(size_t)(b * LEN + base_l) * STATE + i];
    __syncthreads();
    float Ar[STATE];
#pragma unroll
    for (int s = 0; s < STATE; s++) Ar[s] = -expf(A_log[d * STATE + s]);
    float h[STATE], Pr[STATE];
#pragma unroll
    for (int s = 0; s < STATE; s++) { h[s] = 0.f; Pr[s] = 1.f; }
    const __half* dtp = g_dth + (size_t)(b * LEN + base_l) * INNER + d;
    const __half* xcp = g_xch + (size_t)(b * LEN + base_l) * INNER + d;
    for (int l = 0; l < LC; ++l) {
        float dtv = __half2float(dtp[(size_t)l * INNER]);
        float dtx = dtv * __half2float(xcp[(size_t)l * INNER]);
#pragma unroll
        for (int s = 0; s < STATE; s++) {
            float dA = __expf(dtv * Ar[s]);
            Pr[s] *= dA;
            h[s] = fmaf(dA, h[s], sB[l * STATE + s] * dtx);
        }
    }
    size_t ob = (size_t)(b * NC + c) * STATE * INNER + d;
#pragma unroll
    for (int s = 0; s < STATE; s++) {
        g_P[ob + (size_t)s * INNER] = Pr[s];
        g_S[ob + (size_t)s * INNER] = h[s];
    }
}

__global__ void __launch_bounds__(256) scanB_kernel()
{
    int g = blockIdx.x * 256 + threadIdx.x;
    int b = g / (STATE * INNER);
    int r = g - b * (STATE * INNER);
    float h = 0.f;
    for (int c = 0; c < NC; ++c) {
        size_t idx = (size_t)(b * NC + c) * STATE * INNER + r;
        g_H0[idx] = h;
        h = g_P[idx] * h + g_S[idx];
    }
}

__global__ void __launch_bounds__(128) scanC_kernel(
    const float* __restrict__ A_log, const float* __restrict__ Dv)
{
    __shared__ float sB[LC * STATE];
    __shared__ float sC[LC * STATE];
    const int d = blockIdx.x * 128 + threadIdx.x;
    const int c = blockIdx.y;
    const int b = blockIdx.z;
    const int base_l = c * LC;
    for (int i = threadIdx.x; i < LC * STATE; i += 128) {
        sB[i] = g_Bm[(size_t)(b * LEN + base_l) * STATE + i];
        sC[i] = g_Cm[(size_t)(b * LEN + base_l) * STATE + i];
    }
    __syncthreads();
    float Ar[STATE];
#pragma unroll
    for (int s = 0; s < STATE; s++) Ar[s] = -expf(A_log[d * STATE + s]);
    const float Dd = Dv[d];
    float h[STATE];
    size_t ob = (size_t)(b * NC + c) * STATE * INNER + d;
#pragma unroll
    for (int s = 0; s < STATE; s++) h[s] = g_H0[ob + (size_t)s * INNER];
    const __half* dtp = g_dth + (size_t)(b * LEN + base_l) * INNER + d;
    const __half* xcp = g_xch + (size_t)(b * LEN + base_l) * INNER + d;
    const __half* zp  = g_zh  + (size_t)(b * LEN + base_l) * INNER + d;
    __half* y0p = g_y0h + (size_t)(b * LEN + base_l) * INNER + d;
    for (int l = 0; l < LC; ++l) {
        float dtv = __half2float(dtp[(size_t)l * INNER]);
        float xv  = __half2float(xcp[(size_t)l * INNER]);
        float zv  = __half2float(zp[(size_t)l * INNER]);
        float dtx = dtv * xv;
        float acc = Dd * xv;
#pragma unroll
        for (int s = 0; s < STATE; s++) {
            float dA = __expf(dtv * Ar[s]);
            h[s] = fmaf(dA, h[s], sB[l * STATE + s] * dtx);
            acc  = fmaf(sC[l * STATE + s], h[s], acc);
        }
        y0p[(size_t)l * INNER] = __float2half_rn(acc * siluf(zv));
    }
}

// ---------------- launch ----------------
extern "C" void kernel_launch(void* const* d_in, const int* in_sizes, int n_in,
                              void* d_out, int out_size)
{
    const float* x      = (const float*)d_in[0];
    const float* in_w   = (const float*)d_in[1];
    const float* in_b   = (const float*)d_in[2];
    const float* conv_w = (const float*)d_in[3];
    const float* conv_b = (const float*)d_in[4];
    const float* dt_w   = (const float*)d_in[5];
    const float* dt_b   = (const float*)d_in[6];
    const float* A_log  = (const float*)d_in[7];
    const float* B_w    = (const float*)d_in[8];
    const float* B_b    = (const float*)d_in[9];
    const float* C_w    = (const float*)d_in[10];
    const float* C_b    = (const float*)d_in[11];
    const float* Dv     = (const float*)d_in[12];
    const float* out_w  = (const float*)d_in[13];
    const float* out_b  = (const float*)d_in[14];
    float* out = (float*)d_out;

    float *xp;
    __half *x0h, *wh, *dtwh, *xch, *y0h, *owh, *wbch, *zh, *dth;
    cudaGetSymbolAddress((void**)&xp, g_xp);
    cudaGetSymbolAddress((void**)&x0h, g_x0h);
    cudaGetSymbolAddress((void**)&wh, g_wh);
    cudaGetSymbolAddress((void**)&dtwh, g_dtwh);
    cudaGetSymbolAddress((void**)&xch, g_xch);
    cudaGetSymbolAddress((void**)&y0h, g_y0h);
    cudaGetSymbolAddress((void**)&owh, g_owh);
    cudaGetSymbolAddress((void**)&wbch, g_wbch);
    cudaGetSymbolAddress((void**)&zh, g_zh);
    cudaGetSymbolAddress((void**)&dth, g_dth);

    cudaFuncSetAttribute(gemm_mma<0>, cudaFuncAttributeMaxDynamicSharedMemorySize, GSMEM);
    cudaFuncSetAttribute(gemm_mma<1>, cudaFuncAttributeMaxDynamicSharedMemorySize, GSMEM);
    cudaFuncSetAttribute(gemm_mma<2>, cudaFuncAttributeMaxDynamicSharedMemorySize, GSMEM);
    cudaFuncSetAttribute(bc_mma, cudaFuncAttributeMaxDynamicSharedMemorySize, BCSMEM);

    // 0) fp16 conversions
    cvt1h_kernel<<<2048, 256>>>(x, x0h, (size_t)M_TOT * HID / 4);
    cvt1h_kernel<<<1024, 256>>>(in_w, wh, (size_t)2 * INNER * HID / 4);
    cvt1h_kernel<<<1024, 256>>>(dt_w, dtwh, (size_t)INNER * INNER / 4);
    cvt1h_kernel<<<512, 256>>>(out_w, owh, (size_t)HID * INNER / 4);
    cvtbc_kernel<<<(32 * INNER) / 256, 256>>>(B_w, C_w, wbch);

    // 1a) in-proj x_part half -> fp32 contiguous           (16384 x 2048 x 1024)
    gemm_mma<0><<<dim3(INNER / GBN, M_TOT / GBM), 256, GSMEM>>>(
        x0h, wh, in_b, xp, INNER, HID);
    // 1b) in-proj z half -> fp16 contiguous                (16384 x 2048 x 1024)
    gemm_mma<2><<<dim3(INNER / GBN, M_TOT / GBM), 256, GSMEM>>>(
        x0h, wh + (size_t)INNER * HID, in_b + INNER, zh, INNER, HID);

    // 2) conv + silu -> fp16
    conv_silu_kernel<<<dim3(INNER / 256, LEN / 128, B_SZ), 256>>>(conv_w, conv_b);

    // 3) B/C projections via mma (N = 32)
    bc_mma<<<M_TOT / 128, 256, BCSMEM>>>(xch, wbch, B_b, C_b);

    // 4) dt = softplus(xconv @ dt_w^T + dt_b) -> fp16      (16384 x 2048 x 2048)
    gemm_mma<1><<<dim3(INNER / GBN, M_TOT / GBM), 256, GSMEM>>>(
        xch, dtwh, dt_b, dth, INNER, INNER);

    // 5) chunked selective scan + gating
    scanA_kernel<<<dim3(INNER / 128, NC, B_SZ), 128>>>(A_log);
    scanB_kernel<<<(B_SZ * STATE * INNER) / 256, 256>>>();
    scanC_kernel<<<dim3(INNER / 128, NC, B_SZ), 128>>>(A_log, Dv);

    // 6) out-proj, 1-pass fp16: out = y @ out_w^T + out_b  (16384 x 1024 x 2048)
    gemm_mma<0><<<dim3(HID / GBN, M_TOT / GBM), 256, GSMEM>>>(
        y0h, owh, out_b, out, HID, INNER);
}

// round 10
// speedup vs baseline: 4.7360x; 1.0421x over previous
#include <cuda_runtime.h>
#include <cuda_fp16.h>
#include <math.h>
#include <stdint.h>

#define B_SZ   4
#define LEN    4096
#define HID    1024
#define STATE  16
#define INNER  2048
#define M_TOT  (B_SZ * LEN)
#define NC     16
#define LC     256
#define LOG2E  1.4426950408889634f

// ---------------- scratch ----------------
__device__ __align__(1024) float  g_xp  [(size_t)M_TOT * INNER];   // x_part fp32 (conv input)
__device__ __align__(1024) float  g_Bm  [(size_t)M_TOT * STATE];
__device__ __align__(1024) float  g_Cm  [(size_t)M_TOT * STATE];
__device__ __align__(1024) float  g_P [(size_t)B_SZ * NC * STATE * INNER];
__device__ __align__(1024) float  g_S [(size_t)B_SZ * NC * STATE * INNER];
__device__ __align__(1024) float  g_H0[(size_t)B_SZ * NC * STATE * INNER];
__device__ __align__(1024) __half g_zh  [(size_t)M_TOT * INNER];
__device__ __align__(1024) __half g_dth [(size_t)M_TOT * INNER];
__device__ __align__(1024) __half g_x0h [(size_t)M_TOT * HID];
__device__ __align__(1024) __half g_wh  [(size_t)2 * INNER * HID];
__device__ __align__(1024) __half g_dtwh[(size_t)INNER * INNER];
__device__ __align__(1024) __half g_xch [(size_t)M_TOT * INNER];
__device__ __align__(1024) __half g_y0h [(size_t)M_TOT * INNER];
__device__ __align__(1024) __half g_owh [(size_t)HID * INNER];
__device__ __align__(1024) __half g_wbch[32 * INNER];

// ---------------- PTX helpers ----------------
__device__ __forceinline__ uint32_t smem_u32(const void* p) {
    uint32_t a;
    asm("{ .reg .u64 t; cvta.to.shared.u64 t, %1; cvt.u32.u64 %0, t; }" : "=r"(a) : "l"(p));
    return a;
}
__device__ __forceinline__ void cp_async16(uint32_t dst, const void* src) {
    asm volatile("cp.async.cg.shared.global [%0], [%1], 16;" :: "r"(dst), "l"(src) : "memory");
}
#define CP_COMMIT() asm volatile("cp.async.commit_group;" ::: "memory")
#define CP_WAIT1()  asm volatile("cp.async.wait_group 1;" ::: "memory")

__device__ __forceinline__ void ldm_x4(uint32_t* r, uint32_t addr) {
    asm volatile("ldmatrix.sync.aligned.m8n8.x4.shared.b16 {%0,%1,%2,%3}, [%4];"
        : "=r"(r[0]), "=r"(r[1]), "=r"(r[2]), "=r"(r[3]) : "r"(addr));
}
__device__ __forceinline__ void mma16816h(float* d, const uint32_t* a, const uint32_t* b) {
    asm volatile("mma.sync.aligned.m16n8k16.row.col.f32.f16.f16.f32 "
        "{%0,%1,%2,%3}, {%4,%5,%6,%7}, {%8,%9}, {%0,%1,%2,%3};"
        : "+f"(d[0]), "+f"(d[1]), "+f"(d[2]), "+f"(d[3])
        : "r"(a[0]), "r"(a[1]), "r"(a[2]), "r"(a[3]), "r"(b[0]), "r"(b[1]));
}
__device__ __forceinline__ __half2 hexp2_x2(__half2 x) {
    __half2 r;
    asm("ex2.approx.f16x2 %0, %1;" : "=r"(*(uint32_t*)&r) : "r"(*(uint32_t*)&x));
    return r;
}
__device__ __forceinline__ float softplusf(float v) { return v > 20.f ? v : log1pf(__expf(v)); }
__device__ __forceinline__ float siluf(float v)     { return v / (1.f + __expf(-v)); }

// ---------------- fp16 mma.sync GEMM (unchanged core) ----------------
#define GBM 128
#define GBN 256
#define GAST (GBM * 128)
#define GSTG (GAST + GBN * 128)
#define GSMEM (3 * GSTG)

template <int EPI>   // 0 = fp32 bias, 1 = fp16 softplus, 2 = fp16 bias
__global__ void __launch_bounds__(256, 1) gemm_mma(
    const __half* __restrict__ Ap, const __half* __restrict__ Bp,
    const float* __restrict__ bias, void* __restrict__ Cv, int Cstride, int K)
{
    extern __shared__ char smraw[];
    const uint32_t sbase = smem_u32(smraw);
    const int tid  = threadIdx.x;
    const int wid  = tid >> 5;
    const int lane = tid & 31;
    const int bm0  = blockIdx.y * GBM;
    const int bn0  = blockIdx.x * GBN;

    const int KTT = K >> 6;
    const size_t lda = (size_t)K * 2;

    auto load_stage = [&](int kt, int s) {
        const uint32_t sa = sbase + s * GSTG;
        const uint32_t sb = sa + GAST;
#pragma unroll
        for (int i = 0; i < 4; ++i) {
            int idx = tid + i * 256, r = idx >> 3, c = idx & 7;
            cp_async16(sa + r * 128 + ((c ^ (r & 7)) << 4),
                       (const char*)Ap + (size_t)(bm0 + r) * lda + (size_t)kt * 128 + c * 16);
        }
#pragma unroll
        for (int i = 0; i < 8; ++i) {
            int idx = tid + i * 256, r = idx >> 3, c = idx & 7;
            cp_async16(sb + r * 128 + ((c ^ (r & 7)) << 4),
                       (const char*)Bp + (size_t)(bn0 + r) * lda + (size_t)kt * 128 + c * 16);
        }
    };

    float acc[4][8][4];
#pragma unroll
    for (int mt = 0; mt < 4; ++mt)
#pragma unroll
        for (int nt = 0; nt < 8; ++nt)
#pragma unroll
            for (int q = 0; q < 4; ++q) acc[mt][nt][q] = 0.f;

    load_stage(0, 0); CP_COMMIT();
    load_stage(1, 1); CP_COMMIT();

    const int wm0 = (wid >> 2) * 64;
    const int wn0 = (wid & 3) * 64;
    const int aRow = wm0 + ((lane >> 3) & 1) * 8 + (lane & 7);
    const int bRow = wn0 + ((lane >> 4) & 1) * 8 + (lane & 7);
    const int swzX = (lane & 7) << 4;
    const int aKs  = (lane >> 4) << 4;
    const int bKs  = ((lane >> 3) & 1) << 4;

    for (int kt = 0; kt < KTT; ++kt) {
        const int s = kt % 3;
        CP_WAIT1();
        __syncthreads();
        if (kt + 2 < KTT) { load_stage(kt + 2, (kt + 2) % 3); CP_COMMIT(); }

        const uint32_t Ab = sbase + s * GSTG;
        const uint32_t Bb = Ab + GAST;
#pragma unroll
        for (int ks = 0; ks < 4; ++ks) {
            const int swA = (ks * 32 + aKs) ^ swzX;
            const int swB = (ks * 32 + bKs) ^ swzX;
            uint32_t a[4][4], b[4][4];
#pragma unroll
            for (int mt = 0; mt < 4; ++mt) ldm_x4(a[mt], Ab + (aRow + mt * 16) * 128 + swA);
#pragma unroll
            for (int np = 0; np < 4; ++np) ldm_x4(b[np], Bb + (bRow + np * 16) * 128 + swB);
#pragma unroll
            for (int mt = 0; mt < 4; ++mt)
#pragma unroll
                for (int nt = 0; nt < 8; ++nt)
                    mma16816h(acc[mt][nt], a[mt], &b[nt >> 1][(nt & 1) * 2]);
        }
    }

#pragma unroll
    for (int nt = 0; nt < 8; ++nt) {
        const int col = bn0 + wn0 + nt * 8 + (lane & 3) * 2;
        const float b0v = bias[col], b1v = bias[col + 1];
#pragma unroll
        for (int mt = 0; mt < 4; ++mt) {
            const int row = bm0 + wm0 + mt * 16 + (lane >> 2);
            float v0 = acc[mt][nt][0] + b0v, v1 = acc[mt][nt][1] + b1v;
            float v2 = acc[mt][nt][2] + b0v, v3 = acc[mt][nt][3] + b1v;
            if (EPI == 1) {
                v0 = softplusf(v0); v1 = softplusf(v1);
                v2 = softplusf(v2); v3 = softplusf(v3);
            }
            if (EPI == 0) {
                float* C = (float*)Cv;
                *reinterpret_cast<float2*>(&C[(size_t)row * Cstride + col])       = make_float2(v0, v1);
                *reinterpret_cast<float2*>(&C[(size_t)(row + 8) * Cstride + col]) = make_float2(v2, v3);
            } else {
                __half* C = (__half*)Cv;
                *reinterpret_cast<__half2*>(&C[(size_t)row * Cstride + col])       = __floats2half2_rn(v0, v1);
                *reinterpret_cast<__half2*>(&C[(size_t)(row + 8) * Cstride + col]) = __floats2half2_rn(v2, v3);
            }
        }
    }
}

// ---------------- B/C projection via mma ----------------
#define BCAST (128 * 128)
#define BCSTG (BCAST + 32 * 128)
#define BCSMEM (3 * BCSTG)
__global__ void __launch_bounds__(256, 1) bc_mma(
    const __half* __restrict__ A, const __half* __restrict__ W,
    const float* __restrict__ Bb, const float* __restrict__ Cb)
{
    extern __shared__ char smraw[];
    const uint32_t sbase = smem_u32(smraw);
    const int tid  = threadIdx.x;
    const int wid  = tid >> 5;
    const int lane = tid & 31;
    const int bm0  = blockIdx.x * 128;
    const size_t lda = (size_t)INNER * 2;

    auto load_stage = [&](int kt, int s) {
        const uint32_t sa = sbase + s * BCSTG;
        const uint32_t sb = sa + BCAST;
#pragma unroll
        for (int i = 0; i < 4; ++i) {
            int idx = tid + i * 256, r = idx >> 3, c = idx & 7;
            cp_async16(sa + r * 128 + ((c ^ (r & 7)) << 4),
                       (const char*)A + (size_t)(bm0 + r) * lda + (size_t)kt * 128 + c * 16);
        }
        {
            int r = tid >> 3, c = tid & 7;
            cp_async16(sb + r * 128 + ((c ^ (r & 7)) << 4),
                       (const char*)W + (size_t)r * lda + (size_t)kt * 128 + c * 16);
        }
    };

    float acc[4][4];
#pragma unroll
    for (int nt = 0; nt < 4; ++nt)
#pragma unroll
        for (int q = 0; q < 4; ++q) acc[nt][q] = 0.f;

    load_stage(0, 0); CP_COMMIT();
    load_stage(1, 1); CP_COMMIT();

    const int aRow = wid * 16 + ((lane >> 3) & 1) * 8 + (lane & 7);
    const int bRow = ((lane >> 4) & 1) * 8 + (lane & 7);
    const int swzX = (lane & 7) << 4;
    const int aKs  = (lane >> 4) << 4;
    const int bKs  = ((lane >> 3) & 1) << 4;

    const int KT = INNER / 64;
    for (int kt = 0; kt < KT; ++kt) {
        const int s = kt % 3;
        CP_WAIT1();
        __syncthreads();
        if (kt + 2 < KT) { load_stage(kt + 2, (kt + 2) % 3); CP_COMMIT(); }

        const uint32_t Ab = sbase + s * BCSTG;
        const uint32_t Bb_ = Ab + BCAST;
#pragma unroll
        for (int ks = 0; ks < 4; ++ks) {
            const int swA = (ks * 32 + aKs) ^ swzX;
            const int swB = (ks * 32 + bKs) ^ swzX;
            uint32_t a[4], b[2][4];
            ldm_x4(a, Ab + aRow * 128 + swA);
#pragma unroll
            for (int np = 0; np < 2; ++np) ldm_x4(b[np], Bb_ + (bRow + np * 16) * 128 + swB);
#pragma unroll
            for (int nt = 0; nt < 4; ++nt)
                mma16816h(acc[nt], a, &b[nt >> 1][(nt & 1) * 2]);
        }
    }

#pragma unroll
    for (int nt = 0; nt < 4; ++nt) {
        const int col = nt * 8 + (lane & 3) * 2;
        const int row = bm0 + wid * 16 + (lane >> 2);
        if (col < 16) {
            const float c0 = Bb[col], c1 = Bb[col + 1];
            *reinterpret_cast<float2*>(&g_Bm[(size_t)row * 16 + col]) =
                make_float2(acc[nt][0] + c0, acc[nt][1] + c1);
            *reinterpret_cast<float2*>(&g_Bm[(size_t)(row + 8) * 16 + col]) =
                make_float2(acc[nt][2] + c0, acc[nt][3] + c1);
        } else {
            const int cc = col - 16;
            const float c0 = Cb[cc], c1 = Cb[cc + 1];
            *reinterpret_cast<float2*>(&g_Cm[(size_t)row * 16 + cc]) =
                make_float2(acc[nt][0] + c0, acc[nt][1] + c1);
            *reinterpret_cast<float2*>(&g_Cm[(size_t)(row + 8) * 16 + cc]) =
                make_float2(acc[nt][2] + c0, acc[nt][3] + c1);
        }
    }
}

// ---------------- conversion kernels ----------------
__global__ void __launch_bounds__(256) cvt1h_kernel(
    const float* __restrict__ in, __half* __restrict__ o0, size_t n4)
{
    for (size_t i = (size_t)blockIdx.x * 256 + threadIdx.x; i < n4; i += (size_t)gridDim.x * 256) {
        float4 v = reinterpret_cast<const float4*>(in)[i];
        ((ushort4*)o0)[i] = make_ushort4(
            __half_as_ushort(__float2half_rn(v.x)), __half_as_ushort(__float2half_rn(v.y)),
            __half_as_ushort(__float2half_rn(v.z)), __half_as_ushort(__float2half_rn(v.w)));
    }
}
__global__ void __launch_bounds__(256) cvtbc_kernel(
    const float* __restrict__ Bw, const float* __restrict__ Cw, __half* __restrict__ o)
{
    int i = blockIdx.x * 256 + threadIdx.x;
    int r = i / INNER, k = i - r * INNER;
    float v = (r < 16) ? Bw[(size_t)r * INNER + k] : Cw[(size_t)(r - 16) * INNER + k];
    o[i] = __float2half_rn(v);
}

// ---------------- causal depthwise conv (K=4) + SiLU -> fp16 ----------------
__global__ void __launch_bounds__(256) conv_silu_kernel(
    const float* __restrict__ conv_w, const float* __restrict__ conv_b)
{
    const int d  = blockIdx.x * 256 + threadIdx.x;
    const int l0 = blockIdx.y * 128;
    const int b  = blockIdx.z;
    const float w0 = conv_w[d * 4 + 0], w1 = conv_w[d * 4 + 1];
    const float w2 = conv_w[d * 4 + 2], w3 = conv_w[d * 4 + 3];
    const float cb = conv_b[d];
    const float* xp = g_xp + (size_t)(b * LEN) * INNER + d;
    float m3, m2, m1;
    if (l0 == 0) { m3 = m2 = m1 = 0.f; }
    else {
        m3 = xp[(size_t)(l0 - 3) * INNER];
        m2 = xp[(size_t)(l0 - 2) * INNER];
        m1 = xp[(size_t)(l0 - 1) * INNER];
    }
    __half* xh = g_xch + (size_t)(b * LEN + l0) * INNER + d;
#pragma unroll 4
    for (int i = 0; i < 128; ++i) {
        float cur = xp[(size_t)(l0 + i) * INNER];
        float v = siluf(w0 * m3 + w1 * m2 + w2 * m1 + w3 * cur + cb);
        xh[(size_t)i * INNER] = __float2half_rn(v);
        m3 = m2; m2 = m1; m1 = cur;
    }
}

// ---------------- chunked selective scan (f16x2 ex2 for dA) ----------------
__global__ void __launch_bounds__(128) scanA_kernel(const float* __restrict__ A_log)
{
    __shared__ float sB[LC * STATE];
    const int d = blockIdx.x * 128 + threadIdx.x;
    const int c = blockIdx.y;
    const int b = blockIdx.z;
    const int base_l = c * LC;
    for (int i = threadIdx.x; i < LC * STATE; i += 128)
        sB[i] = g_Bm[(size_t)(b * LEN + base_l) * STATE + i];
    __syncthreads();
    __half2 Ar2[STATE / 2];
#pragma unroll
    for (int i = 0; i < STATE / 2; i++)
        Ar2[i] = __floats2half2_rn(-expf(A_log[d * STATE + 2 * i]) * LOG2E,
                                   -expf(A_log[d * STATE + 2 * i + 1]) * LOG2E);
    float h[STATE], Pr[STATE];
#pragma unroll
    for (int s = 0; s < STATE; s++) { h[s] = 0.f; Pr[s] = 1.f; }
    const __half* dtp = g_dth + (size_t)(b * LEN + base_l) * INNER + d;
    const __half* xcp = g_xch + (size_t)(b * LEN + base_l) * INNER + d;
    for (int l = 0; l < LC; ++l) {
        __half dthv = dtp[(size_t)l * INNER];
        float dtv = __half2float(dthv);
        float dtx = dtv * __half2float(xcp[(size_t)l * INNER]);
        __half2 dt2 = __half2half2(dthv);
#pragma unroll
        for (int i = 0; i < STATE / 2; i++) {
            float2 dA = __half22float2(hexp2_x2(__hmul2(dt2, Ar2[i])));
            int s0 = 2 * i;
            Pr[s0] *= dA.x;
            h[s0] = fmaf(dA.x, h[s0], sB[l * STATE + s0] * dtx);
            Pr[s0 + 1] *= dA.y;
            h[s0 + 1] = fmaf(dA.y, h[s0 + 1], sB[l * STATE + s0 + 1] * dtx);
        }
    }
    size_t ob = (size_t)(b * NC + c) * STATE * INNER + d;
#pragma unroll
    for (int s = 0; s < STATE; s++) {
        g_P[ob + (size_t)s * INNER] = Pr[s];
        g_S[ob + (size_t)s * INNER] = h[s];
    }
}

__global__ void __launch_bounds__(256) scanB_kernel()
{
    int g = blockIdx.x * 256 + threadIdx.x;
    int b = g / (STATE * INNER);
    int r = g - b * (STATE * INNER);
    float h = 0.f;
    for (int c = 0; c < NC; ++c) {
        size_t idx = (size_t)(b * NC + c) * STATE * INNER + r;
        g_H0[idx] = h;
        h = g_P[idx] * h + g_S[idx];
    }
}

__global__ void __launch_bounds__(128) scanC_kernel(
    const float* __restrict__ A_log, const float* __restrict__ Dv)
{
    __shared__ float sB[LC * STATE];
    __shared__ float sC[LC * STATE];
    const int d = blockIdx.x * 128 + threadIdx.x;
    const int c = blockIdx.y;
    const int b = blockIdx.z;
    const int base_l = c * LC;
    for (int i = threadIdx.x; i < LC * STATE; i += 128) {
        sB[i] = g_Bm[(size_t)(b * LEN + base_l) * STATE + i];
        sC[i] = g_Cm[(size_t)(b * LEN + base_l) * STATE + i];
    }
    __syncthreads();
    __half2 Ar2[STATE / 2];
#pragma unroll
    for (int i = 0; i < STATE / 2; i++)
        Ar2[i] = __floats2half2_rn(-expf(A_log[d * STATE + 2 * i]) * LOG2E,
                                   -expf(A_log[d * STATE + 2 * i + 1]) * LOG2E);
    const float Dd = Dv[d];
    float h[STATE];
    size_t ob = (size_t)(b * NC + c) * STATE * INNER + d;
#pragma unroll
    for (int s = 0; s < STATE; s++) h[s] = g_H0[ob + (size_t)s * INNER];
    const __half* dtp = g_dth + (size_t)(b * LEN + base_l) * INNER + d;
    const __half* xcp = g_xch + (size_t)(b * LEN + base_l) * INNER + d;
    const __half* zp  = g_zh  + (size_t)(b * LEN + base_l) * INNER + d;
    __half* y0p = g_y0h + (size_t)(b * LEN + base_l) * INNER + d;
    for (int l = 0; l < LC; ++l) {
        __half dthv = dtp[(size_t)l * INNER];
        float dtv = __half2float(dthv);
        float xv  = __half2float(xcp[(size_t)l * INNER]);
        float zv  = __half2float(zp[(size_t)l * INNER]);
        float dtx = dtv * xv;
        float acc = Dd * xv;
        __half2 dt2 = __half2half2(dthv);
#pragma unroll
        for (int i = 0; i < STATE / 2; i++) {
            float2 dA = __half22float2(hexp2_x2(__hmul2(dt2, Ar2[i])));
            int s0 = 2 * i;
            h[s0] = fmaf(dA.x, h[s0], sB[l * STATE + s0] * dtx);
            acc   = fmaf(sC[l * STATE + s0], h[s0], acc);
            h[s0 + 1] = fmaf(dA.y, h[s0 + 1], sB[l * STATE + s0 + 1] * dtx);
            acc   = fmaf(sC[l * STATE + s0 + 1], h[s0 + 1], acc);
        }
        y0p[(size_t)l * INNER] = __float2half_rn(acc * siluf(zv));
    }
}

// ---------------- launch ----------------
extern "C" void kernel_launch(void* const* d_in, const int* in_sizes, int n_in,
                              void* d_out, int out_size)
{
    const float* x      = (const float*)d_in[0];
    const float* in_w   = (const float*)d_in[1];
    const float* in_b   = (const float*)d_in[2];
    const float* conv_w = (const float*)d_in[3];
    const float* conv_b = (const float*)d_in[4];
    const float* dt_w   = (const float*)d_in[5];
    const float* dt_b   = (const float*)d_in[6];
    const float* A_log  = (const float*)d_in[7];
    const float* B_w    = (const float*)d_in[8];
    const float* B_b    = (const float*)d_in[9];
    const float* C_w    = (const float*)d_in[10];
    const float* C_b    = (const float*)d_in[11];
    const float* Dv     = (const float*)d_in[12];
    const float* out_w  = (const float*)d_in[13];
    const float* out_b  = (const float*)d_in[14];
    float* out = (float*)d_out;

    float *xp;
    __half *x0h, *wh, *dtwh, *xch, *y0h, *owh, *wbch, *zh, *dth;
    cudaGetSymbolAddress((void**)&xp, g_xp);
    cudaGetSymbolAddress((void**)&x0h, g_x0h);
    cudaGetSymbolAddress((void**)&wh, g_wh);
    cudaGetSymbolAddress((void**)&dtwh, g_dtwh);
    cudaGetSymbolAddress((void**)&xch, g_xch);
    cudaGetSymbolAddress((void**)&y0h, g_y0h);
    cudaGetSymbolAddress((void**)&owh, g_owh);
    cudaGetSymbolAddress((void**)&wbch, g_wbch);
    cudaGetSymbolAddress((void**)&zh, g_zh);
    cudaGetSymbolAddress((void**)&dth, g_dth);

    cudaFuncSetAttribute(gemm_mma<0>, cudaFuncAttributeMaxDynamicSharedMemorySize, GSMEM);
    cudaFuncSetAttribute(gemm_mma<1>, cudaFuncAttributeMaxDynamicSharedMemorySize, GSMEM);
    cudaFuncSetAttribute(gemm_mma<2>, cudaFuncAttributeMaxDynamicSharedMemorySize, GSMEM);
    cudaFuncSetAttribute(bc_mma, cudaFuncAttributeMaxDynamicSharedMemorySize, BCSMEM);

    // one-time stream/event setup (host resources; created on the first,
    // non-captured correctness call — identical captured work on every call)
    static cudaStream_t s1 = nullptr;
    static cudaEvent_t evA = nullptr, evZ = nullptr;
    if (s1 == nullptr) {
        cudaStreamCreateWithFlags(&s1, cudaStreamNonBlocking);
        cudaEventCreateWithFlags(&evA, cudaEventDisableTiming);
        cudaEventCreateWithFlags(&evZ, cudaEventDisableTiming);
    }

    // 0) fp16 conversions (x and in_w first so the z-GEMM can fork early)
    cvt1h_kernel<<<2048, 256>>>(x, x0h, (size_t)M_TOT * HID / 4);
    cvt1h_kernel<<<1024, 256>>>(in_w, wh, (size_t)2 * INNER * HID / 4);
    cudaEventRecord(evA, 0);

    // fork: z half of in-proj on s1, overlapping conv/bc/dt/scanA on stream 0
    cudaStreamWaitEvent(s1, evA, 0);
    gemm_mma<2><<<dim3(INNER / GBN, M_TOT / GBM), 256, GSMEM, s1>>>(
        x0h, wh + (size_t)INNER * HID, in_b + INNER, zh, INNER, HID);
    cudaEventRecord(evZ, s1);

    cvt1h_kernel<<<1024, 256>>>(dt_w, dtwh, (size_t)INNER * INNER / 4);
    cvt1h_kernel<<<512, 256>>>(out_w, owh, (size_t)HID * INNER / 4);
    cvtbc_kernel<<<(32 * INNER) / 256, 256>>>(B_w, C_w, wbch);

    // 1) in-proj x_part half -> fp32                       (16384 x 2048 x 1024)
    gemm_mma<0><<<dim3(INNER / GBN, M_TOT / GBM), 256, GSMEM>>>(
        x0h, wh, in_b, xp, INNER, HID);

    // 2) conv + silu -> fp16
    conv_silu_kernel<<<dim3(INNER / 256, LEN / 128, B_SZ), 256>>>(conv_w, conv_b);

    // 3) B/C projections via mma (N = 32)
    bc_mma<<<M_TOT / 128, 256, BCSMEM>>>(xch, wbch, B_b, C_b);

    // 4) dt = softplus(xconv @ dt_w^T + dt_b) -> fp16      (16384 x 2048 x 2048)
    gemm_mma<1><<<dim3(INNER / GBN, M_TOT / GBM), 256, GSMEM>>>(
        xch, dtwh, dt_b, dth, INNER, INNER);

    // 5) chunked selective scan + gating
    scanA_kernel<<<dim3(INNER / 128, NC, B_SZ), 128>>>(A_log);
    scanB_kernel<<<(B_SZ * STATE * INNER) / 256, 256>>>();
    cudaStreamWaitEvent(0, evZ, 0);   // join: z must be ready for scanC
    scanC_kernel<<<dim3(INNER / 128, NC, B_SZ), 128>>>(A_log, Dv);

    // 6) out-proj: out = y @ out_w^T + out_b               (16384 x 1024 x 2048)
    gemm_mma<0><<<dim3(HID / GBN, M_TOT / GBM), 256, GSMEM>>>(
        y0h, owh, out_b, out, HID, INNER);
}

// round 11
// speedup vs baseline: 5.0041x; 1.0566x over previous
#include <cuda_runtime.h>
#include <cuda_fp16.h>
#include <math.h>
#include <stdint.h>

#define B_SZ   4
#define LEN    4096
#define HID    1024
#define STATE  16
#define INNER  2048
#define M_TOT  (B_SZ * LEN)
#define NC     16
#define LC     256
#define LOG2E  1.4426950408889634f

// ---------------- scratch ----------------
__device__ __align__(1024) float    g_Bm  [(size_t)M_TOT * STATE];
__device__ __align__(1024) float    g_Cm  [(size_t)M_TOT * STATE];
__device__ __align__(1024) uint32_t g_S2  [(size_t)B_SZ * NC * 8 * INNER];   // chunk-end h, half2 pairs
__device__ __align__(1024) float    g_dts [(size_t)B_SZ * NC * INNER];       // per-chunk sum(dt)
__device__ __align__(1024) float    g_H0  [(size_t)B_SZ * NC * STATE * INNER];
__device__ __align__(1024) __half   g_xph [(size_t)M_TOT * INNER];  // x_part fp16 (conv input)
__device__ __align__(1024) __half   g_zh  [(size_t)M_TOT * INNER];
__device__ __align__(1024) __half   g_dth [(size_t)M_TOT * INNER];
__device__ __align__(1024) __half   g_x0h [(size_t)M_TOT * HID];
__device__ __align__(1024) __half   g_wh  [(size_t)2 * INNER * HID];
__device__ __align__(1024) __half   g_dtwh[(size_t)INNER * INNER];
__device__ __align__(1024) __half   g_xch [(size_t)M_TOT * INNER];
__device__ __align__(1024) __half   g_y0h [(size_t)M_TOT * INNER];
__device__ __align__(1024) __half   g_owh [(size_t)HID * INNER];
__device__ __align__(1024) __half   g_wbch[32 * INNER];

// ---------------- PTX helpers ----------------
__device__ __forceinline__ uint32_t smem_u32(const void* p) {
    uint32_t a;
    asm("{ .reg .u64 t; cvta.to.shared.u64 t, %1; cvt.u32.u64 %0, t; }" : "=r"(a) : "l"(p));
    return a;
}
__device__ __forceinline__ void cp_async16(uint32_t dst, const void* src) {
    asm volatile("cp.async.cg.shared.global [%0], [%1], 16;" :: "r"(dst), "l"(src) : "memory");
}
#define CP_COMMIT() asm volatile("cp.async.commit_group;" ::: "memory")
#define CP_WAIT1()  asm volatile("cp.async.wait_group 1;" ::: "memory")

__device__ __forceinline__ void ldm_x4(uint32_t* r, uint32_t addr) {
    asm volatile("ldmatrix.sync.aligned.m8n8.x4.shared.b16 {%0,%1,%2,%3}, [%4];"
        : "=r"(r[0]), "=r"(r[1]), "=r"(r[2]), "=r"(r[3]) : "r"(addr));
}
__device__ __forceinline__ void mma16816h(float* d, const uint32_t* a, const uint32_t* b) {
    asm volatile("mma.sync.aligned.m16n8k16.row.col.f32.f16.f16.f32 "
        "{%0,%1,%2,%3}, {%4,%5,%6,%7}, {%8,%9}, {%0,%1,%2,%3};"
        : "+f"(d[0]), "+f"(d[1]), "+f"(d[2]), "+f"(d[3])
        : "r"(a[0]), "r"(a[1]), "r"(a[2]), "r"(a[3]), "r"(b[0]), "r"(b[1]));
}
__device__ __forceinline__ __half2 hexp2_x2(__half2 x) {
    __half2 r;
    asm("ex2.approx.f16x2 %0, %1;" : "=r"(*(uint32_t*)&r) : "r"(*(uint32_t*)&x));
    return r;
}
__device__ __forceinline__ float softplusf(float v) { return v > 20.f ? v : log1pf(__expf(v)); }
__device__ __forceinline__ float siluf(float v)     { return v / (1.f + __expf(-v)); }

// ---------------- fp16 mma.sync GEMM (unchanged core) ----------------
#define GBM 128
#define GBN 256
#define GAST (GBM * 128)
#define GSTG (GAST + GBN * 128)
#define GSMEM (3 * GSTG)

template <int EPI>   // 0 = fp32 bias, 1 = fp16 softplus, 2 = fp16 bias
__global__ void __launch_bounds__(256, 1) gemm_mma(
    const __half* __restrict__ Ap, const __half* __restrict__ Bp,
    const float* __restrict__ bias, void* __restrict__ Cv, int Cstride, int K)
{
    extern __shared__ char smraw[];
    const uint32_t sbase = smem_u32(smraw);
    const int tid  = threadIdx.x;
    const int wid  = tid >> 5;
    const int lane = tid & 31;
    const int bm0  = blockIdx.y * GBM;
    const int bn0  = blockIdx.x * GBN;

    const int KTT = K >> 6;
    const size_t lda = (size_t)K * 2;

    auto load_stage = [&](int kt, int s) {
        const uint32_t sa = sbase + s * GSTG;
        const uint32_t sb = sa + GAST;
#pragma unroll
        for (int i = 0; i < 4; ++i) {
            int idx = tid + i * 256, r = idx >> 3, c = idx & 7;
            cp_async16(sa + r * 128 + ((c ^ (r & 7)) << 4),
                       (const char*)Ap + (size_t)(bm0 + r) * lda + (size_t)kt * 128 + c * 16);
        }
#pragma unroll
        for (int i = 0; i < 8; ++i) {
            int idx = tid + i * 256, r = idx >> 3, c = idx & 7;
            cp_async16(sb + r * 128 + ((c ^ (r & 7)) << 4),
                       (const char*)Bp + (size_t)(bn0 + r) * lda + (size_t)kt * 128 + c * 16);
        }
    };

    float acc[4][8][4];
#pragma unroll
    for (int mt = 0; mt < 4; ++mt)
#pragma unroll
        for (int nt = 0; nt < 8; ++nt)
#pragma unroll
            for (int q = 0; q < 4; ++q) acc[mt][nt][q] = 0.f;

    load_stage(0, 0); CP_COMMIT();
    load_stage(1, 1); CP_COMMIT();

    const int wm0 = (wid >> 2) * 64;
    const int wn0 = (wid & 3) * 64;
    const int aRow = wm0 + ((lane >> 3) & 1) * 8 + (lane & 7);
    const int bRow = wn0 + ((lane >> 4) & 1) * 8 + (lane & 7);
    const int swzX = (lane & 7) << 4;
    const int aKs  = (lane >> 4) << 4;
    const int bKs  = ((lane >> 3) & 1) << 4;

    for (int kt = 0; kt < KTT; ++kt) {
        const int s = kt % 3;
        CP_WAIT1();
        __syncthreads();
        if (kt + 2 < KTT) { load_stage(kt + 2, (kt + 2) % 3); CP_COMMIT(); }

        const uint32_t Ab = sbase + s * GSTG;
        const uint32_t Bb = Ab + GAST;
#pragma unroll
        for (int ks = 0; ks < 4; ++ks) {
            const int swA = (ks * 32 + aKs) ^ swzX;
            const int swB = (ks * 32 + bKs) ^ swzX;
            uint32_t a[4][4], b[4][4];
#pragma unroll
            for (int mt = 0; mt < 4; ++mt) ldm_x4(a[mt], Ab + (aRow + mt * 16) * 128 + swA);
#pragma unroll
            for (int np = 0; np < 4; ++np) ldm_x4(b[np], Bb + (bRow + np * 16) * 128 + swB);
#pragma unroll
            for (int mt = 0; mt < 4; ++mt)
#pragma unroll
                for (int nt = 0; nt < 8; ++nt)
                    mma16816h(acc[mt][nt], a[mt], &b[nt >> 1][(nt & 1) * 2]);
        }
    }

#pragma unroll
    for (int nt = 0; nt < 8; ++nt) {
        const int col = bn0 + wn0 + nt * 8 + (lane & 3) * 2;
        const float b0v = bias[col], b1v = bias[col + 1];
#pragma unroll
        for (int mt = 0; mt < 4; ++mt) {
            const int row = bm0 + wm0 + mt * 16 + (lane >> 2);
            float v0 = acc[mt][nt][0] + b0v, v1 = acc[mt][nt][1] + b1v;
            float v2 = acc[mt][nt][2] + b0v, v3 = acc[mt][nt][3] + b1v;
            if (EPI == 1) {
                v0 = softplusf(v0); v1 = softplusf(v1);
                v2 = softplusf(v2); v3 = softplusf(v3);
            }
            if (EPI == 0) {
                float* C = (float*)Cv;
                *reinterpret_cast<float2*>(&C[(size_t)row * Cstride + col])       = make_float2(v0, v1);
                *reinterpret_cast<float2*>(&C[(size_t)(row + 8) * Cstride + col]) = make_float2(v2, v3);
            } else {
                __half* C = (__half*)Cv;
                *reinterpret_cast<__half2*>(&C[(size_t)row * Cstride + col])       = __floats2half2_rn(v0, v1);
                *reinterpret_cast<__half2*>(&C[(size_t)(row + 8) * Cstride + col]) = __floats2half2_rn(v2, v3);
            }
        }
    }
}

// ---------------- B/C projection via mma ----------------
#define BCAST (128 * 128)
#define BCSTG (BCAST + 32 * 128)
#define BCSMEM (3 * BCSTG)
__global__ void __launch_bounds__(256, 1) bc_mma(
    const __half* __restrict__ A, const __half* __restrict__ W,
    const float* __restrict__ Bb, const float* __restrict__ Cb)
{
    extern __shared__ char smraw[];
    const uint32_t sbase = smem_u32(smraw);
    const int tid  = threadIdx.x;
    const int wid  = tid >> 5;
    const int lane = tid & 31;
    const int bm0  = blockIdx.x * 128;
    const size_t lda = (size_t)INNER * 2;

    auto load_stage = [&](int kt, int s) {
        const uint32_t sa = sbase + s * BCSTG;
        const uint32_t sb = sa + BCAST;
#pragma unroll
        for (int i = 0; i < 4; ++i) {
            int idx = tid + i * 256, r = idx >> 3, c = idx & 7;
            cp_async16(sa + r * 128 + ((c ^ (r & 7)) << 4),
                       (const char*)A + (size_t)(bm0 + r) * lda + (size_t)kt * 128 + c * 16);
        }
        {
            int r = tid >> 3, c = tid & 7;
            cp_async16(sb + r * 128 + ((c ^ (r & 7)) << 4),
                       (const char*)W + (size_t)r * lda + (size_t)kt * 128 + c * 16);
        }
    };

    float acc[4][4];
#pragma unroll
    for (int nt = 0; nt < 4; ++nt)
#pragma unroll
        for (int q = 0; q < 4; ++q) acc[nt][q] = 0.f;

    load_stage(0, 0); CP_COMMIT();
    load_stage(1, 1); CP_COMMIT();

    const int aRow = wid * 16 + ((lane >> 3) & 1) * 8 + (lane & 7);
    const int bRow = ((lane >> 4) & 1) * 8 + (lane & 7);
    const int swzX = (lane & 7) << 4;
    const int aKs  = (lane >> 4) << 4;
    const int bKs  = ((lane >> 3) & 1) << 4;

    const int KT = INNER / 64;
    for (int kt = 0; kt < KT; ++kt) {
        const int s = kt % 3;
        CP_WAIT1();
        __syncthreads();
        if (kt + 2 < KT) { load_stage(kt + 2, (kt + 2) % 3); CP_COMMIT(); }

        const uint32_t Ab = sbase + s * BCSTG;
        const uint32_t Bb_ = Ab + BCAST;
#pragma unroll
        for (int ks = 0; ks < 4; ++ks) {
            const int swA = (ks * 32 + aKs) ^ swzX;
            const int swB = (ks * 32 + bKs) ^ swzX;
            uint32_t a[4], b[2][4];
            ldm_x4(a, Ab + aRow * 128 + swA);
#pragma unroll
            for (int np = 0; np < 2; ++np) ldm_x4(b[np], Bb_ + (bRow + np * 16) * 128 + swB);
#pragma unroll
            for (int nt = 0; nt < 4; ++nt)
                mma16816h(acc[nt], a, &b[nt >> 1][(nt & 1) * 2]);
        }
    }

#pragma unroll
    for (int nt = 0; nt < 4; ++nt) {
        const int col = nt * 8 + (lane & 3) * 2;
        const int row = bm0 + wid * 16 + (lane >> 2);
        if (col < 16) {
            const float c0 = Bb[col], c1 = Bb[col + 1];
            *reinterpret_cast<float2*>(&g_Bm[(size_t)row * 16 + col]) =
                make_float2(acc[nt][0] + c0, acc[nt][1] + c1);
            *reinterpret_cast<float2*>(&g_Bm[(size_t)(row + 8) * 16 + col]) =
                make_float2(acc[nt][2] + c0, acc[nt][3] + c1);
        } else {
            const int cc = col - 16;
            const float c0 = Cb[cc], c1 = Cb[cc + 1];
            *reinterpret_cast<float2*>(&g_Cm[(size_t)row * 16 + cc]) =
                make_float2(acc[nt][0] + c0, acc[nt][1] + c1);
            *reinterpret_cast<float2*>(&g_Cm[(size_t)(row + 8) * 16 + cc]) =
                make_float2(acc[nt][2] + c0, acc[nt][3] + c1);
        }
    }
}

// ---------------- conversion kernels ----------------
__global__ void __launch_bounds__(256) cvt1h_kernel(
    const float* __restrict__ in, __half* __restrict__ o0, size_t n4)
{
    for (size_t i = (size_t)blockIdx.x * 256 + threadIdx.x; i < n4; i += (size_t)gridDim.x * 256) {
        float4 v = reinterpret_cast<const float4*>(in)[i];
        ((ushort4*)o0)[i] = make_ushort4(
            __half_as_ushort(__float2half_rn(v.x)), __half_as_ushort(__float2half_rn(v.y)),
            __half_as_ushort(__float2half_rn(v.z)), __half_as_ushort(__float2half_rn(v.w)));
    }
}
// all three big weights in one launch
__global__ void __launch_bounds__(256) cvtw_kernel(
    const float* __restrict__ w1, const float* __restrict__ w2, const float* __restrict__ w3,
    __half* __restrict__ o1, __half* __restrict__ o2, __half* __restrict__ o3)
{
    const size_t n1 = (size_t)2 * INNER * HID / 4;
    const size_t n2 = (size_t)INNER * INNER / 4;
    const size_t n3 = (size_t)HID * INNER / 4;
    for (size_t i = (size_t)blockIdx.x * 256 + threadIdx.x; i < n1 + n2 + n3;
         i += (size_t)gridDim.x * 256) {
        const float* src; __half* dst; size_t j;
        if (i < n1)            { src = w1; dst = o1; j = i; }
        else if (i < n1 + n2)  { src = w2; dst = o2; j = i - n1; }
        else                   { src = w3; dst = o3; j = i - n1 - n2; }
        float4 v = reinterpret_cast<const float4*>(src)[j];
        ((ushort4*)dst)[j] = make_ushort4(
            __half_as_ushort(__float2half_rn(v.x)), __half_as_ushort(__float2half_rn(v.y)),
            __half_as_ushort(__float2half_rn(v.z)), __half_as_ushort(__float2half_rn(v.w)));
    }
}
__global__ void __launch_bounds__(256) cvtbc_kernel(
    const float* __restrict__ Bw, const float* __restrict__ Cw, __half* __restrict__ o)
{
    int i = blockIdx.x * 256 + threadIdx.x;
    int r = i / INNER, k = i - r * INNER;
    float v = (r < 16) ? Bw[(size_t)r * INNER + k] : Cw[(size_t)(r - 16) * INNER + k];
    o[i] = __float2half_rn(v);
}

// ---------------- causal depthwise conv (K=4) + SiLU, fp16 in/out ----------------
__global__ void __launch_bounds__(256) conv_silu_kernel(
    const float* __restrict__ conv_w, const float* __restrict__ conv_b)
{
    const int d  = blockIdx.x * 256 + threadIdx.x;
    const int l0 = blockIdx.y * 128;
    const int b  = blockIdx.z;
    const float w0 = conv_w[d * 4 + 0], w1 = conv_w[d * 4 + 1];
    const float w2 = conv_w[d * 4 + 2], w3 = conv_w[d * 4 + 3];
    const float cb = conv_b[d];
    const __half* xp = g_xph + (size_t)(b * LEN) * INNER + d;
    float m3, m2, m1;
    if (l0 == 0) { m3 = m2 = m1 = 0.f; }
    else {
        m3 = __half2float(xp[(size_t)(l0 - 3) * INNER]);
        m2 = __half2float(xp[(size_t)(l0 - 2) * INNER]);
        m1 = __half2float(xp[(size_t)(l0 - 1) * INNER]);
    }
    __half* xh = g_xch + (size_t)(b * LEN + l0) * INNER + d;
#pragma unroll 4
    for (int i = 0; i < 128; ++i) {
        float cur = __half2float(xp[(size_t)(l0 + i) * INNER]);
        float v = siluf(w0 * m3 + w1 * m2 + w2 * m1 + w3 * cur + cb);
        xh[(size_t)i * INNER] = __float2half_rn(v);
        m3 = m2; m2 = m1; m1 = cur;
    }
}

// ---------------- chunked selective scan ----------------
// pass A: full half2 local scan; records chunk-end state (half2) + sum(dt)
__global__ void __launch_bounds__(128) scanA_kernel(const float* __restrict__ A_log)
{
    __shared__ uint32_t sBh[LC * 8];
    const int d = blockIdx.x * 128 + threadIdx.x;
    const int c = blockIdx.y;
    const int b = blockIdx.z;
    const int base_l = c * LC;
    for (int i = threadIdx.x; i < LC * 8; i += 128) {
        const float2 v = *reinterpret_cast<const float2*>(
            &g_Bm[(size_t)(b * LEN + base_l) * STATE + 2 * i]);
        __half2 hh = __floats2half2_rn(v.x, v.y);
        sBh[i] = *reinterpret_cast<uint32_t*>(&hh);
    }
    __syncthreads();
    __half2 Ar2[8];
#pragma unroll
    for (int i = 0; i < 8; i++)
        Ar2[i] = __floats2half2_rn(-expf(A_log[d * STATE + 2 * i]) * LOG2E,
                                   -expf(A_log[d * STATE + 2 * i + 1]) * LOG2E);
    __half2 h2[8];
#pragma unroll
    for (int i = 0; i < 8; i++) h2[i] = __floats2half2_rn(0.f, 0.f);
    float dtsum = 0.f;
    const __half* dtp = g_dth + (size_t)(b * LEN + base_l) * INNER + d;
    const __half* xcp = g_xch + (size_t)(b * LEN + base_l) * INNER + d;
    for (int l = 0; l < LC; ++l) {
        __half dtv = dtp[(size_t)l * INNER];
        __half xv  = xcp[(size_t)l * INNER];
        dtsum += __half2float(dtv);
        __half2 dt2  = __half2half2(dtv);
        __half2 dtx2 = __half2half2(__hmul(dtv, xv));
#pragma unroll
        for (int i = 0; i < 8; i++) {
            __half2 dA  = hexp2_x2(__hmul2(dt2, Ar2[i]));
            __half2 inc = __hmul2(*reinterpret_cast<const __half2*>(&sBh[l * 8 + i]), dtx2);
            h2[i] = __hfma2(dA, h2[i], inc);
        }
    }
    size_t sb2 = (size_t)(b * NC + c) * 8 * INNER + d;
#pragma unroll
    for (int i = 0; i < 8; i++)
        g_S2[sb2 + (size_t)i * INNER] = *reinterpret_cast<uint32_t*>(&h2[i]);
    g_dts[(size_t)(b * NC + c) * INNER + d] = dtsum;
}

// pass B: stitch chunk states; P reconstructed exactly as exp(A * dtsum)
__global__ void __launch_bounds__(256) scanB_kernel(const float* __restrict__ A_log)
{
    int g = blockIdx.x * 256 + threadIdx.x;            // 0 .. B*INNER-1
    int b = g / INNER;
    int d = g - b * INNER;
    float Ar[STATE];
#pragma unroll
    for (int s = 0; s < STATE; s++) Ar[s] = -expf(A_log[d * STATE + s]);
    float h[STATE];
#pragma unroll
    for (int s = 0; s < STATE; s++) h[s] = 0.f;
    for (int c = 0; c < NC; ++c) {
        size_t hb = (size_t)(b * NC + c) * STATE * INNER + d;
#pragma unroll
        for (int s = 0; s < STATE; s++) g_H0[hb + (size_t)s * INNER] = h[s];
        float ds = g_dts[(size_t)(b * NC + c) * INNER + d];
        size_t sb2 = (size_t)(b * NC + c) * 8 * INNER + d;
#pragma unroll
        for (int i = 0; i < 8; i++) {
            uint32_t sv = g_S2[sb2 + (size_t)i * INNER];
            float2 svf = __half22float2(*reinterpret_cast<__half2*>(&sv));
            h[2 * i]     = __expf(Ar[2 * i] * ds)     * h[2 * i]     + svf.x;
            h[2 * i + 1] = __expf(Ar[2 * i + 1] * ds) * h[2 * i + 1] + svf.y;
        }
    }
}

// pass C: fp32 replay with correct h0, fused gating
__global__ void __launch_bounds__(128) scanC_kernel(
    const float* __restrict__ A_log, const float* __restrict__ Dv)
{
    __shared__ float sB[LC * STATE];
    __shared__ float sC[LC * STATE];
    const int d = blockIdx.x * 128 + threadIdx.x;
    const int c = blockIdx.y;
    const int b = blockIdx.z;
    const int base_l = c * LC;
    for (int i = threadIdx.x; i < LC * STATE; i += 128) {
        sB[i] = g_Bm[(size_t)(b * LEN + base_l) * STATE + i];
        sC[i] = g_Cm[(size_t)(b * LEN + base_l) * STATE + i];
    }
    __syncthreads();
    __half2 Ar2[8];
#pragma unroll
    for (int i = 0; i < 8; i++)
        Ar2[i] = __floats2half2_rn(-expf(A_log[d * STATE + 2 * i]) * LOG2E,
                                   -expf(A_log[d * STATE + 2 * i + 1]) * LOG2E);
    const float Dd = Dv[d];
    float h[STATE];
    size_t ob = (size_t)(b * NC + c) * STATE * INNER + d;
#pragma unroll
    for (int s = 0; s < STATE; s++) h[s] = g_H0[ob + (size_t)s * INNER];
    const __half* dtp = g_dth + (size_t)(b * LEN + base_l) * INNER + d;
    const __half* xcp = g_xch + (size_t)(b * LEN + base_l) * INNER + d;
    const __half* zp  = g_zh  + (size_t)(b * LEN + base_l) * INNER + d;
    __half* y0p = g_y0h + (size_t)(b * LEN + base_l) * INNER + d;
    for (int l = 0; l < LC; ++l) {
        __half dthv = dtp[(size_t)l * INNER];
        float dtv = __half2float(dthv);
        float xv  = __half2float(xcp[(size_t)l * INNER]);
        float zv  = __half2float(zp[(size_t)l * INNER]);
        float dtx = dtv * xv;
        float acc = Dd * xv;
        __half2 dt2 = __half2half2(dthv);
#pragma unroll
        for (int i = 0; i < 8; i++) {
            float2 dA = __half22float2(hexp2_x2(__hmul2(dt2, Ar2[i])));
            int s0 = 2 * i;
            h[s0] = fmaf(dA.x, h[s0], sB[l * STATE + s0] * dtx);
            acc   = fmaf(sC[l * STATE + s0], h[s0], acc);
            h[s0 + 1] = fmaf(dA.y, h[s0 + 1], sB[l * STATE + s0 + 1] * dtx);
            acc   = fmaf(sC[l * STATE + s0 + 1], h[s0 + 1], acc);
        }
        y0p[(size_t)l * INNER] = __float2half_rn(acc * siluf(zv));
    }
}

// ---------------- launch ----------------
extern "C" void kernel_launch(void* const* d_in, const int* in_sizes, int n_in,
                              void* d_out, int out_size)
{
    const float* x      = (const float*)d_in[0];
    const float* in_w   = (const float*)d_in[1];
    const float* in_b   = (const float*)d_in[2];
    const float* conv_w = (const float*)d_in[3];
    const float* conv_b = (const float*)d_in[4];
    const float* dt_w   = (const float*)d_in[5];
    const float* dt_b   = (const float*)d_in[6];
    const float* A_log  = (const float*)d_in[7];
    const float* B_w    = (const float*)d_in[8];
    const float* B_b    = (const float*)d_in[9];
    const float* C_w    = (const float*)d_in[10];
    const float* C_b    = (const float*)d_in[11];
    const float* Dv     = (const float*)d_in[12];
    const float* out_w  = (const float*)d_in[13];
    const float* out_b  = (const float*)d_in[14];
    float* out = (float*)d_out;

    __half *x0h, *wh, *dtwh, *xch, *y0h, *owh, *wbch, *zh, *dth, *xph;
    cudaGetSymbolAddress((void**)&xph, g_xph);
    cudaGetSymbolAddress((void**)&x0h, g_x0h);
    cudaGetSymbolAddress((void**)&wh, g_wh);
    cudaGetSymbolAddress((void**)&dtwh, g_dtwh);
    cudaGetSymbolAddress((void**)&xch, g_xch);
    cudaGetSymbolAddress((void**)&y0h, g_y0h);
    cudaGetSymbolAddress((void**)&owh, g_owh);
    cudaGetSymbolAddress((void**)&wbch, g_wbch);
    cudaGetSymbolAddress((void**)&zh, g_zh);
    cudaGetSymbolAddress((void**)&dth, g_dth);

    cudaFuncSetAttribute(gemm_mma<1>, cudaFuncAttributeMaxDynamicSharedMemorySize, GSMEM);
    cudaFuncSetAttribute(gemm_mma<0>, cudaFuncAttributeMaxDynamicSharedMemorySize, GSMEM);
    cudaFuncSetAttribute(gemm_mma<2>, cudaFuncAttributeMaxDynamicSharedMemorySize, GSMEM);
    cudaFuncSetAttribute(bc_mma, cudaFuncAttributeMaxDynamicSharedMemorySize, BCSMEM);

    static cudaStream_t s1 = nullptr;
    static cudaEvent_t evA = nullptr, evZ = nullptr;
    if (s1 == nullptr) {
        cudaStreamCreateWithFlags(&s1, cudaStreamNonBlocking);
        cudaEventCreateWithFlags(&evA, cudaEventDisableTiming);
        cudaEventCreateWithFlags(&evZ, cudaEventDisableTiming);
    }

    // 0) fp16 conversions
    cvt1h_kernel<<<2048, 256>>>(x, x0h, (size_t)M_TOT * HID / 4);
    cvtw_kernel<<<2048, 256>>>(in_w, dt_w, out_w, wh, dtwh, owh);
    cudaEventRecord(evA, 0);

    // fork: z half of in-proj on s1
    cudaStreamWaitEvent(s1, evA, 0);
    gemm_mma<2><<<dim3(INNER / GBN, M_TOT / GBM), 256, GSMEM, s1>>>(
        x0h, wh + (size_t)INNER * HID, in_b + INNER, zh, INNER, HID);
    cudaEventRecord(evZ, s1);

    cvtbc_kernel<<<(32 * INNER) / 256, 256>>>(B_w, C_w, wbch);

    // 1) in-proj x_part half -> fp16                       (16384 x 2048 x 1024)
    gemm_mma<2><<<dim3(INNER / GBN, M_TOT / GBM), 256, GSMEM>>>(
        x0h, wh, in_b, xph, INNER, HID);

    // 2) conv + silu (fp16 in/out)
    conv_silu_kernel<<<dim3(INNER / 256, LEN / 128, B_SZ), 256>>>(conv_w, conv_b);

    // 3) B/C projections via mma (N = 32)
    bc_mma<<<M_TOT / 128, 256, BCSMEM>>>(xch, wbch, B_b, C_b);

    // 4) dt = softplus(xconv @ dt_w^T + dt_b) -> fp16      (16384 x 2048 x 2048)
    gemm_mma<1><<<dim3(INNER / GBN, M_TOT / GBM), 256, GSMEM>>>(
        xch, dtwh, dt_b, dth, INNER, INNER);

    // 5) chunked selective scan + gating
    scanA_kernel<<<dim3(INNER / 128, NC, B_SZ), 128>>>(A_log);
    scanB_kernel<<<(B_SZ * INNER) / 256, 256>>>(A_log);
    cudaStreamWaitEvent(0, evZ, 0);
    scanC_kernel<<<dim3(INNER / 128, NC, B_SZ), 128>>>(A_log, Dv);

    // 6) out-proj: out = y @ out_w^T + out_b               (16384 x 1024 x 2048)
    gemm_mma<0><<<dim3(HID / GBN, M_TOT / GBM), 256, GSMEM>>>(
        y0h, owh, out_b, out, HID, INNER);
}

// round 12
// speedup vs baseline: 5.3772x; 1.0746x over previous
#include <cuda_runtime.h>
#include <cuda_fp16.h>
#include <math.h>
#include <stdint.h>

#define B_SZ   4
#define LEN    4096
#define HID    1024
#define STATE  16
#define INNER  2048
#define M_TOT  (B_SZ * LEN)
#define NC     16
#define LC     256
#define LOG2E  1.4426950408889634f

// ---------------- scratch ----------------
__device__ __align__(1024) float    g_Bm  [(size_t)M_TOT * STATE];
__device__ __align__(1024) float    g_Cm  [(size_t)M_TOT * STATE];
__device__ __align__(1024) uint32_t g_S2  [(size_t)B_SZ * NC * 8 * INNER];
__device__ __align__(1024) float    g_dts [(size_t)B_SZ * NC * INNER];
__device__ __align__(1024) float    g_H0  [(size_t)B_SZ * NC * STATE * INNER];
__device__ __align__(1024) __half   g_xph [(size_t)M_TOT * INNER];
__device__ __align__(1024) __half   g_zh  [(size_t)M_TOT * INNER];
__device__ __align__(1024) __half   g_dth [(size_t)M_TOT * INNER];
__device__ __align__(1024) __half   g_x0h [(size_t)M_TOT * HID];
__device__ __align__(1024) __half   g_wh  [(size_t)2 * INNER * HID];
__device__ __align__(1024) __half   g_dtwh[(size_t)INNER * INNER];
__device__ __align__(1024) __half   g_xch [(size_t)M_TOT * INNER];
__device__ __align__(1024) __half   g_y0h [(size_t)M_TOT * INNER];
__device__ __align__(1024) __half   g_owh [(size_t)HID * INNER];
__device__ __align__(1024) __half   g_wbch[32 * INNER];

// ---------------- PTX helpers ----------------
__device__ __forceinline__ uint32_t smem_u32(const void* p) {
    uint32_t a;
    asm("{ .reg .u64 t; cvta.to.shared.u64 t, %1; cvt.u32.u64 %0, t; }" : "=r"(a) : "l"(p));
    return a;
}
__device__ __forceinline__ void cp_async16(uint32_t dst, const void* src) {
    asm volatile("cp.async.cg.shared.global [%0], [%1], 16;" :: "r"(dst), "l"(src) : "memory");
}
#define CP_COMMIT() asm volatile("cp.async.commit_group;" ::: "memory")
#define CP_WAIT1()  asm volatile("cp.async.wait_group 1;" ::: "memory")

__device__ __forceinline__ void ldm_x4(uint32_t* r, uint32_t addr) {
    asm volatile("ldmatrix.sync.aligned.m8n8.x4.shared.b16 {%0,%1,%2,%3}, [%4];"
        : "=r"(r[0]), "=r"(r[1]), "=r"(r[2]), "=r"(r[3]) : "r"(addr));
}
__device__ __forceinline__ void mma16816h(float* d, const uint32_t* a, const uint32_t* b) {
    asm volatile("mma.sync.aligned.m16n8k16.row.col.f32.f16.f16.f32 "
        "{%0,%1,%2,%3}, {%4,%5,%6,%7}, {%8,%9}, {%0,%1,%2,%3};"
        : "+f"(d[0]), "+f"(d[1]), "+f"(d[2]), "+f"(d[3])
        : "r"(a[0]), "r"(a[1]), "r"(a[2]), "r"(a[3]), "r"(b[0]), "r"(b[1]));
}
__device__ __forceinline__ __half2 hexp2_x2(__half2 x) {
    __half2 r;
    asm("ex2.approx.f16x2 %0, %1;" : "=r"(*(uint32_t*)&r) : "r"(*(uint32_t*)&x));
    return r;
}
__device__ __forceinline__ float softplusf(float v) { return v > 20.f ? v : log1pf(__expf(v)); }
__device__ __forceinline__ float siluf(float v)     { return v / (1.f + __expf(-v)); }

// ---------------- fp16 mma.sync GEMM (unchanged core) ----------------
#define GBM 128
#define GBN 256
#define GAST (GBM * 128)
#define GSTG (GAST + GBN * 128)
#define GSMEM (3 * GSTG)

template <int EPI>   // 0 = fp32 bias, 1 = fp16 softplus, 2 = fp16 bias
__global__ void __launch_bounds__(256, 1) gemm_mma(
    const __half* __restrict__ Ap, const __half* __restrict__ Bp,
    const float* __restrict__ bias, void* __restrict__ Cv, int Cstride, int K)
{
    extern __shared__ char smraw[];
    const uint32_t sbase = smem_u32(smraw);
    const int tid  = threadIdx.x;
    const int wid  = tid >> 5;
    const int lane = tid & 31;
    const int bm0  = blockIdx.y * GBM;
    const int bn0  = blockIdx.x * GBN;

    const int KTT = K >> 6;
    const size_t lda = (size_t)K * 2;

    auto load_stage = [&](int kt, int s) {
        const uint32_t sa = sbase + s * GSTG;
        const uint32_t sb = sa + GAST;
#pragma unroll
        for (int i = 0; i < 4; ++i) {
            int idx = tid + i * 256, r = idx >> 3, c = idx & 7;
            cp_async16(sa + r * 128 + ((c ^ (r & 7)) << 4),
                       (const char*)Ap + (size_t)(bm0 + r) * lda + (size_t)kt * 128 + c * 16);
        }
#pragma unroll
        for (int i = 0; i < 8; ++i) {
            int idx = tid + i * 256, r = idx >> 3, c = idx & 7;
            cp_async16(sb + r * 128 + ((c ^ (r & 7)) << 4),
                       (const char*)Bp + (size_t)(bn0 + r) * lda + (size_t)kt * 128 + c * 16);
        }
    };

    float acc[4][8][4];
#pragma unroll
    for (int mt = 0; mt < 4; ++mt)
#pragma unroll
        for (int nt = 0; nt < 8; ++nt)
#pragma unroll
            for (int q = 0; q < 4; ++q) acc[mt][nt][q] = 0.f;

    load_stage(0, 0); CP_COMMIT();
    load_stage(1, 1); CP_COMMIT();

    const int wm0 = (wid >> 2) * 64;
    const int wn0 = (wid & 3) * 64;
    const int aRow = wm0 + ((lane >> 3) & 1) * 8 + (lane & 7);
    const int bRow = wn0 + ((lane >> 4) & 1) * 8 + (lane & 7);
    const int swzX = (lane & 7) << 4;
    const int aKs  = (lane >> 4) << 4;
    const int bKs  = ((lane >> 3) & 1) << 4;

    for (int kt = 0; kt < KTT; ++kt) {
        const int s = kt % 3;
        CP_WAIT1();
        __syncthreads();
        if (kt + 2 < KTT) { load_stage(kt + 2, (kt + 2) % 3); CP_COMMIT(); }

        const uint32_t Ab = sbase + s * GSTG;
        const uint32_t Bb = Ab + GAST;
#pragma unroll
        for (int ks = 0; ks < 4; ++ks) {
            const int swA = (ks * 32 + aKs) ^ swzX;
            const int swB = (ks * 32 + bKs) ^ swzX;
            uint32_t a[4][4], b[4][4];
#pragma unroll
            for (int mt = 0; mt < 4; ++mt) ldm_x4(a[mt], Ab + (aRow + mt * 16) * 128 + swA);
#pragma unroll
            for (int np = 0; np < 4; ++np) ldm_x4(b[np], Bb + (bRow + np * 16) * 128 + swB);
#pragma unroll
            for (int mt = 0; mt < 4; ++mt)
#pragma unroll
                for (int nt = 0; nt < 8; ++nt)
                    mma16816h(acc[mt][nt], a[mt], &b[nt >> 1][(nt & 1) * 2]);
        }
    }

#pragma unroll
    for (int nt = 0; nt < 8; ++nt) {
        const int col = bn0 + wn0 + nt * 8 + (lane & 3) * 2;
        const float b0v = bias[col], b1v = bias[col + 1];
#pragma unroll
        for (int mt = 0; mt < 4; ++mt) {
            const int row = bm0 + wm0 + mt * 16 + (lane >> 2);
            float v0 = acc[mt][nt][0] + b0v, v1 = acc[mt][nt][1] + b1v;
            float v2 = acc[mt][nt][2] + b0v, v3 = acc[mt][nt][3] + b1v;
            if (EPI == 1) {
                v0 = softplusf(v0); v1 = softplusf(v1);
                v2 = softplusf(v2); v3 = softplusf(v3);
            }
            if (EPI == 0) {
                float* C = (float*)Cv;
                *reinterpret_cast<float2*>(&C[(size_t)row * Cstride + col])       = make_float2(v0, v1);
                *reinterpret_cast<float2*>(&C[(size_t)(row + 8) * Cstride + col]) = make_float2(v2, v3);
            } else {
                __half* C = (__half*)Cv;
                *reinterpret_cast<__half2*>(&C[(size_t)row * Cstride + col])       = __floats2half2_rn(v0, v1);
                *reinterpret_cast<__half2*>(&C[(size_t)(row + 8) * Cstride + col]) = __floats2half2_rn(v2, v3);
            }
        }
    }
}

// ---------------- B/C projection via mma ----------------
#define BCAST (128 * 128)
#define BCSTG (BCAST + 32 * 128)
#define BCSMEM (3 * BCSTG)
__global__ void __launch_bounds__(256, 1) bc_mma(
    const __half* __restrict__ A, const __half* __restrict__ W,
    const float* __restrict__ Bb, const float* __restrict__ Cb)
{
    extern __shared__ char smraw[];
    const uint32_t sbase = smem_u32(smraw);
    const int tid  = threadIdx.x;
    const int wid  = tid >> 5;
    const int lane = tid & 31;
    const int bm0  = blockIdx.x * 128;
    const size_t lda = (size_t)INNER * 2;

    auto load_stage = [&](int kt, int s) {
        const uint32_t sa = sbase + s * BCSTG;
        const uint32_t sb = sa + BCAST;
#pragma unroll
        for (int i = 0; i < 4; ++i) {
            int idx = tid + i * 256, r = idx >> 3, c = idx & 7;
            cp_async16(sa + r * 128 + ((c ^ (r & 7)) << 4),
                       (const char*)A + (size_t)(bm0 + r) * lda + (size_t)kt * 128 + c * 16);
        }
        {
            int r = tid >> 3, c = tid & 7;
            cp_async16(sb + r * 128 + ((c ^ (r & 7)) << 4),
                       (const char*)W + (size_t)r * lda + (size_t)kt * 128 + c * 16);
        }
    };

    float acc[4][4];
#pragma unroll
    for (int nt = 0; nt < 4; ++nt)
#pragma unroll
        for (int q = 0; q < 4; ++q) acc[nt][q] = 0.f;

    load_stage(0, 0); CP_COMMIT();
    load_stage(1, 1); CP_COMMIT();

    const int aRow = wid * 16 + ((lane >> 3) & 1) * 8 + (lane & 7);
    const int bRow = ((lane >> 4) & 1) * 8 + (lane & 7);
    const int swzX = (lane & 7) << 4;
    const int aKs  = (lane >> 4) << 4;
    const int bKs  = ((lane >> 3) & 1) << 4;

    const int KT = INNER / 64;
    for (int kt = 0; kt < KT; ++kt) {
        const int s = kt % 3;
        CP_WAIT1();
        __syncthreads();
        if (kt + 2 < KT) { load_stage(kt + 2, (kt + 2) % 3); CP_COMMIT(); }

        const uint32_t Ab = sbase + s * BCSTG;
        const uint32_t Bb_ = Ab + BCAST;
#pragma unroll
        for (int ks = 0; ks < 4; ++ks) {
            const int swA = (ks * 32 + aKs) ^ swzX;
            const int swB = (ks * 32 + bKs) ^ swzX;
            uint32_t a[4], b[2][4];
            ldm_x4(a, Ab + aRow * 128 + swA);
#pragma unroll
            for (int np = 0; np < 2; ++np) ldm_x4(b[np], Bb_ + (bRow + np * 16) * 128 + swB);
#pragma unroll
            for (int nt = 0; nt < 4; ++nt)
                mma16816h(acc[nt], a, &b[nt >> 1][(nt & 1) * 2]);
        }
    }

#pragma unroll
    for (int nt = 0; nt < 4; ++nt) {
        const int col = nt * 8 + (lane & 3) * 2;
        const int row = bm0 + wid * 16 + (lane >> 2);
        if (col < 16) {
            const float c0 = Bb[col], c1 = Bb[col + 1];
            *reinterpret_cast<float2*>(&g_Bm[(size_t)row * 16 + col]) =
                make_float2(acc[nt][0] + c0, acc[nt][1] + c1);
            *reinterpret_cast<float2*>(&g_Bm[(size_t)(row + 8) * 16 + col]) =
                make_float2(acc[nt][2] + c0, acc[nt][3] + c1);
        } else {
            const int cc = col - 16;
            const float c0 = Cb[cc], c1 = Cb[cc + 1];
            *reinterpret_cast<float2*>(&g_Cm[(size_t)row * 16 + cc]) =
                make_float2(acc[nt][0] + c0, acc[nt][1] + c1);
            *reinterpret_cast<float2*>(&g_Cm[(size_t)(row + 8) * 16 + cc]) =
                make_float2(acc[nt][2] + c0, acc[nt][3] + c1);
        }
    }
}

// ---------------- conversion kernels ----------------
__global__ void __launch_bounds__(256) cvt1h_kernel(
    const float* __restrict__ in, __half* __restrict__ o0, size_t n4)
{
    for (size_t i = (size_t)blockIdx.x * 256 + threadIdx.x; i < n4; i += (size_t)gridDim.x * 256) {
        float4 v = reinterpret_cast<const float4*>(in)[i];
        ((ushort4*)o0)[i] = make_ushort4(
            __half_as_ushort(__float2half_rn(v.x)), __half_as_ushort(__float2half_rn(v.y)),
            __half_as_ushort(__float2half_rn(v.z)), __half_as_ushort(__float2half_rn(v.w)));
    }
}
// all weights (in_w, dt_w, out_w, B_w, C_w) in one launch
__global__ void __launch_bounds__(256) cvtw_kernel(
    const float* __restrict__ w1, const float* __restrict__ w2, const float* __restrict__ w3,
    const float* __restrict__ w4, const float* __restrict__ w5,
    __half* __restrict__ o1, __half* __restrict__ o2, __half* __restrict__ o3,
    __half* __restrict__ o4)
{
    const size_t n1 = (size_t)2 * INNER * HID / 4;
    const size_t n2 = (size_t)INNER * INNER / 4;
    const size_t n3 = (size_t)HID * INNER / 4;
    const size_t n4 = (size_t)16 * INNER / 4;       // B_w -> o4[0]
    const size_t n5 = (size_t)16 * INNER / 4;       // C_w -> o4[16*INNER]
    for (size_t i = (size_t)blockIdx.x * 256 + threadIdx.x; i < n1 + n2 + n3 + n4 + n5;
         i += (size_t)gridDim.x * 256) {
        const float* src; __half* dst; size_t j;
        if (i < n1)                 { src = w1; dst = o1; j = i; }
        else if (i < n1 + n2)       { src = w2; dst = o2; j = i - n1; }
        else if (i < n1 + n2 + n3)  { src = w3; dst = o3; j = i - n1 - n2; }
        else if (i < n1 + n2 + n3 + n4) { src = w4; dst = o4; j = i - n1 - n2 - n3; }
        else { src = w5; dst = o4 + (size_t)16 * INNER / 4 * 4; j = i - n1 - n2 - n3 - n4; }
        float4 v = reinterpret_cast<const float4*>(src)[j];
        ((ushort4*)dst)[j] = make_ushort4(
            __half_as_ushort(__float2half_rn(v.x)), __half_as_ushort(__float2half_rn(v.y)),
            __half_as_ushort(__float2half_rn(v.z)), __half_as_ushort(__float2half_rn(v.w)));
    }
}

// ---------------- causal depthwise conv (K=4) + SiLU, half2 vectorized ----------------
// grid (INNER/256, LEN/128, B), block 128 -> each thread owns 2 adjacent channels
__global__ void __launch_bounds__(128) conv_silu_kernel(
    const float* __restrict__ conv_w, const float* __restrict__ conv_b)
{
    const int d2 = blockIdx.x * 128 + threadIdx.x;     // half2 index
    const int l0 = blockIdx.y * 128;
    const int b  = blockIdx.z;
    const int d  = d2 * 2;
    const float2 w0 = make_float2(conv_w[d * 4 + 0], conv_w[d * 4 + 4]);
    const float2 w1 = make_float2(conv_w[d * 4 + 1], conv_w[d * 4 + 5]);
    const float2 w2 = make_float2(conv_w[d * 4 + 2], conv_w[d * 4 + 6]);
    const float2 w3 = make_float2(conv_w[d * 4 + 3], conv_w[d * 4 + 7]);
    const float2 cb = make_float2(conv_b[d], conv_b[d + 1]);
    const __half2* xp = (const __half2*)g_xph + (size_t)(b * LEN) * (INNER / 2) + d2;
    float2 m3, m2, m1;
    if (l0 == 0) { m3 = m2 = m1 = make_float2(0.f, 0.f); }
    else {
        m3 = __half22float2(xp[(size_t)(l0 - 3) * (INNER / 2)]);
        m2 = __half22float2(xp[(size_t)(l0 - 2) * (INNER / 2)]);
        m1 = __half22float2(xp[(size_t)(l0 - 1) * (INNER / 2)]);
    }
    __half2* xh = (__half2*)g_xch + (size_t)(b * LEN + l0) * (INNER / 2) + d2;
#pragma unroll 4
    for (int i = 0; i < 128; ++i) {
        float2 cur = __half22float2(xp[(size_t)(l0 + i) * (INNER / 2)]);
        float vx = w0.x * m3.x + w1.x * m2.x + w2.x * m1.x + w3.x * cur.x + cb.x;
        float vy = w0.y * m3.y + w1.y * m2.y + w2.y * m1.y + w3.y * cur.y + cb.y;
        xh[(size_t)i * (INNER / 2)] = __floats2half2_rn(siluf(vx), siluf(vy));
        m3 = m2; m2 = m1; m1 = cur;
    }
}

// ---------------- chunked selective scan ----------------
// pass A: full half2 local scan; records chunk-end state (half2) + sum(dt)
__global__ void __launch_bounds__(128) scanA_kernel(const float* __restrict__ A_log)
{
    __shared__ uint32_t sBh[LC * 8];
    const int d = blockIdx.x * 128 + threadIdx.x;
    const int c = blockIdx.y;
    const int b = blockIdx.z;
    const int base_l = c * LC;
    for (int i = threadIdx.x; i < LC * 8; i += 128) {
        const float2 v = *reinterpret_cast<const float2*>(
            &g_Bm[(size_t)(b * LEN + base_l) * STATE + 2 * i]);
        __half2 hh = __floats2half2_rn(v.x, v.y);
        sBh[i] = *reinterpret_cast<uint32_t*>(&hh);
    }
    __syncthreads();
    __half2 Ar2[8];
#pragma unroll
    for (int i = 0; i < 8; i++)
        Ar2[i] = __floats2half2_rn(-expf(A_log[d * STATE + 2 * i]) * LOG2E,
                                   -expf(A_log[d * STATE + 2 * i + 1]) * LOG2E);
    __half2 h2[8];
#pragma unroll
    for (int i = 0; i < 8; i++) h2[i] = __floats2half2_rn(0.f, 0.f);
    float dtsum = 0.f;
    const __half* dtp = g_dth + (size_t)(b * LEN + base_l) * INNER + d;
    const __half* xcp = g_xch + (size_t)(b * LEN + base_l) * INNER + d;
    for (int l = 0; l < LC; ++l) {
        __half dtv = dtp[(size_t)l * INNER];
        __half xv  = xcp[(size_t)l * INNER];
        dtsum += __half2float(dtv);
        __half2 dt2  = __half2half2(dtv);
        __half2 dtx2 = __half2half2(__hmul(dtv, xv));
#pragma unroll
        for (int i = 0; i < 8; i++) {
            __half2 dA  = hexp2_x2(__hmul2(dt2, Ar2[i]));
            __half2 inc = __hmul2(*reinterpret_cast<const __half2*>(&sBh[l * 8 + i]), dtx2);
            h2[i] = __hfma2(dA, h2[i], inc);
        }
    }
    size_t sb2 = (size_t)(b * NC + c) * 8 * INNER + d;
#pragma unroll
    for (int i = 0; i < 8; i++)
        g_S2[sb2 + (size_t)i * INNER] = *reinterpret_cast<uint32_t*>(&h2[i]);
    g_dts[(size_t)(b * NC + c) * INNER + d] = dtsum;
}

// pass B: stitch chunk states; P reconstructed exactly as exp(A * dtsum)
__global__ void __launch_bounds__(256) scanB_kernel(const float* __restrict__ A_log)
{
    int g = blockIdx.x * 256 + threadIdx.x;
    int b = g / INNER;
    int d = g - b * INNER;
    float Ar[STATE];
#pragma unroll
    for (int s = 0; s < STATE; s++) Ar[s] = -expf(A_log[d * STATE + s]);
    float h[STATE];
#pragma unroll
    for (int s = 0; s < STATE; s++) h[s] = 0.f;
    for (int c = 0; c < NC; ++c) {
        size_t hb = (size_t)(b * NC + c) * STATE * INNER + d;
#pragma unroll
        for (int s = 0; s < STATE; s++) g_H0[hb + (size_t)s * INNER] = h[s];
        float ds = g_dts[(size_t)(b * NC + c) * INNER + d];
        size_t sb2 = (size_t)(b * NC + c) * 8 * INNER + d;
#pragma unroll
        for (int i = 0; i < 8; i++) {
            uint32_t sv = g_S2[sb2 + (size_t)i * INNER];
            float2 svf = __half22float2(*reinterpret_cast<__half2*>(&sv));
            h[2 * i]     = __expf(Ar[2 * i] * ds)     * h[2 * i]     + svf.x;
            h[2 * i + 1] = __expf(Ar[2 * i + 1] * ds) * h[2 * i + 1] + svf.y;
        }
    }
}

// pass C: half2 replay with correct h0, fused gating (D*x + silu in fp32)
__global__ void __launch_bounds__(128) scanC_kernel(
    const float* __restrict__ A_log, const float* __restrict__ Dv)
{
    __shared__ uint32_t sBh[LC * 8];
    __shared__ uint32_t sCh[LC * 8];
    const int d = blockIdx.x * 128 + threadIdx.x;
    const int c = blockIdx.y;
    const int b = blockIdx.z;
    const int base_l = c * LC;
    for (int i = threadIdx.x; i < LC * 8; i += 128) {
        const float2 vb = *reinterpret_cast<const float2*>(
            &g_Bm[(size_t)(b * LEN + base_l) * STATE + 2 * i]);
        const float2 vc = *reinterpret_cast<const float2*>(
            &g_Cm[(size_t)(b * LEN + base_l) * STATE + 2 * i]);
        __half2 hb = __floats2half2_rn(vb.x, vb.y);
        __half2 hc = __floats2half2_rn(vc.x, vc.y);
        sBh[i] = *reinterpret_cast<uint32_t*>(&hb);
        sCh[i] = *reinterpret_cast<uint32_t*>(&hc);
    }
    __syncthreads();
    __half2 Ar2[8];
#pragma unroll
    for (int i = 0; i < 8; i++)
        Ar2[i] = __floats2half2_rn(-expf(A_log[d * STATE + 2 * i]) * LOG2E,
                                   -expf(A_log[d * STATE + 2 * i + 1]) * LOG2E);
    const float Dd = Dv[d];
    __half2 h2[8];
    size_t ob = (size_t)(b * NC + c) * STATE * INNER + d;
#pragma unroll
    for (int i = 0; i < 8; i++)
        h2[i] = __floats2half2_rn(g_H0[ob + (size_t)(2 * i) * INNER],
                                  g_H0[ob + (size_t)(2 * i + 1) * INNER]);
    const __half* dtp = g_dth + (size_t)(b * LEN + base_l) * INNER + d;
    const __half* xcp = g_xch + (size_t)(b * LEN + base_l) * INNER + d;
    const __half* zp  = g_zh  + (size_t)(b * LEN + base_l) * INNER + d;
    __half* y0p = g_y0h + (size_t)(b * LEN + base_l) * INNER + d;
    for (int l = 0; l < LC; ++l) {
        __half dtv = dtp[(size_t)l * INNER];
        __half xv  = xcp[(size_t)l * INNER];
        float zv   = __half2float(zp[(size_t)l * INNER]);
        __half2 dt2  = __half2half2(dtv);
        __half2 dtx2 = __half2half2(__hmul(dtv, xv));
        __half2 acc2 = __floats2half2_rn(0.f, 0.f);
#pragma unroll
        for (int i = 0; i < 8; i++) {
            __half2 dA  = hexp2_x2(__hmul2(dt2, Ar2[i]));
            __half2 inc = __hmul2(*reinterpret_cast<const __half2*>(&sBh[l * 8 + i]), dtx2);
            h2[i] = __hfma2(dA, h2[i], inc);
            acc2  = __hfma2(*reinterpret_cast<const __half2*>(&sCh[l * 8 + i]), h2[i], acc2);
        }
        float acc = __low2float(acc2) + __high2float(acc2) + Dd * __half2float(xv);
        y0p[(size_t)l * INNER] = __float2half_rn(acc * siluf(zv));
    }
}

// ---------------- launch ----------------
extern "C" void kernel_launch(void* const* d_in, const int* in_sizes, int n_in,
                              void* d_out, int out_size)
{
    const float* x      = (const float*)d_in[0];
    const float* in_w   = (const float*)d_in[1];
    const float* in_b   = (const float*)d_in[2];
    const float* conv_w = (const float*)d_in[3];
    const float* conv_b = (const float*)d_in[4];
    const float* dt_w   = (const float*)d_in[5];
    const float* dt_b   = (const float*)d_in[6];
    const float* A_log  = (const float*)d_in[7];
    const float* B_w    = (const float*)d_in[8];
    const float* B_b    = (const float*)d_in[9];
    const float* C_w    = (const float*)d_in[10];
    const float* C_b    = (const float*)d_in[11];
    const float* Dv     = (const float*)d_in[12];
    const float* out_w  = (const float*)d_in[13];
    const float* out_b  = (const float*)d_in[14];
    float* out = (float*)d_out;

    __half *x0h, *wh, *dtwh, *xch, *y0h, *owh, *wbch, *zh, *dth, *xph;
    cudaGetSymbolAddress((void**)&xph, g_xph);
    cudaGetSymbolAddress((void**)&x0h, g_x0h);
    cudaGetSymbolAddress((void**)&wh, g_wh);
    cudaGetSymbolAddress((void**)&dtwh, g_dtwh);
    cudaGetSymbolAddress((void**)&xch, g_xch);
    cudaGetSymbolAddress((void**)&y0h, g_y0h);
    cudaGetSymbolAddress((void**)&owh, g_owh);
    cudaGetSymbolAddress((void**)&wbch, g_wbch);
    cudaGetSymbolAddress((void**)&zh, g_zh);
    cudaGetSymbolAddress((void**)&dth, g_dth);

    cudaFuncSetAttribute(gemm_mma<1>, cudaFuncAttributeMaxDynamicSharedMemorySize, GSMEM);
    cudaFuncSetAttribute(gemm_mma<0>, cudaFuncAttributeMaxDynamicSharedMemorySize, GSMEM);
    cudaFuncSetAttribute(gemm_mma<2>, cudaFuncAttributeMaxDynamicSharedMemorySize, GSMEM);
    cudaFuncSetAttribute(bc_mma, cudaFuncAttributeMaxDynamicSharedMemorySize, BCSMEM);

    static cudaStream_t s1 = nullptr;
    static cudaEvent_t evA = nullptr, evZ = nullptr;
    if (s1 == nullptr) {
        cudaStreamCreateWithFlags(&s1, cudaStreamNonBlocking);
        cudaEventCreateWithFlags(&evA, cudaEventDisableTiming);
        cudaEventCreateWithFlags(&evZ, cudaEventDisableTiming);
    }

    // 0) fp16 conversions
    cvt1h_kernel<<<2048, 256>>>(x, x0h, (size_t)M_TOT * HID / 4);
    cvtw_kernel<<<2048, 256>>>(in_w, dt_w, out_w, B_w, C_w, wh, dtwh, owh, wbch);
    cudaEventRecord(evA, 0);

    // fork: z half of in-proj on s1
    cudaStreamWaitEvent(s1, evA, 0);
    gemm_mma<2><<<dim3(INNER / GBN, M_TOT / GBM), 256, GSMEM, s1>>>(
        x0h, wh + (size_t)INNER * HID, in_b + INNER, zh, INNER, HID);
    cudaEventRecord(evZ, s1);

    // 1) in-proj x_part half -> fp16                       (16384 x 2048 x 1024)
    gemm_mma<2><<<dim3(INNER / GBN, M_TOT / GBM), 256, GSMEM>>>(
        x0h, wh, in_b, xph, INNER, HID);

    // 2) conv + silu (half2 vectorized)
    conv_silu_kernel<<<dim3(INNER / 256, LEN / 128, B_SZ), 128>>>(conv_w, conv_b);

    // 3) B/C projections via mma (N = 32)
    bc_mma<<<M_TOT / 128, 256, BCSMEM>>>(xch, wbch, B_b, C_b);

    // 4) dt = softplus(xconv @ dt_w^T + dt_b) -> fp16      (16384 x 2048 x 2048)
    gemm_mma<1><<<dim3(INNER / GBN, M_TOT / GBM), 256, GSMEM>>>(
        xch, dtwh, dt_b, dth, INNER, INNER);

    // 5) chunked selective scan + gating
    scanA_kernel<<<dim3(INNER / 128, NC, B_SZ), 128>>>(A_log);
    scanB_kernel<<<(B_SZ * INNER) / 256, 256>>>(A_log);
    cudaStreamWaitEvent(0, evZ, 0);
    scanC_kernel<<<dim3(INNER / 128, NC, B_SZ), 128>>>(A_log, Dv);

    // 6) out-proj: out = y @ out_w^T + out_b               (16384 x 1024 x 2048)
    gemm_mma<0><<<dim3(HID / GBN, M_TOT / GBM), 256, GSMEM>>>(
        y0h, owh, out_b, out, HID, INNER);
}

// round 13
// speedup vs baseline: 5.8436x; 1.0867x over previous
#include <cuda_runtime.h>
#include <cuda_fp16.h>
#include <math.h>
#include <stdint.h>

#define B_SZ   4
#define LEN    4096
#define HID    1024
#define STATE  16
#define INNER  2048
#define M_TOT  (B_SZ * LEN)
#define NC     16
#define LC     256
#define LOG2E  1.4426950408889634f

// ---------------- scratch ----------------
__device__ __align__(1024) float    g_Bm  [(size_t)M_TOT * STATE];
__device__ __align__(1024) float    g_Cm  [(size_t)M_TOT * STATE];
__device__ __align__(1024) uint32_t g_S2  [(size_t)B_SZ * NC * 8 * INNER];
__device__ __align__(1024) float    g_dts [(size_t)B_SZ * NC * INNER];
__device__ __align__(1024) float    g_H0  [(size_t)B_SZ * NC * STATE * INNER];
__device__ __align__(1024) __half   g_xph [(size_t)M_TOT * INNER];
__device__ __align__(1024) __half   g_zh  [(size_t)M_TOT * INNER];
__device__ __align__(1024) __half   g_dth [(size_t)M_TOT * INNER];
__device__ __align__(1024) __half   g_x0h [(size_t)M_TOT * HID];
__device__ __align__(1024) __half   g_wh  [(size_t)2 * INNER * HID];
__device__ __align__(1024) __half   g_dtwh[(size_t)INNER * INNER];
__device__ __align__(1024) __half   g_xch [(size_t)M_TOT * INNER];
__device__ __align__(1024) __half   g_y0h [(size_t)M_TOT * INNER];
__device__ __align__(1024) __half   g_owh [(size_t)HID * INNER];
__device__ __align__(1024) __half   g_wbch[32 * INNER];

// ---------------- PTX helpers ----------------
__device__ __forceinline__ uint32_t smem_u32(const void* p) {
    uint32_t a;
    asm("{ .reg .u64 t; cvta.to.shared.u64 t, %1; cvt.u32.u64 %0, t; }" : "=r"(a) : "l"(p));
    return a;
}
__device__ __forceinline__ void cp_async16(uint32_t dst, const void* src) {
    asm volatile("cp.async.cg.shared.global [%0], [%1], 16;" :: "r"(dst), "l"(src) : "memory");
}
#define CP_COMMIT() asm volatile("cp.async.commit_group;" ::: "memory")
#define CP_WAIT1()  asm volatile("cp.async.wait_group 1;" ::: "memory")

__device__ __forceinline__ void ldm_x4(uint32_t* r, uint32_t addr) {
    asm volatile("ldmatrix.sync.aligned.m8n8.x4.shared.b16 {%0,%1,%2,%3}, [%4];"
        : "=r"(r[0]), "=r"(r[1]), "=r"(r[2]), "=r"(r[3]) : "r"(addr));
}
__device__ __forceinline__ void mma16816h(float* d, const uint32_t* a, const uint32_t* b) {
    asm volatile("mma.sync.aligned.m16n8k16.row.col.f32.f16.f16.f32 "
        "{%0,%1,%2,%3}, {%4,%5,%6,%7}, {%8,%9}, {%0,%1,%2,%3};"
        : "+f"(d[0]), "+f"(d[1]), "+f"(d[2]), "+f"(d[3])
        : "r"(a[0]), "r"(a[1]), "r"(a[2]), "r"(a[3]), "r"(b[0]), "r"(b[1]));
}
__device__ __forceinline__ __half2 hexp2_x2(__half2 x) {
    __half2 r;
    asm("ex2.approx.f16x2 %0, %1;" : "=r"(*(uint32_t*)&r) : "r"(*(uint32_t*)&x));
    return r;
}
__device__ __forceinline__ float softplusf(float v) { return v > 20.f ? v : log1pf(__expf(v)); }
__device__ __forceinline__ float siluf(float v)     { return v / (1.f + __expf(-v)); }

// ---------------- fp16 mma.sync GEMM, 2 CTAs/SM tiling ----------------
// BM=128, BN=128, BK=64 (SW128), 8 warps of 64x32 tiles, 3-stage cp.async, 96KB smem.
#define GBM 128
#define GBN 128
#define GAST (GBM * 128)
#define GSTG (GAST + GBN * 128)
#define GSMEM (3 * GSTG)

template <int EPI>   // 0 = fp32 bias, 1 = fp16 softplus, 2 = fp16 bias
__global__ void __launch_bounds__(256, 2) gemm_mma(
    const __half* __restrict__ Ap, const __half* __restrict__ Bp,
    const float* __restrict__ bias, void* __restrict__ Cv, int Cstride, int K)
{
    extern __shared__ char smraw[];
    const uint32_t sbase = smem_u32(smraw);
    const int tid  = threadIdx.x;
    const int wid  = tid >> 5;
    const int lane = tid & 31;
    const int bm0  = blockIdx.y * GBM;
    const int bn0  = blockIdx.x * GBN;

    const int KTT = K >> 6;
    const size_t lda = (size_t)K * 2;

    auto load_stage = [&](int kt, int s) {
        const uint32_t sa = sbase + s * GSTG;
        const uint32_t sb = sa + GAST;
#pragma unroll
        for (int i = 0; i < 4; ++i) {
            int idx = tid + i * 256, r = idx >> 3, c = idx & 7;
            cp_async16(sa + r * 128 + ((c ^ (r & 7)) << 4),
                       (const char*)Ap + (size_t)(bm0 + r) * lda + (size_t)kt * 128 + c * 16);
        }
#pragma unroll
        for (int i = 0; i < 4; ++i) {
            int idx = tid + i * 256, r = idx >> 3, c = idx & 7;
            cp_async16(sb + r * 128 + ((c ^ (r & 7)) << 4),
                       (const char*)Bp + (size_t)(bn0 + r) * lda + (size_t)kt * 128 + c * 16);
        }
    };

    float acc[4][4][4];
#pragma unroll
    for (int mt = 0; mt < 4; ++mt)
#pragma unroll
        for (int nt = 0; nt < 4; ++nt)
#pragma unroll
            for (int q = 0; q < 4; ++q) acc[mt][nt][q] = 0.f;

    load_stage(0, 0); CP_COMMIT();
    load_stage(1, 1); CP_COMMIT();

    const int wm0 = (wid >> 2) * 64;            // 0 / 64
    const int wn0 = (wid & 3) * 32;             // 0..96
    const int aRow = wm0 + ((lane >> 3) & 1) * 8 + (lane & 7);
    const int bRow = wn0 + ((lane >> 4) & 1) * 8 + (lane & 7);
    const int swzX = (lane & 7) << 4;
    const int aKs  = (lane >> 4) << 4;
    const int bKs  = ((lane >> 3) & 1) << 4;

    for (int kt = 0; kt < KTT; ++kt) {
        const int s = kt % 3;
        CP_WAIT1();
        __syncthreads();
        if (kt + 2 < KTT) { load_stage(kt + 2, (kt + 2) % 3); CP_COMMIT(); }

        const uint32_t Ab = sbase + s * GSTG;
        const uint32_t Bb = Ab + GAST;
#pragma unroll
        for (int ks = 0; ks < 4; ++ks) {
            const int swA = (ks * 32 + aKs) ^ swzX;
            const int swB = (ks * 32 + bKs) ^ swzX;
            uint32_t a[4][4], b[2][4];
#pragma unroll
            for (int mt = 0; mt < 4; ++mt) ldm_x4(a[mt], Ab + (aRow + mt * 16) * 128 + swA);
#pragma unroll
            for (int np = 0; np < 2; ++np) ldm_x4(b[np], Bb + (bRow + np * 16) * 128 + swB);
#pragma unroll
            for (int mt = 0; mt < 4; ++mt)
#pragma unroll
                for (int nt = 0; nt < 4; ++nt)
                    mma16816h(acc[mt][nt], a[mt], &b[nt >> 1][(nt & 1) * 2]);
        }
    }

#pragma unroll
    for (int nt = 0; nt < 4; ++nt) {
        const int col = bn0 + wn0 + nt * 8 + (lane & 3) * 2;
        const float b0v = bias[col], b1v = bias[col + 1];
#pragma unroll
        for (int mt = 0; mt < 4; ++mt) {
            const int row = bm0 + wm0 + mt * 16 + (lane >> 2);
            float v0 = acc[mt][nt][0] + b0v, v1 = acc[mt][nt][1] + b1v;
            float v2 = acc[mt][nt][2] + b0v, v3 = acc[mt][nt][3] + b1v;
            if (EPI == 1) {
                v0 = softplusf(v0); v1 = softplusf(v1);
                v2 = softplusf(v2); v3 = softplusf(v3);
            }
            if (EPI == 0) {
                float* C = (float*)Cv;
                *reinterpret_cast<float2*>(&C[(size_t)row * Cstride + col])       = make_float2(v0, v1);
                *reinterpret_cast<float2*>(&C[(size_t)(row + 8) * Cstride + col]) = make_float2(v2, v3);
            } else {
                __half* C = (__half*)Cv;
                *reinterpret_cast<__half2*>(&C[(size_t)row * Cstride + col])       = __floats2half2_rn(v0, v1);
                *reinterpret_cast<__half2*>(&C[(size_t)(row + 8) * Cstride + col]) = __floats2half2_rn(v2, v3);
            }
        }
    }
}

// ---------------- B/C projection via mma ----------------
#define BCAST (128 * 128)
#define BCSTG (BCAST + 32 * 128)
#define BCSMEM (3 * BCSTG)
__global__ void __launch_bounds__(256, 1) bc_mma(
    const __half* __restrict__ A, const __half* __restrict__ W,
    const float* __restrict__ Bb, const float* __restrict__ Cb)
{
    extern __shared__ char smraw[];
    const uint32_t sbase = smem_u32(smraw);
    const int tid  = threadIdx.x;
    const int wid  = tid >> 5;
    const int lane = tid & 31;
    const int bm0  = blockIdx.x * 128;
    const size_t lda = (size_t)INNER * 2;

    auto load_stage = [&](int kt, int s) {
        const uint32_t sa = sbase + s * BCSTG;
        const uint32_t sb = sa + BCAST;
#pragma unroll
        for (int i = 0; i < 4; ++i) {
            int idx = tid + i * 256, r = idx >> 3, c = idx & 7;
            cp_async16(sa + r * 128 + ((c ^ (r & 7)) << 4),
                       (const char*)A + (size_t)(bm0 + r) * lda + (size_t)kt * 128 + c * 16);
        }
        {
            int r = tid >> 3, c = tid & 7;
            cp_async16(sb + r * 128 + ((c ^ (r & 7)) << 4),
                       (const char*)W + (size_t)r * lda + (size_t)kt * 128 + c * 16);
        }
    };

    float acc[4][4];
#pragma unroll
    for (int nt = 0; nt < 4; ++nt)
#pragma unroll
        for (int q = 0; q < 4; ++q) acc[nt][q] = 0.f;

    load_stage(0, 0); CP_COMMIT();
    load_stage(1, 1); CP_COMMIT();

    const int aRow = wid * 16 + ((lane >> 3) & 1) * 8 + (lane & 7);
    const int bRow = ((lane >> 4) & 1) * 8 + (lane & 7);
    const int swzX = (lane & 7) << 4;
    const int aKs  = (lane >> 4) << 4;
    const int bKs  = ((lane >> 3) & 1) << 4;

    const int KT = INNER / 64;
    for (int kt = 0; kt < KT; ++kt) {
        const int s = kt % 3;
        CP_WAIT1();
        __syncthreads();
        if (kt + 2 < KT) { load_stage(kt + 2, (kt + 2) % 3); CP_COMMIT(); }

        const uint32_t Ab = sbase + s * BCSTG;
        const uint32_t Bb_ = Ab + BCAST;
#pragma unroll
        for (int ks = 0; ks < 4; ++ks) {
            const int swA = (ks * 32 + aKs) ^ swzX;
            const int swB = (ks * 32 + bKs) ^ swzX;
            uint32_t a[4], b[2][4];
            ldm_x4(a, Ab + aRow * 128 + swA);
#pragma unroll
            for (int np = 0; np < 2; ++np) ldm_x4(b[np], Bb_ + (bRow + np * 16) * 128 + swB);
#pragma unroll
            for (int nt = 0; nt < 4; ++nt)
                mma16816h(acc[nt], a, &b[nt >> 1][(nt & 1) * 2]);
        }
    }

#pragma unroll
    for (int nt = 0; nt < 4; ++nt) {
        const int col = nt * 8 + (lane & 3) * 2;
        const int row = bm0 + wid * 16 + (lane >> 2);
        if (col < 16) {
            const float c0 = Bb[col], c1 = Bb[col + 1];
            *reinterpret_cast<float2*>(&g_Bm[(size_t)row * 16 + col]) =
                make_float2(acc[nt][0] + c0, acc[nt][1] + c1);
            *reinterpret_cast<float2*>(&g_Bm[(size_t)(row + 8) * 16 + col]) =
                make_float2(acc[nt][2] + c0, acc[nt][3] + c1);
        } else {
            const int cc = col - 16;
            const float c0 = Cb[cc], c1 = Cb[cc + 1];
            *reinterpret_cast<float2*>(&g_Cm[(size_t)row * 16 + cc]) =
                make_float2(acc[nt][0] + c0, acc[nt][1] + c1);
            *reinterpret_cast<float2*>(&g_Cm[(size_t)(row + 8) * 16 + cc]) =
                make_float2(acc[nt][2] + c0, acc[nt][3] + c1);
        }
    }
}

// ---------------- conversion kernels ----------------
__global__ void __launch_bounds__(256) cvt1h_kernel(
    const float* __restrict__ in, __half* __restrict__ o0, size_t n4)
{
    for (size_t i = (size_t)blockIdx.x * 256 + threadIdx.x; i < n4; i += (size_t)gridDim.x * 256) {
        float4 v = reinterpret_cast<const float4*>(in)[i];
        ((ushort4*)o0)[i] = make_ushort4(
            __half_as_ushort(__float2half_rn(v.x)), __half_as_ushort(__float2half_rn(v.y)),
            __half_as_ushort(__float2half_rn(v.z)), __half_as_ushort(__float2half_rn(v.w)));
    }
}
__global__ void __launch_bounds__(256) cvtw_kernel(
    const float* __restrict__ w1, const float* __restrict__ w2, const float* __restrict__ w3,
    const float* __restrict__ w4, const float* __restrict__ w5,
    __half* __restrict__ o1, __half* __restrict__ o2, __half* __restrict__ o3,
    __half* __restrict__ o4)
{
    const size_t n1 = (size_t)2 * INNER * HID / 4;
    const size_t n2 = (size_t)INNER * INNER / 4;
    const size_t n3 = (size_t)HID * INNER / 4;
    const size_t n4 = (size_t)16 * INNER / 4;
    const size_t n5 = (size_t)16 * INNER / 4;
    for (size_t i = (size_t)blockIdx.x * 256 + threadIdx.x; i < n1 + n2 + n3 + n4 + n5;
         i += (size_t)gridDim.x * 256) {
        const float* src; __half* dst; size_t j;
        if (i < n1)                 { src = w1; dst = o1; j = i; }
        else if (i < n1 + n2)       { src = w2; dst = o2; j = i - n1; }
        else if (i < n1 + n2 + n3)  { src = w3; dst = o3; j = i - n1 - n2; }
        else if (i < n1 + n2 + n3 + n4) { src = w4; dst = o4; j = i - n1 - n2 - n3; }
        else { src = w5; dst = o4 + (size_t)16 * INNER / 4 * 4; j = i - n1 - n2 - n3 - n4; }
        float4 v = reinterpret_cast<const float4*>(src)[j];
        ((ushort4*)dst)[j] = make_ushort4(
            __half_as_ushort(__float2half_rn(v.x)), __half_as_ushort(__float2half_rn(v.y)),
            __half_as_ushort(__float2half_rn(v.z)), __half_as_ushort(__float2half_rn(v.w)));
    }
}

// ---------------- causal depthwise conv (K=4) + SiLU, half2 vectorized ----------------
__global__ void __launch_bounds__(128) conv_silu_kernel(
    const float* __restrict__ conv_w, const float* __restrict__ conv_b)
{
    const int d2 = blockIdx.x * 128 + threadIdx.x;
    const int l0 = blockIdx.y * 128;
    const int b  = blockIdx.z;
    const int d  = d2 * 2;
    const float2 w0 = make_float2(conv_w[d * 4 + 0], conv_w[d * 4 + 4]);
    const float2 w1 = make_float2(conv_w[d * 4 + 1], conv_w[d * 4 + 5]);
    const float2 w2 = make_float2(conv_w[d * 4 + 2], conv_w[d * 4 + 6]);
    const float2 w3 = make_float2(conv_w[d * 4 + 3], conv_w[d * 4 + 7]);
    const float2 cb = make_float2(conv_b[d], conv_b[d + 1]);
    const __half2* xp = (const __half2*)g_xph + (size_t)(b * LEN) * (INNER / 2) + d2;
    float2 m3, m2, m1;
    if (l0 == 0) { m3 = m2 = m1 = make_float2(0.f, 0.f); }
    else {
        m3 = __half22float2(xp[(size_t)(l0 - 3) * (INNER / 2)]);
        m2 = __half22float2(xp[(size_t)(l0 - 2) * (INNER / 2)]);
        m1 = __half22float2(xp[(size_t)(l0 - 1) * (INNER / 2)]);
    }
    __half2* xh = (__half2*)g_xch + (size_t)(b * LEN + l0) * (INNER / 2) + d2;
#pragma unroll 4
    for (int i = 0; i < 128; ++i) {
        float2 cur = __half22float2(xp[(size_t)(l0 + i) * (INNER / 2)]);
        float vx = w0.x * m3.x + w1.x * m2.x + w2.x * m1.x + w3.x * cur.x + cb.x;
        float vy = w0.y * m3.y + w1.y * m2.y + w2.y * m1.y + w3.y * cur.y + cb.y;
        xh[(size_t)i * (INNER / 2)] = __floats2half2_rn(siluf(vx), siluf(vy));
        m3 = m2; m2 = m1; m1 = cur;
    }
}

// ---------------- chunked selective scan ----------------
__global__ void __launch_bounds__(128) scanA_kernel(const float* __restrict__ A_log)
{
    __shared__ uint32_t sBh[LC * 8];
    const int d = blockIdx.x * 128 + threadIdx.x;
    const int c = blockIdx.y;
    const int b = blockIdx.z;
    const int base_l = c * LC;
    for (int i = threadIdx.x; i < LC * 8; i += 128) {
        const float2 v = *reinterpret_cast<const float2*>(
            &g_Bm[(size_t)(b * LEN + base_l) * STATE + 2 * i]);
        __half2 hh = __floats2half2_rn(v.x, v.y);
        sBh[i] = *reinterpret_cast<uint32_t*>(&hh);
    }
    __syncthreads();
    __half2 Ar2[8];
#pragma unroll
    for (int i = 0; i < 8; i++)
        Ar2[i] = __floats2half2_rn(-expf(A_log[d * STATE + 2 * i]) * LOG2E,
                                   -expf(A_log[d * STATE + 2 * i + 1]) * LOG2E);
    __half2 h2[8];
#pragma unroll
    for (int i = 0; i < 8; i++) h2[i] = __floats2half2_rn(0.f, 0.f);
    float dtsum = 0.f;
    const __half* dtp = g_dth + (size_t)(b * LEN + base_l) * INNER + d;
    const __half* xcp = g_xch + (size_t)(b * LEN + base_l) * INNER + d;
    for (int l = 0; l < LC; ++l) {
        __half dtv = dtp[(size_t)l * INNER];
        __half xv  = xcp[(size_t)l * INNER];
        dtsum += __half2float(dtv);
        __half2 dt2  = __half2half2(dtv);
        __half2 dtx2 = __half2half2(__hmul(dtv, xv));
#pragma unroll
        for (int i = 0; i < 8; i++) {
            __half2 dA  = hexp2_x2(__hmul2(dt2, Ar2[i]));
            __half2 inc = __hmul2(*reinterpret_cast<const __half2*>(&sBh[l * 8 + i]), dtx2);
            h2[i] = __hfma2(dA, h2[i], inc);
        }
    }
    size_t sb2 = (size_t)(b * NC + c) * 8 * INNER + d;
#pragma unroll
    for (int i = 0; i < 8; i++)
        g_S2[sb2 + (size_t)i * INNER] = *reinterpret_cast<uint32_t*>(&h2[i]);
    g_dts[(size_t)(b * NC + c) * INNER + d] = dtsum;
}

__global__ void __launch_bounds__(256) scanB_kernel(const float* __restrict__ A_log)
{
    int g = blockIdx.x * 256 + threadIdx.x;
    int b = g / INNER;
    int d = g - b * INNER;
    float Ar[STATE];
#pragma unroll
    for (int s = 0; s < STATE; s++) Ar[s] = -expf(A_log[d * STATE + s]);
    float h[STATE];
#pragma unroll
    for (int s = 0; s < STATE; s++) h[s] = 0.f;
    for (int c = 0; c < NC; ++c) {
        size_t hb = (size_t)(b * NC + c) * STATE * INNER + d;
#pragma unroll
        for (int s = 0; s < STATE; s++) g_H0[hb + (size_t)s * INNER] = h[s];
        float ds = g_dts[(size_t)(b * NC + c) * INNER + d];
        size_t sb2 = (size_t)(b * NC + c) * 8 * INNER + d;
#pragma unroll
        for (int i = 0; i < 8; i++) {
            uint32_t sv = g_S2[sb2 + (size_t)i * INNER];
            float2 svf = __half22float2(*reinterpret_cast<__half2*>(&sv));
            h[2 * i]     = __expf(Ar[2 * i] * ds)     * h[2 * i]     + svf.x;
            h[2 * i + 1] = __expf(Ar[2 * i + 1] * ds) * h[2 * i + 1] + svf.y;
        }
    }
}

__global__ void __launch_bounds__(128) scanC_kernel(
    const float* __restrict__ A_log, const float* __restrict__ Dv)
{
    __shared__ uint32_t sBh[LC * 8];
    __shared__ uint32_t sCh[LC * 8];
    const int d = blockIdx.x * 128 + threadIdx.x;
    const int c = blockIdx.y;
    const int b = blockIdx.z;
    const int base_l = c * LC;
    for (int i = threadIdx.x; i < LC * 8; i += 128) {
        const float2 vb = *reinterpret_cast<const float2*>(
            &g_Bm[(size_t)(b * LEN + base_l) * STATE + 2 * i]);
        const float2 vc = *reinterpret_cast<const float2*>(
            &g_Cm[(size_t)(b * LEN + base_l) * STATE + 2 * i]);
        __half2 hb = __floats2half2_rn(vb.x, vb.y);
        __half2 hc = __floats2half2_rn(vc.x, vc.y);
        sBh[i] = *reinterpret_cast<uint32_t*>(&hb);
        sCh[i] = *reinterpret_cast<uint32_t*>(&hc);
    }
    __syncthreads();
    __half2 Ar2[8];
#pragma unroll
    for (int i = 0; i < 8; i++)
        Ar2[i] = __floats2half2_rn(-expf(A_log[d * STATE + 2 * i]) * LOG2E,
                                   -expf(A_log[d * STATE + 2 * i + 1]) * LOG2E);
    const float Dd = Dv[d];
    __half2 h2[8];
    size_t ob = (size_t)(b * NC + c) * STATE * INNER + d;
#pragma unroll
    for (int i = 0; i < 8; i++)
        h2[i] = __floats2half2_rn(g_H0[ob + (size_t)(2 * i) * INNER],
                                  g_H0[ob + (size_t)(2 * i + 1) * INNER]);
    const __half* dtp = g_dth + (size_t)(b * LEN + base_l) * INNER + d;
    const __half* xcp = g_xch + (size_t)(b * LEN + base_l) * INNER + d;
    const __half* zp  = g_zh  + (size_t)(b * LEN + base_l) * INNER + d;
    __half* y0p = g_y0h + (size_t)(b * LEN + base_l) * INNER + d;
    for (int l = 0; l < LC; ++l) {
        __half dtv = dtp[(size_t)l * INNER];
        __half xv  = xcp[(size_t)l * INNER];
        float zv   = __half2float(zp[(size_t)l * INNER]);
        __half2 dt2  = __half2half2(dtv);
        __half2 dtx2 = __half2half2(__hmul(dtv, xv));
        __half2 acc2 = __floats2half2_rn(0.f, 0.f);
#pragma unroll
        for (int i = 0; i < 8; i++) {
            __half2 dA  = hexp2_x2(__hmul2(dt2, Ar2[i]));
            __half2 inc = __hmul2(*reinterpret_cast<const __half2*>(&sBh[l * 8 + i]), dtx2);
            h2[i] = __hfma2(dA, h2[i], inc);
            acc2  = __hfma2(*reinterpret_cast<const __half2*>(&sCh[l * 8 + i]), h2[i], acc2);
        }
        float acc = __low2float(acc2) + __high2float(acc2) + Dd * __half2float(xv);
        y0p[(size_t)l * INNER] = __float2half_rn(acc * siluf(zv));
    }
}

// ---------------- launch ----------------
extern "C" void kernel_launch(void* const* d_in, const int* in_sizes, int n_in,
                              void* d_out, int out_size)
{
    const float* x      = (const float*)d_in[0];
    const float* in_w   = (const float*)d_in[1];
    const float* in_b   = (const float*)d_in[2];
    const float* conv_w = (const float*)d_in[3];
    const float* conv_b = (const float*)d_in[4];
    const float* dt_w   = (const float*)d_in[5];
    const float* dt_b   = (const float*)d_in[6];
    const float* A_log  = (const float*)d_in[7];
    const float* B_w    = (const float*)d_in[8];
    const float* B_b    = (const float*)d_in[9];
    const float* C_w    = (const float*)d_in[10];
    const float* C_b    = (const float*)d_in[11];
    const float* Dv     = (const float*)d_in[12];
    const float* out_w  = (const float*)d_in[13];
    const float* out_b  = (const float*)d_in[14];
    float* out = (float*)d_out;

    __half *x0h, *wh, *dtwh, *xch, *y0h, *owh, *wbch, *zh, *dth, *xph;
    cudaGetSymbolAddress((void**)&xph, g_xph);
    cudaGetSymbolAddress((void**)&x0h, g_x0h);
    cudaGetSymbolAddress((void**)&wh, g_wh);
    cudaGetSymbolAddress((void**)&dtwh, g_dtwh);
    cudaGetSymbolAddress((void**)&xch, g_xch);
    cudaGetSymbolAddress((void**)&y0h, g_y0h);
    cudaGetSymbolAddress((void**)&owh, g_owh);
    cudaGetSymbolAddress((void**)&wbch, g_wbch);
    cudaGetSymbolAddress((void**)&zh, g_zh);
    cudaGetSymbolAddress((void**)&dth, g_dth);

    cudaFuncSetAttribute(gemm_mma<1>, cudaFuncAttributeMaxDynamicSharedMemorySize, GSMEM);
    cudaFuncSetAttribute(gemm_mma<0>, cudaFuncAttributeMaxDynamicSharedMemorySize, GSMEM);
    cudaFuncSetAttribute(gemm_mma<2>, cudaFuncAttributeMaxDynamicSharedMemorySize, GSMEM);
    cudaFuncSetAttribute(bc_mma, cudaFuncAttributeMaxDynamicSharedMemorySize, BCSMEM);

    static cudaStream_t s1 = nullptr;
    static cudaEvent_t evA = nullptr, evZ = nullptr;
    if (s1 == nullptr) {
        cudaStreamCreateWithFlags(&s1, cudaStreamNonBlocking);
        cudaEventCreateWithFlags(&evA, cudaEventDisableTiming);
        cudaEventCreateWithFlags(&evZ, cudaEventDisableTiming);
    }

    // 0) fp16 conversions
    cvt1h_kernel<<<2048, 256>>>(x, x0h, (size_t)M_TOT * HID / 4);
    cvtw_kernel<<<2048, 256>>>(in_w, dt_w, out_w, B_w, C_w, wh, dtwh, owh, wbch);
    cudaEventRecord(evA, 0);

    // fork: z half of in-proj on s1
    cudaStreamWaitEvent(s1, evA, 0);
    gemm_mma<2><<<dim3(INNER / GBN, M_TOT / GBM), 256, GSMEM, s1>>>(
        x0h, wh + (size_t)INNER * HID, in_b + INNER, zh, INNER, HID);
    cudaEventRecord(evZ, s1);

    // 1) in-proj x_part half -> fp16                       (16384 x 2048 x 1024)
    gemm_mma<2><<<dim3(INNER / GBN, M_TOT / GBM), 256, GSMEM>>>(
        x0h, wh, in_b, xph, INNER, HID);

    // 2) conv + silu (half2 vectorized)
    conv_silu_kernel<<<dim3(INNER / 256, LEN / 128, B_SZ), 128>>>(conv_w, conv_b);

    // 3) B/C projections via mma (N = 32)
    bc_mma<<<M_TOT / 128, 256, BCSMEM>>>(xch, wbch, B_b, C_b);

    // 4) dt = softplus(xconv @ dt_w^T + dt_b) -> fp16      (16384 x 2048 x 2048)
    gemm_mma<1><<<dim3(INNER / GBN, M_TOT / GBM), 256, GSMEM>>>(
        xch, dtwh, dt_b, dth, INNER, INNER);

    // 5) chunked selective scan + gating
    scanA_kernel<<<dim3(INNER / 128, NC, B_SZ), 128>>>(A_log);
    scanB_kernel<<<(B_SZ * INNER) / 256, 256>>>(A_log);
    cudaStreamWaitEvent(0, evZ, 0);
    scanC_kernel<<<dim3(INNER / 128, NC, B_SZ), 128>>>(A_log, Dv);

    // 6) out-proj: out = y @ out_w^T + out_b               (16384 x 1024 x 2048)
    gemm_mma<0><<<dim3(HID / GBN, M_TOT / GBM), 256, GSMEM>>>(
        y0h, owh, out_b, out, HID, INNER);
}

// round 14
// speedup vs baseline: 5.8497x; 1.0010x over previous
#include <cuda_runtime.h>
#include <cuda_fp16.h>
#include <math.h>
#include <stdint.h>

#define B_SZ   4
#define LEN    4096
#define HID    1024
#define STATE  16
#define INNER  2048
#define M_TOT  (B_SZ * LEN)
#define NC     16
#define LC     256
#define LOG2E  1.4426950408889634f

// ---------------- scratch ----------------
__device__ __align__(1024) float    g_Bm  [(size_t)M_TOT * STATE];
__device__ __align__(1024) float    g_Cm  [(size_t)M_TOT * STATE];
__device__ __align__(1024) uint32_t g_S2  [(size_t)B_SZ * NC * 8 * INNER];
__device__ __align__(1024) float    g_dts [(size_t)B_SZ * NC * INNER];
__device__ __align__(1024) float    g_H0  [(size_t)B_SZ * NC * STATE * INNER];
__device__ __align__(1024) __half   g_xph [(size_t)M_TOT * INNER];
__device__ __align__(1024) __half   g_zh  [(size_t)M_TOT * INNER];
__device__ __align__(1024) __half   g_dth [(size_t)M_TOT * INNER];
__device__ __align__(1024) __half   g_x0h [(size_t)M_TOT * HID];
__device__ __align__(1024) __half   g_wh  [(size_t)2 * INNER * HID];
__device__ __align__(1024) __half   g_dtwh[(size_t)INNER * INNER];
__device__ __align__(1024) __half   g_xch [(size_t)M_TOT * INNER];
__device__ __align__(1024) __half   g_y0h [(size_t)M_TOT * INNER];
__device__ __align__(1024) __half   g_owh [(size_t)HID * INNER];
__device__ __align__(1024) __half   g_wbch[32 * INNER];

// ---------------- PTX helpers ----------------
__device__ __forceinline__ uint32_t smem_u32(const void* p) {
    uint32_t a;
    asm("{ .reg .u64 t; cvta.to.shared.u64 t, %1; cvt.u32.u64 %0, t; }" : "=r"(a) : "l"(p));
    return a;
}
__device__ __forceinline__ void cp_async16(uint32_t dst, const void* src) {
    asm volatile("cp.async.cg.shared.global [%0], [%1], 16;" :: "r"(dst), "l"(src) : "memory");
}
#define CP_COMMIT() asm volatile("cp.async.commit_group;" ::: "memory")
#define CP_WAIT1()  asm volatile("cp.async.wait_group 1;" ::: "memory")

__device__ __forceinline__ void ldm_x4(uint32_t* r, uint32_t addr) {
    asm volatile("ldmatrix.sync.aligned.m8n8.x4.shared.b16 {%0,%1,%2,%3}, [%4];"
        : "=r"(r[0]), "=r"(r[1]), "=r"(r[2]), "=r"(r[3]) : "r"(addr));
}
__device__ __forceinline__ void mma16816h(float* d, const uint32_t* a, const uint32_t* b) {
    asm volatile("mma.sync.aligned.m16n8k16.row.col.f32.f16.f16.f32 "
        "{%0,%1,%2,%3}, {%4,%5,%6,%7}, {%8,%9}, {%0,%1,%2,%3};"
        : "+f"(d[0]), "+f"(d[1]), "+f"(d[2]), "+f"(d[3])
        : "r"(a[0]), "r"(a[1]), "r"(a[2]), "r"(a[3]), "r"(b[0]), "r"(b[1]));
}
__device__ __forceinline__ __half2 hexp2_x2(__half2 x) {
    __half2 r;
    asm("ex2.approx.f16x2 %0, %1;" : "=r"(*(uint32_t*)&r) : "r"(*(uint32_t*)&x));
    return r;
}
__device__ __forceinline__ float softplusf(float v) { return v > 20.f ? v : log1pf(__expf(v)); }
__device__ __forceinline__ float siluf(float v)     { return v / (1.f + __expf(-v)); }

// ---------------- fp16 mma.sync GEMM, 2 CTAs/SM tiling ----------------
#define GBM 128
#define GBN 128
#define GAST (GBM * 128)
#define GSTG (GAST + GBN * 128)
#define GSMEM (3 * GSTG)

template <int EPI>   // 0 = fp32 bias, 1 = fp16 softplus, 2 = fp16 bias
__global__ void __launch_bounds__(256, 2) gemm_mma(
    const __half* __restrict__ Ap, const __half* __restrict__ Bp,
    const float* __restrict__ bias, void* __restrict__ Cv, int Cstride, int K)
{
    extern __shared__ char smraw[];
    const uint32_t sbase = smem_u32(smraw);
    const int tid  = threadIdx.x;
    const int wid  = tid >> 5;
    const int lane = tid & 31;
    const int bm0  = blockIdx.y * GBM;
    const int bn0  = blockIdx.x * GBN;

    const int KTT = K >> 6;
    const size_t lda = (size_t)K * 2;

    auto load_stage = [&](int kt, int s) {
        const uint32_t sa = sbase + s * GSTG;
        const uint32_t sb = sa + GAST;
#pragma unroll
        for (int i = 0; i < 4; ++i) {
            int idx = tid + i * 256, r = idx >> 3, c = idx & 7;
            cp_async16(sa + r * 128 + ((c ^ (r & 7)) << 4),
                       (const char*)Ap + (size_t)(bm0 + r) * lda + (size_t)kt * 128 + c * 16);
        }
#pragma unroll
        for (int i = 0; i < 4; ++i) {
            int idx = tid + i * 256, r = idx >> 3, c = idx & 7;
            cp_async16(sb + r * 128 + ((c ^ (r & 7)) << 4),
                       (const char*)Bp + (size_t)(bn0 + r) * lda + (size_t)kt * 128 + c * 16);
        }
    };

    float acc[4][4][4];
#pragma unroll
    for (int mt = 0; mt < 4; ++mt)
#pragma unroll
        for (int nt = 0; nt < 4; ++nt)
#pragma unroll
            for (int q = 0; q < 4; ++q) acc[mt][nt][q] = 0.f;

    load_stage(0, 0); CP_COMMIT();
    load_stage(1, 1); CP_COMMIT();

    const int wm0 = (wid >> 2) * 64;
    const int wn0 = (wid & 3) * 32;
    const int aRow = wm0 + ((lane >> 3) & 1) * 8 + (lane & 7);
    const int bRow = wn0 + ((lane >> 4) & 1) * 8 + (lane & 7);
    const int swzX = (lane & 7) << 4;
    const int aKs  = (lane >> 4) << 4;
    const int bKs  = ((lane >> 3) & 1) << 4;

    for (int kt = 0; kt < KTT; ++kt) {
        const int s = kt % 3;
        CP_WAIT1();
        __syncthreads();
        if (kt + 2 < KTT) { load_stage(kt + 2, (kt + 2) % 3); CP_COMMIT(); }

        const uint32_t Ab = sbase + s * GSTG;
        const uint32_t Bb = Ab + GAST;
#pragma unroll
        for (int ks = 0; ks < 4; ++ks) {
            const int swA = (ks * 32 + aKs) ^ swzX;
            const int swB = (ks * 32 + bKs) ^ swzX;
            uint32_t a[4][4], b[2][4];
#pragma unroll
            for (int mt = 0; mt < 4; ++mt) ldm_x4(a[mt], Ab + (aRow + mt * 16) * 128 + swA);
#pragma unroll
            for (int np = 0; np < 2; ++np) ldm_x4(b[np], Bb + (bRow + np * 16) * 128 + swB);
#pragma unroll
            for (int mt = 0; mt < 4; ++mt)
#pragma unroll
                for (int nt = 0; nt < 4; ++nt)
                    mma16816h(acc[mt][nt], a[mt], &b[nt >> 1][(nt & 1) * 2]);
        }
    }

#pragma unroll
    for (int nt = 0; nt < 4; ++nt) {
        const int col = bn0 + wn0 + nt * 8 + (lane & 3) * 2;
        const float b0v = bias[col], b1v = bias[col + 1];
#pragma unroll
        for (int mt = 0; mt < 4; ++mt) {
            const int row = bm0 + wm0 + mt * 16 + (lane >> 2);
            float v0 = acc[mt][nt][0] + b0v, v1 = acc[mt][nt][1] + b1v;
            float v2 = acc[mt][nt][2] + b0v, v3 = acc[mt][nt][3] + b1v;
            if (EPI == 1) {
                v0 = softplusf(v0); v1 = softplusf(v1);
                v2 = softplusf(v2); v3 = softplusf(v3);
            }
            if (EPI == 0) {
                float* C = (float*)Cv;
                *reinterpret_cast<float2*>(&C[(size_t)row * Cstride + col])       = make_float2(v0, v1);
                *reinterpret_cast<float2*>(&C[(size_t)(row + 8) * Cstride + col]) = make_float2(v2, v3);
            } else {
                __half* C = (__half*)Cv;
                *reinterpret_cast<__half2*>(&C[(size_t)row * Cstride + col])       = __floats2half2_rn(v0, v1);
                *reinterpret_cast<__half2*>(&C[(size_t)(row + 8) * Cstride + col]) = __floats2half2_rn(v2, v3);
            }
        }
    }
}

// ---------------- B/C projection via mma: BM=64, 128 threads, 36KB (co-resides with dt GEMM) ----------------
#define BCAST (64 * 128)
#define BCSTG (BCAST + 32 * 128)
#define BCSMEM (3 * BCSTG)
__global__ void __launch_bounds__(128, 1) bc_mma(
    const __half* __restrict__ A, const __half* __restrict__ W,
    const float* __restrict__ Bb, const float* __restrict__ Cb)
{
    extern __shared__ char smraw[];
    const uint32_t sbase = smem_u32(smraw);
    const int tid  = threadIdx.x;
    const int wid  = tid >> 5;       // 0..3
    const int lane = tid & 31;
    const int bm0  = blockIdx.x * 64;
    const size_t lda = (size_t)INNER * 2;

    auto load_stage = [&](int kt, int s) {
        const uint32_t sa = sbase + s * BCSTG;
        const uint32_t sb = sa + BCAST;
#pragma unroll
        for (int i = 0; i < 4; ++i) {                     // A: 64 rows x 8 chunks = 512
            int idx = tid + i * 128, r = idx >> 3, c = idx & 7;
            cp_async16(sa + r * 128 + ((c ^ (r & 7)) << 4),
                       (const char*)A + (size_t)(bm0 + r) * lda + (size_t)kt * 128 + c * 16);
        }
#pragma unroll
        for (int i = 0; i < 2; ++i) {                     // W: 32 rows x 8 chunks = 256
            int idx = tid + i * 128, r = idx >> 3, c = idx & 7;
            cp_async16(sb + r * 128 + ((c ^ (r & 7)) << 4),
                       (const char*)W + (size_t)r * lda + (size_t)kt * 128 + c * 16);
        }
    };

    float acc[4][4];
#pragma unroll
    for (int nt = 0; nt < 4; ++nt)
#pragma unroll
        for (int q = 0; q < 4; ++q) acc[nt][q] = 0.f;

    load_stage(0, 0); CP_COMMIT();
    load_stage(1, 1); CP_COMMIT();

    const int aRow = wid * 16 + ((lane >> 3) & 1) * 8 + (lane & 7);
    const int bRow = ((lane >> 4) & 1) * 8 + (lane & 7);
    const int swzX = (lane & 7) << 4;
    const int aKs  = (lane >> 4) << 4;
    const int bKs  = ((lane >> 3) & 1) << 4;

    const int KT = INNER / 64;
    for (int kt = 0; kt < KT; ++kt) {
        const int s = kt % 3;
        CP_WAIT1();
        __syncthreads();
        if (kt + 2 < KT) { load_stage(kt + 2, (kt + 2) % 3); CP_COMMIT(); }

        const uint32_t Ab = sbase + s * BCSTG;
        const uint32_t Bb_ = Ab + BCAST;
#pragma unroll
        for (int ks = 0; ks < 4; ++ks) {
            const int swA = (ks * 32 + aKs) ^ swzX;
            const int swB = (ks * 32 + bKs) ^ swzX;
            uint32_t a[4], b[2][4];
            ldm_x4(a, Ab + aRow * 128 + swA);
#pragma unroll
            for (int np = 0; np < 2; ++np) ldm_x4(b[np], Bb_ + (bRow + np * 16) * 128 + swB);
#pragma unroll
            for (int nt = 0; nt < 4; ++nt)
                mma16816h(acc[nt], a, &b[nt >> 1][(nt & 1) * 2]);
        }
    }

#pragma unroll
    for (int nt = 0; nt < 4; ++nt) {
        const int col = nt * 8 + (lane & 3) * 2;
        const int row = bm0 + wid * 16 + (lane >> 2);
        if (col < 16) {
            const float c0 = Bb[col], c1 = Bb[col + 1];
            *reinterpret_cast<float2*>(&g_Bm[(size_t)row * 16 + col]) =
                make_float2(acc[nt][0] + c0, acc[nt][1] + c1);
            *reinterpret_cast<float2*>(&g_Bm[(size_t)(row + 8) * 16 + col]) =
                make_float2(acc[nt][2] + c0, acc[nt][3] + c1);
        } else {
            const int cc = col - 16;
            const float c0 = Cb[cc], c1 = Cb[cc + 1];
            *reinterpret_cast<float2*>(&g_Cm[(size_t)row * 16 + cc]) =
                make_float2(acc[nt][0] + c0, acc[nt][1] + c1);
            *reinterpret_cast<float2*>(&g_Cm[(size_t)(row + 8) * 16 + cc]) =
                make_float2(acc[nt][2] + c0, acc[nt][3] + c1);
        }
    }
}

// ---------------- conversion kernels ----------------
__global__ void __launch_bounds__(256) cvt1h_kernel(
    const float* __restrict__ in, __half* __restrict__ o0, size_t n4)
{
    for (size_t i = (size_t)blockIdx.x * 256 + threadIdx.x; i < n4; i += (size_t)gridDim.x * 256) {
        float4 v = reinterpret_cast<const float4*>(in)[i];
        ((ushort4*)o0)[i] = make_ushort4(
            __half_as_ushort(__float2half_rn(v.x)), __half_as_ushort(__float2half_rn(v.y)),
            __half_as_ushort(__float2half_rn(v.z)), __half_as_ushort(__float2half_rn(v.w)));
    }
}
__global__ void __launch_bounds__(256) cvtw_kernel(
    const float* __restrict__ w1, const float* __restrict__ w2, const float* __restrict__ w3,
    const float* __restrict__ w4, const float* __restrict__ w5,
    __half* __restrict__ o1, __half* __restrict__ o2, __half* __restrict__ o3,
    __half* __restrict__ o4)
{
    const size_t n1 = (size_t)2 * INNER * HID / 4;
    const size_t n2 = (size_t)INNER * INNER / 4;
    const size_t n3 = (size_t)HID * INNER / 4;
    const size_t n4 = (size_t)16 * INNER / 4;
    const size_t n5 = (size_t)16 * INNER / 4;
    for (size_t i = (size_t)blockIdx.x * 256 + threadIdx.x; i < n1 + n2 + n3 + n4 + n5;
         i += (size_t)gridDim.x * 256) {
        const float* src; __half* dst; size_t j;
        if (i < n1)                 { src = w1; dst = o1; j = i; }
        else if (i < n1 + n2)       { src = w2; dst = o2; j = i - n1; }
        else if (i < n1 + n2 + n3)  { src = w3; dst = o3; j = i - n1 - n2; }
        else if (i < n1 + n2 + n3 + n4) { src = w4; dst = o4; j = i - n1 - n2 - n3; }
        else { src = w5; dst = o4 + (size_t)16 * INNER / 4 * 4; j = i - n1 - n2 - n3 - n4; }
        float4 v = reinterpret_cast<const float4*>(src)[j];
        ((ushort4*)dst)[j] = make_ushort4(
            __half_as_ushort(__float2half_rn(v.x)), __half_as_ushort(__float2half_rn(v.y)),
            __half_as_ushort(__float2half_rn(v.z)), __half_as_ushort(__float2half_rn(v.w)));
    }
}

// ---------------- causal depthwise conv (K=4) + SiLU, half2 vectorized ----------------
__global__ void __launch_bounds__(128) conv_silu_kernel(
    const float* __restrict__ conv_w, const float* __restrict__ conv_b)
{
    const int d2 = blockIdx.x * 128 + threadIdx.x;
    const int l0 = blockIdx.y * 128;
    const int b  = blockIdx.z;
    const int d  = d2 * 2;
    const float2 w0 = make_float2(conv_w[d * 4 + 0], conv_w[d * 4 + 4]);
    const float2 w1 = make_float2(conv_w[d * 4 + 1], conv_w[d * 4 + 5]);
    const float2 w2 = make_float2(conv_w[d * 4 + 2], conv_w[d * 4 + 6]);
    const float2 w3 = make_float2(conv_w[d * 4 + 3], conv_w[d * 4 + 7]);
    const float2 cb = make_float2(conv_b[d], conv_b[d + 1]);
    const __half2* xp = (const __half2*)g_xph + (size_t)(b * LEN) * (INNER / 2) + d2;
    float2 m3, m2, m1;
    if (l0 == 0) { m3 = m2 = m1 = make_float2(0.f, 0.f); }
    else {
        m3 = __half22float2(xp[(size_t)(l0 - 3) * (INNER / 2)]);
        m2 = __half22float2(xp[(size_t)(l0 - 2) * (INNER / 2)]);
        m1 = __half22float2(xp[(size_t)(l0 - 1) * (INNER / 2)]);
    }
    __half2* xh = (__half2*)g_xch + (size_t)(b * LEN + l0) * (INNER / 2) + d2;
#pragma unroll 4
    for (int i = 0; i < 128; ++i) {
        float2 cur = __half22float2(xp[(size_t)(l0 + i) * (INNER / 2)]);
        float vx = w0.x * m3.x + w1.x * m2.x + w2.x * m1.x + w3.x * cur.x + cb.x;
        float vy = w0.y * m3.y + w1.y * m2.y + w2.y * m1.y + w3.y * cur.y + cb.y;
        xh[(size_t)i * (INNER / 2)] = __floats2half2_rn(siluf(vx), siluf(vy));
        m3 = m2; m2 = m1; m1 = cur;
    }
}

// ---------------- chunked selective scan ----------------
__global__ void __launch_bounds__(128) scanA_kernel(const float* __restrict__ A_log)
{
    __shared__ uint32_t sBh[LC * 8];
    const int d = blockIdx.x * 128 + threadIdx.x;
    const int c = blockIdx.y;
    const int b = blockIdx.z;
    const int base_l = c * LC;
    for (int i = threadIdx.x; i < LC * 8; i += 128) {
        const float2 v = *reinterpret_cast<const float2*>(
            &g_Bm[(size_t)(b * LEN + base_l) * STATE + 2 * i]);
        __half2 hh = __floats2half2_rn(v.x, v.y);
        sBh[i] = *reinterpret_cast<uint32_t*>(&hh);
    }
    __syncthreads();
    __half2 Ar2[8];
#pragma unroll
    for (int i = 0; i < 8; i++)
        Ar2[i] = __floats2half2_rn(-expf(A_log[d * STATE + 2 * i]) * LOG2E,
                                   -expf(A_log[d * STATE + 2 * i + 1]) * LOG2E);
    __half2 h2[8];
#pragma unroll
    for (int i = 0; i < 8; i++) h2[i] = __floats2half2_rn(0.f, 0.f);
    float dtsum = 0.f;
    const __half* dtp = g_dth + (size_t)(b * LEN + base_l) * INNER + d;
    const __half* xcp = g_xch + (size_t)(b * LEN + base_l) * INNER + d;
    for (int l = 0; l < LC; ++l) {
        __half dtv = dtp[(size_t)l * INNER];
        __half xv  = xcp[(size_t)l * INNER];
        dtsum += __half2float(dtv);
        __half2 dt2  = __half2half2(dtv);
        __half2 dtx2 = __half2half2(__hmul(dtv, xv));
#pragma unroll
        for (int i = 0; i < 8; i++) {
            __half2 dA  = hexp2_x2(__hmul2(dt2, Ar2[i]));
            __half2 inc = __hmul2(*reinterpret_cast<const __half2*>(&sBh[l * 8 + i]), dtx2);
            h2[i] = __hfma2(dA, h2[i], inc);
        }
    }
    size_t sb2 = (size_t)(b * NC + c) * 8 * INNER + d;
#pragma unroll
    for (int i = 0; i < 8; i++)
        g_S2[sb2 + (size_t)i * INNER] = *reinterpret_cast<uint32_t*>(&h2[i]);
    g_dts[(size_t)(b * NC + c) * INNER + d] = dtsum;
}

__global__ void __launch_bounds__(256) scanB_kernel(const float* __restrict__ A_log)
{
    int g = blockIdx.x * 256 + threadIdx.x;
    int b = g / INNER;
    int d = g - b * INNER;
    float Ar[STATE];
#pragma unroll
    for (int s = 0; s < STATE; s++) Ar[s] = -expf(A_log[d * STATE + s]);
    float h[STATE];
#pragma unroll
    for (int s = 0; s < STATE; s++) h[s] = 0.f;
    for (int c = 0; c < NC; ++c) {
        size_t hb = (size_t)(b * NC + c) * STATE * INNER + d;
#pragma unroll
        for (int s = 0; s < STATE; s++) g_H0[hb + (size_t)s * INNER] = h[s];
        float ds = g_dts[(size_t)(b * NC + c) * INNER + d];
        size_t sb2 = (size_t)(b * NC + c) * 8 * INNER + d;
#pragma unroll
        for (int i = 0; i < 8; i++) {
            uint32_t sv = g_S2[sb2 + (size_t)i * INNER];
            float2 svf = __half22float2(*reinterpret_cast<__half2*>(&sv));
            h[2 * i]     = __expf(Ar[2 * i] * ds)     * h[2 * i]     + svf.x;
            h[2 * i + 1] = __expf(Ar[2 * i + 1] * ds) * h[2 * i + 1] + svf.y;
        }
    }
}

__global__ void __launch_bounds__(128) scanC_kernel(
    const float* __restrict__ A_log, const float* __restrict__ Dv)
{
    __shared__ uint32_t sBh[LC * 8];
    __shared__ uint32_t sCh[LC * 8];
    const int d = blockIdx.x * 128 + threadIdx.x;
    const int c = blockIdx.y;
    const int b = blockIdx.z;
    const int base_l = c * LC;
    for (int i = threadIdx.x; i < LC * 8; i += 128) {
        const float2 vb = *reinterpret_cast<const float2*>(
            &g_Bm[(size_t)(b * LEN + base_l) * STATE + 2 * i]);
        const float2 vc = *reinterpret_cast<const float2*>(
            &g_Cm[(size_t)(b * LEN + base_l) * STATE + 2 * i]);
        __half2 hb = __floats2half2_rn(vb.x, vb.y);
        __half2 hc = __floats2half2_rn(vc.x, vc.y);
        sBh[i] = *reinterpret_cast<uint32_t*>(&hb);
        sCh[i] = *reinterpret_cast<uint32_t*>(&hc);
    }
    __syncthreads();
    __half2 Ar2[8];
#pragma unroll
    for (int i = 0; i < 8; i++)
        Ar2[i] = __floats2half2_rn(-expf(A_log[d * STATE + 2 * i]) * LOG2E,
                                   -expf(A_log[d * STATE + 2 * i + 1]) * LOG2E);
    const float Dd = Dv[d];
    __half2 h2[8];
    size_t ob = (size_t)(b * NC + c) * STATE * INNER + d;
#pragma unroll
    for (int i = 0; i < 8; i++)
        h2[i] = __floats2half2_rn(g_H0[ob + (size_t)(2 * i) * INNER],
                                  g_H0[ob + (size_t)(2 * i + 1) * INNER]);
    const __half* dtp = g_dth + (size_t)(b * LEN + base_l) * INNER + d;
    const __half* xcp = g_xch + (size_t)(b * LEN + base_l) * INNER + d;
    const __half* zp  = g_zh  + (size_t)(b * LEN + base_l) * INNER + d;
    __half* y0p = g_y0h + (size_t)(b * LEN + base_l) * INNER + d;
    for (int l = 0; l < LC; ++l) {
        __half dtv = dtp[(size_t)l * INNER];
        __half xv  = xcp[(size_t)l * INNER];
        float zv   = __half2float(zp[(size_t)l * INNER]);
        __half2 dt2  = __half2half2(dtv);
        __half2 dtx2 = __half2half2(__hmul(dtv, xv));
        __half2 acc2 = __floats2half2_rn(0.f, 0.f);
#pragma unroll
        for (int i = 0; i < 8; i++) {
            __half2 dA  = hexp2_x2(__hmul2(dt2, Ar2[i]));
            __half2 inc = __hmul2(*reinterpret_cast<const __half2*>(&sBh[l * 8 + i]), dtx2);
            h2[i] = __hfma2(dA, h2[i], inc);
            acc2  = __hfma2(*reinterpret_cast<const __half2*>(&sCh[l * 8 + i]), h2[i], acc2);
        }
        float acc = __low2float(acc2) + __high2float(acc2) + Dd * __half2float(xv);
        y0p[(size_t)l * INNER] = __float2half_rn(acc * siluf(zv));
    }
}

// ---------------- launch ----------------
extern "C" void kernel_launch(void* const* d_in, const int* in_sizes, int n_in,
                              void* d_out, int out_size)
{
    const float* x      = (const float*)d_in[0];
    const float* in_w   = (const float*)d_in[1];
    const float* in_b   = (const float*)d_in[2];
    const float* conv_w = (const float*)d_in[3];
    const float* conv_b = (const float*)d_in[4];
    const float* dt_w   = (const float*)d_in[5];
    const float* dt_b   = (const float*)d_in[6];
    const float* A_log  = (const float*)d_in[7];
    const float* B_w    = (const float*)d_in[8];
    const float* B_b    = (const float*)d_in[9];
    const float* C_w    = (const float*)d_in[10];
    const float* C_b    = (const float*)d_in[11];
    const float* Dv     = (const float*)d_in[12];
    const float* out_w  = (const float*)d_in[13];
    const float* out_b  = (const float*)d_in[14];
    float* out = (float*)d_out;

    __half *x0h, *wh, *dtwh, *xch, *y0h, *owh, *wbch, *zh, *dth, *xph;
    cudaGetSymbolAddress((void**)&xph, g_xph);
    cudaGetSymbolAddress((void**)&x0h, g_x0h);
    cudaGetSymbolAddress((void**)&wh, g_wh);
    cudaGetSymbolAddress((void**)&dtwh, g_dtwh);
    cudaGetSymbolAddress((void**)&xch, g_xch);
    cudaGetSymbolAddress((void**)&y0h, g_y0h);
    cudaGetSymbolAddress((void**)&owh, g_owh);
    cudaGetSymbolAddress((void**)&wbch, g_wbch);
    cudaGetSymbolAddress((void**)&zh, g_zh);
    cudaGetSymbolAddress((void**)&dth, g_dth);

    cudaFuncSetAttribute(gemm_mma<1>, cudaFuncAttributeMaxDynamicSharedMemorySize, GSMEM);
    cudaFuncSetAttribute(gemm_mma<0>, cudaFuncAttributeMaxDynamicSharedMemorySize, GSMEM);
    cudaFuncSetAttribute(gemm_mma<2>, cudaFuncAttributeMaxDynamicSharedMemorySize, GSMEM);
    cudaFuncSetAttribute(bc_mma, cudaFuncAttributeMaxDynamicSharedMemorySize, BCSMEM);

    static cudaStream_t s1 = nullptr;
    static cudaEvent_t evA = nullptr, evZ = nullptr, evC = nullptr, evB = nullptr;
    if (s1 == nullptr) {
        cudaStreamCreateWithFlags(&s1, cudaStreamNonBlocking);
        cudaEventCreateWithFlags(&evA, cudaEventDisableTiming);
        cudaEventCreateWithFlags(&evZ, cudaEventDisableTiming);
        cudaEventCreateWithFlags(&evC, cudaEventDisableTiming);
        cudaEventCreateWithFlags(&evB, cudaEventDisableTiming);
    }

    // 0) fp16 conversions
    cvt1h_kernel<<<2048, 256>>>(x, x0h, (size_t)M_TOT * HID / 4);
    cvtw_kernel<<<2048, 256>>>(in_w, dt_w, out_w, B_w, C_w, wh, dtwh, owh, wbch);
    cudaEventRecord(evA, 0);

    // fork: z half of in-proj on s1
    cudaStreamWaitEvent(s1, evA, 0);
    gemm_mma<2><<<dim3(INNER / GBN, M_TOT / GBM), 256, GSMEM, s1>>>(
        x0h, wh + (size_t)INNER * HID, in_b + INNER, zh, INNER, HID);
    cudaEventRecord(evZ, s1);

    // 1) in-proj x_part half -> fp16                       (16384 x 2048 x 1024)
    gemm_mma<2><<<dim3(INNER / GBN, M_TOT / GBM), 256, GSMEM>>>(
        x0h, wh, in_b, xph, INNER, HID);

    // 2) conv + silu (half2 vectorized)
    conv_silu_kernel<<<dim3(INNER / 256, LEN / 128, B_SZ), 128>>>(conv_w, conv_b);
    cudaEventRecord(evC, 0);

    // 3) B/C projections on s1, overlapping the dt GEMM (36KB CTAs co-reside)
    cudaStreamWaitEvent(s1, evC, 0);
    bc_mma<<<M_TOT / 64, 128, BCSMEM, s1>>>(xch, wbch, B_b, C_b);
    cudaEventRecord(evB, s1);

    // 4) dt = softplus(xconv @ dt_w^T + dt_b) -> fp16      (16384 x 2048 x 2048)
    gemm_mma<1><<<dim3(INNER / GBN, M_TOT / GBM), 256, GSMEM>>>(
        xch, dtwh, dt_b, dth, INNER, INNER);

    // 5) chunked selective scan + gating
    cudaStreamWaitEvent(0, evB, 0);   // Bm/Cm ready
    scanA_kernel<<<dim3(INNER / 128, NC, B_SZ), 128>>>(A_log);
    scanB_kernel<<<(B_SZ * INNER) / 256, 256>>>(A_log);
    cudaStreamWaitEvent(0, evZ, 0);   // z ready
    scanC_kernel<<<dim3(INNER / 128, NC, B_SZ), 128>>>(A_log, Dv);

    // 6) out-proj: out = y @ out_w^T + out_b               (16384 x 1024 x 2048)
    gemm_mma<0><<<dim3(HID / GBN, M_TOT / GBM), 256, GSMEM>>>(
        y0h, owh, out_b, out, HID, INNER);
}

// round 15
// speedup vs baseline: 5.9255x; 1.0130x over previous
#include <cuda_runtime.h>
#include <cuda_fp16.h>
#include <math.h>
#include <stdint.h>

#define B_SZ   4
#define LEN    4096
#define HID    1024
#define STATE  16
#define INNER  2048
#define M_TOT  (B_SZ * LEN)
#define NC     16
#define LC     256
#define LOG2E  1.4426950408889634f

// ---------------- scratch ----------------
__device__ __align__(1024) float    g_Bm  [(size_t)M_TOT * STATE];
__device__ __align__(1024) float    g_Cm  [(size_t)M_TOT * STATE];
__device__ __align__(1024) uint32_t g_S2  [(size_t)B_SZ * NC * 8 * INNER];
__device__ __align__(1024) float    g_dts [(size_t)B_SZ * NC * INNER];
__device__ __align__(1024) float    g_H0  [(size_t)B_SZ * NC * STATE * INNER];
__device__ __align__(1024) __half   g_xph [(size_t)M_TOT * INNER];
__device__ __align__(1024) __half   g_zh  [(size_t)M_TOT * INNER];
__device__ __align__(1024) __half   g_dth [(size_t)M_TOT * INNER];
__device__ __align__(1024) __half   g_x0h [(size_t)M_TOT * HID];
__device__ __align__(1024) __half   g_wh  [(size_t)2 * INNER * HID];
__device__ __align__(1024) __half   g_dtwh[(size_t)INNER * INNER];
__device__ __align__(1024) __half   g_xch [(size_t)M_TOT * INNER];
__device__ __align__(1024) __half   g_y0h [(size_t)M_TOT * INNER];
__device__ __align__(1024) __half   g_owh [(size_t)HID * INNER];
__device__ __align__(1024) __half   g_wbch[32 * INNER];

// ---------------- PTX helpers ----------------
__device__ __forceinline__ uint32_t smem_u32(const void* p) {
    uint32_t a;
    asm("{ .reg .u64 t; cvta.to.shared.u64 t, %1; cvt.u32.u64 %0, t; }" : "=r"(a) : "l"(p));
    return a;
}
__device__ __forceinline__ void cp_async16(uint32_t dst, const void* src) {
    asm volatile("cp.async.cg.shared.global [%0], [%1], 16;" :: "r"(dst), "l"(src) : "memory");
}
#define CP_COMMIT() asm volatile("cp.async.commit_group;" ::: "memory")
#define CP_WAIT1()  asm volatile("cp.async.wait_group 1;" ::: "memory")

__device__ __forceinline__ void ldm_x4(uint32_t* r, uint32_t addr) {
    asm volatile("ldmatrix.sync.aligned.m8n8.x4.shared.b16 {%0,%1,%2,%3}, [%4];"
        : "=r"(r[0]), "=r"(r[1]), "=r"(r[2]), "=r"(r[3]) : "r"(addr));
}
__device__ __forceinline__ void mma16816h(float* d, const uint32_t* a, const uint32_t* b) {
    asm volatile("mma.sync.aligned.m16n8k16.row.col.f32.f16.f16.f32 "
        "{%0,%1,%2,%3}, {%4,%5,%6,%7}, {%8,%9}, {%0,%1,%2,%3};"
        : "+f"(d[0]), "+f"(d[1]), "+f"(d[2]), "+f"(d[3])
        : "r"(a[0]), "r"(a[1]), "r"(a[2]), "r"(a[3]), "r"(b[0]), "r"(b[1]));
}
__device__ __forceinline__ __half2 hexp2_x2(__half2 x) {
    __half2 r;
    asm("ex2.approx.f16x2 %0, %1;" : "=r"(*(uint32_t*)&r) : "r"(*(uint32_t*)&x));
    return r;
}
__device__ __forceinline__ float softplusf(float v) { return v > 20.f ? v : log1pf(__expf(v)); }
__device__ __forceinline__ float siluf(float v)     { return v / (1.f + __expf(-v)); }

// ---------------- fp16 mma.sync GEMM, 2 CTAs/SM tiling ----------------
#define GBM 128
#define GBN 128
#define GAST (GBM * 128)
#define GSTG (GAST + GBN * 128)
#define GSMEM (3 * GSTG)

template <int EPI>   // 0 = fp32 bias, 1 = fp16 softplus, 2 = fp16 bias
__global__ void __launch_bounds__(256, 2) gemm_mma(
    const __half* __restrict__ Ap, const __half* __restrict__ Bp,
    const float* __restrict__ bias, void* __restrict__ Cv, int Cstride, int K)
{
    extern __shared__ char smraw[];
    const uint32_t sbase = smem_u32(smraw);
    const int tid  = threadIdx.x;
    const int wid  = tid >> 5;
    const int lane = tid & 31;
    const int bm0  = blockIdx.y * GBM;
    const int bn0  = blockIdx.x * GBN;

    const int KTT = K >> 6;
    const size_t lda = (size_t)K * 2;

    auto load_stage = [&](int kt, int s) {
        const uint32_t sa = sbase + s * GSTG;
        const uint32_t sb = sa + GAST;
#pragma unroll
        for (int i = 0; i < 4; ++i) {
            int idx = tid + i * 256, r = idx >> 3, c = idx & 7;
            cp_async16(sa + r * 128 + ((c ^ (r & 7)) << 4),
                       (const char*)Ap + (size_t)(bm0 + r) * lda + (size_t)kt * 128 + c * 16);
        }
#pragma unroll
        for (int i = 0; i < 4; ++i) {
            int idx = tid + i * 256, r = idx >> 3, c = idx & 7;
            cp_async16(sb + r * 128 + ((c ^ (r & 7)) << 4),
                       (const char*)Bp + (size_t)(bn0 + r) * lda + (size_t)kt * 128 + c * 16);
        }
    };

    float acc[4][4][4];
#pragma unroll
    for (int mt = 0; mt < 4; ++mt)
#pragma unroll
        for (int nt = 0; nt < 4; ++nt)
#pragma unroll
            for (int q = 0; q < 4; ++q) acc[mt][nt][q] = 0.f;

    load_stage(0, 0); CP_COMMIT();
    load_stage(1, 1); CP_COMMIT();

    const int wm0 = (wid >> 2) * 64;
    const int wn0 = (wid & 3) * 32;
    const int aRow = wm0 + ((lane >> 3) & 1) * 8 + (lane & 7);
    const int bRow = wn0 + ((lane >> 4) & 1) * 8 + (lane & 7);
    const int swzX = (lane & 7) << 4;
    const int aKs  = (lane >> 4) << 4;
    const int bKs  = ((lane >> 3) & 1) << 4;

    for (int kt = 0; kt < KTT; ++kt) {
        const int s = kt % 3;
        CP_WAIT1();
        __syncthreads();
        if (kt + 2 < KTT) { load_stage(kt + 2, (kt + 2) % 3); CP_COMMIT(); }

        const uint32_t Ab = sbase + s * GSTG;
        const uint32_t Bb = Ab + GAST;
#pragma unroll
        for (int ks = 0; ks < 4; ++ks) {
            const int swA = (ks * 32 + aKs) ^ swzX;
            const int swB = (ks * 32 + bKs) ^ swzX;
            uint32_t a[4][4], b[2][4];
#pragma unroll
            for (int mt = 0; mt < 4; ++mt) ldm_x4(a[mt], Ab + (aRow + mt * 16) * 128 + swA);
#pragma unroll
            for (int np = 0; np < 2; ++np) ldm_x4(b[np], Bb + (bRow + np * 16) * 128 + swB);
#pragma unroll
            for (int mt = 0; mt < 4; ++mt)
#pragma unroll
                for (int nt = 0; nt < 4; ++nt)
                    mma16816h(acc[mt][nt], a[mt], &b[nt >> 1][(nt & 1) * 2]);
        }
    }

#pragma unroll
    for (int nt = 0; nt < 4; ++nt) {
        const int col = bn0 + wn0 + nt * 8 + (lane & 3) * 2;
        const float b0v = bias[col], b1v = bias[col + 1];
#pragma unroll
        for (int mt = 0; mt < 4; ++mt) {
            const int row = bm0 + wm0 + mt * 16 + (lane >> 2);
            float v0 = acc[mt][nt][0] + b0v, v1 = acc[mt][nt][1] + b1v;
            float v2 = acc[mt][nt][2] + b0v, v3 = acc[mt][nt][3] + b1v;
            if (EPI == 1) {
                v0 = softplusf(v0); v1 = softplusf(v1);
                v2 = softplusf(v2); v3 = softplusf(v3);
            }
            if (EPI == 0) {
                float* C = (float*)Cv;
                *reinterpret_cast<float2*>(&C[(size_t)row * Cstride + col])       = make_float2(v0, v1);
                *reinterpret_cast<float2*>(&C[(size_t)(row + 8) * Cstride + col]) = make_float2(v2, v3);
            } else {
                __half* C = (__half*)Cv;
                *reinterpret_cast<__half2*>(&C[(size_t)row * Cstride + col])       = __floats2half2_rn(v0, v1);
                *reinterpret_cast<__half2*>(&C[(size_t)(row + 8) * Cstride + col]) = __floats2half2_rn(v2, v3);
            }
        }
    }
}

// ---------------- B/C projection: BM=64, 128 threads, 2 stages x 12KB = 24KB ----------------
// small enough to co-reside with the dt GEMM's 2 x 96KB CTAs.
#define BCAST (64 * 128)
#define BCSTG (BCAST + 32 * 128)
#define BCSMEM (2 * BCSTG)
__global__ void __launch_bounds__(128, 1) bc_mma(
    const __half* __restrict__ A, const __half* __restrict__ W,
    const float* __restrict__ Bb, const float* __restrict__ Cb)
{
    extern __shared__ char smraw[];
    const uint32_t sbase = smem_u32(smraw);
    const int tid  = threadIdx.x;
    const int wid  = tid >> 5;
    const int lane = tid & 31;
    const int bm0  = blockIdx.x * 64;
    const size_t lda = (size_t)INNER * 2;

    auto load_stage = [&](int kt, int s) {
        const uint32_t sa = sbase + s * BCSTG;
        const uint32_t sb = sa + BCAST;
#pragma unroll
        for (int i = 0; i < 4; ++i) {
            int idx = tid + i * 128, r = idx >> 3, c = idx & 7;
            cp_async16(sa + r * 128 + ((c ^ (r & 7)) << 4),
                       (const char*)A + (size_t)(bm0 + r) * lda + (size_t)kt * 128 + c * 16);
        }
#pragma unroll
        for (int i = 0; i < 2; ++i) {
            int idx = tid + i * 128, r = idx >> 3, c = idx & 7;
            cp_async16(sb + r * 128 + ((c ^ (r & 7)) << 4),
                       (const char*)W + (size_t)r * lda + (size_t)kt * 128 + c * 16);
        }
    };

    float acc[4][4];
#pragma unroll
    for (int nt = 0; nt < 4; ++nt)
#pragma unroll
        for (int q = 0; q < 4; ++q) acc[nt][q] = 0.f;

    load_stage(0, 0); CP_COMMIT();
    load_stage(1, 1); CP_COMMIT();

    const int aRow = wid * 16 + ((lane >> 3) & 1) * 8 + (lane & 7);
    const int bRow = ((lane >> 4) & 1) * 8 + (lane & 7);
    const int swzX = (lane & 7) << 4;
    const int aKs  = (lane >> 4) << 4;
    const int bKs  = ((lane >> 3) & 1) << 4;

    const int KT = INNER / 64;
    for (int kt = 0; kt < KT; ++kt) {
        const int s = kt & 1;
        CP_WAIT1();
        __syncthreads();

        const uint32_t Ab = sbase + s * BCSTG;
        const uint32_t Bb_ = Ab + BCAST;
#pragma unroll
        for (int ks = 0; ks < 4; ++ks) {
            const int swA = (ks * 32 + aKs) ^ swzX;
            const int swB = (ks * 32 + bKs) ^ swzX;
            uint32_t a[4], b[2][4];
            ldm_x4(a, Ab + aRow * 128 + swA);
#pragma unroll
            for (int np = 0; np < 2; ++np) ldm_x4(b[np], Bb_ + (bRow + np * 16) * 128 + swB);
#pragma unroll
            for (int nt = 0; nt < 4; ++nt)
                mma16816h(acc[nt], a, &b[nt >> 1][(nt & 1) * 2]);
        }
        __syncthreads();                       // all reads of stage s done
        if (kt + 2 < KT) { load_stage(kt + 2, s); CP_COMMIT(); }
    }

#pragma unroll
    for (int nt = 0; nt < 4; ++nt) {
        const int col = nt * 8 + (lane & 3) * 2;
        const int row = bm0 + wid * 16 + (lane >> 2);
        if (col < 16) {
            const float c0 = Bb[col], c1 = Bb[col + 1];
            *reinterpret_cast<float2*>(&g_Bm[(size_t)row * 16 + col]) =
                make_float2(acc[nt][0] + c0, acc[nt][1] + c1);
            *reinterpret_cast<float2*>(&g_Bm[(size_t)(row + 8) * 16 + col]) =
                make_float2(acc[nt][2] + c0, acc[nt][3] + c1);
        } else {
            const int cc = col - 16;
            const float c0 = Cb[cc], c1 = Cb[cc + 1];
            *reinterpret_cast<float2*>(&g_Cm[(size_t)row * 16 + cc]) =
                make_float2(acc[nt][0] + c0, acc[nt][1] + c1);
            *reinterpret_cast<float2*>(&g_Cm[(size_t)(row + 8) * 16 + cc]) =
                make_float2(acc[nt][2] + c0, acc[nt][3] + c1);
        }
    }
}

// ---------------- conversions: x + all weights in ONE launch ----------------
__global__ void __launch_bounds__(256) cvtall_kernel(
    const float* __restrict__ xs, const float* __restrict__ w1, const float* __restrict__ w2,
    const float* __restrict__ w3, const float* __restrict__ w4, const float* __restrict__ w5,
    __half* __restrict__ ox, __half* __restrict__ o1, __half* __restrict__ o2,
    __half* __restrict__ o3, __half* __restrict__ o4)
{
    const size_t n0 = (size_t)M_TOT * HID / 4;
    const size_t n1 = (size_t)2 * INNER * HID / 4;
    const size_t n2 = (size_t)INNER * INNER / 4;
    const size_t n3 = (size_t)HID * INNER / 4;
    const size_t n4 = (size_t)16 * INNER / 4;
    const size_t nt = n0 + n1 + n2 + n3 + 2 * n4;
    for (size_t i = (size_t)blockIdx.x * 256 + threadIdx.x; i < nt;
         i += (size_t)gridDim.x * 256) {
        const float* src; __half* dst; size_t j;
        if (i < n0)                      { src = xs; dst = ox; j = i; }
        else if (i < n0 + n1)            { src = w1; dst = o1; j = i - n0; }
        else if (i < n0 + n1 + n2)       { src = w2; dst = o2; j = i - n0 - n1; }
        else if (i < n0 + n1 + n2 + n3)  { src = w3; dst = o3; j = i - n0 - n1 - n2; }
        else if (i < n0 + n1 + n2 + n3 + n4) { src = w4; dst = o4; j = i - n0 - n1 - n2 - n3; }
        else { src = w5; dst = o4 + (size_t)16 * INNER; j = i - n0 - n1 - n2 - n3 - n4; }
        float4 v = reinterpret_cast<const float4*>(src)[j];
        ((ushort4*)dst)[j] = make_ushort4(
            __half_as_ushort(__float2half_rn(v.x)), __half_as_ushort(__float2half_rn(v.y)),
            __half_as_ushort(__float2half_rn(v.z)), __half_as_ushort(__float2half_rn(v.w)));
    }
}

// ---------------- causal depthwise conv (K=4) + SiLU, half2 vectorized ----------------
__global__ void __launch_bounds__(128) conv_silu_kernel(
    const float* __restrict__ conv_w, const float* __restrict__ conv_b)
{
    const int d2 = blockIdx.x * 128 + threadIdx.x;
    const int l0 = blockIdx.y * 128;
    const int b  = blockIdx.z;
    const int d  = d2 * 2;
    const float2 w0 = make_float2(conv_w[d * 4 + 0], conv_w[d * 4 + 4]);
    const float2 w1 = make_float2(conv_w[d * 4 + 1], conv_w[d * 4 + 5]);
    const float2 w2 = make_float2(conv_w[d * 4 + 2], conv_w[d * 4 + 6]);
    const float2 w3 = make_float2(conv_w[d * 4 + 3], conv_w[d * 4 + 7]);
    const float2 cb = make_float2(conv_b[d], conv_b[d + 1]);
    const __half2* xp = (const __half2*)g_xph + (size_t)(b * LEN) * (INNER / 2) + d2;
    float2 m3, m2, m1;
    if (l0 == 0) { m3 = m2 = m1 = make_float2(0.f, 0.f); }
    else {
        m3 = __half22float2(xp[(size_t)(l0 - 3) * (INNER / 2)]);
        m2 = __half22float2(xp[(size_t)(l0 - 2) * (INNER / 2)]);
        m1 = __half22float2(xp[(size_t)(l0 - 1) * (INNER / 2)]);
    }
    __half2* xh = (__half2*)g_xch + (size_t)(b * LEN + l0) * (INNER / 2) + d2;
#pragma unroll 4
    for (int i = 0; i < 128; ++i) {
        float2 cur = __half22float2(xp[(size_t)(l0 + i) * (INNER / 2)]);
        float vx = w0.x * m3.x + w1.x * m2.x + w2.x * m1.x + w3.x * cur.x + cb.x;
        float vy = w0.y * m3.y + w1.y * m2.y + w2.y * m1.y + w3.y * cur.y + cb.y;
        xh[(size_t)i * (INNER / 2)] = __floats2half2_rn(siluf(vx), siluf(vy));
        m3 = m2; m2 = m1; m1 = cur;
    }
}

// ---------------- chunked selective scan ----------------
__global__ void __launch_bounds__(128) scanA_kernel(const float* __restrict__ A_log)
{
    __shared__ uint32_t sBh[LC * 8];
    const int d = blockIdx.x * 128 + threadIdx.x;
    const int c = blockIdx.y;
    const int b = blockIdx.z;
    const int base_l = c * LC;
    for (int i = threadIdx.x; i < LC * 8; i += 128) {
        const float2 v = *reinterpret_cast<const float2*>(
            &g_Bm[(size_t)(b * LEN + base_l) * STATE + 2 * i]);
        __half2 hh = __floats2half2_rn(v.x, v.y);
        sBh[i] = *reinterpret_cast<uint32_t*>(&hh);
    }
    __syncthreads();
    __half2 Ar2[8];
#pragma unroll
    for (int i = 0; i < 8; i++)
        Ar2[i] = __floats2half2_rn(-expf(A_log[d * STATE + 2 * i]) * LOG2E,
                                   -expf(A_log[d * STATE + 2 * i + 1]) * LOG2E);
    __half2 h2[8];
#pragma unroll
    for (int i = 0; i < 8; i++) h2[i] = __floats2half2_rn(0.f, 0.f);
    float dtsum = 0.f;
    const __half* dtp = g_dth + (size_t)(b * LEN + base_l) * INNER + d;
    const __half* xcp = g_xch + (size_t)(b * LEN + base_l) * INNER + d;
    for (int l = 0; l < LC; ++l) {
        __half dtv = dtp[(size_t)l * INNER];
        __half xv  = xcp[(size_t)l * INNER];
        dtsum += __half2float(dtv);
        __half2 dt2  = __half2half2(dtv);
        __half2 dtx2 = __half2half2(__hmul(dtv, xv));
#pragma unroll
        for (int i = 0; i < 8; i++) {
            __half2 dA  = hexp2_x2(__hmul2(dt2, Ar2[i]));
            __half2 inc = __hmul2(*reinterpret_cast<const __half2*>(&sBh[l * 8 + i]), dtx2);
            h2[i] = __hfma2(dA, h2[i], inc);
        }
    }
    size_t sb2 = (size_t)(b * NC + c) * 8 * INNER + d;
#pragma unroll
    for (int i = 0; i < 8; i++)
        g_S2[sb2 + (size_t)i * INNER] = *reinterpret_cast<uint32_t*>(&h2[i]);
    g_dts[(size_t)(b * NC + c) * INNER + d] = dtsum;
}

// pass B: one thread per (b, d, state-pair); 256 CTAs
__global__ void __launch_bounds__(256) scanB_kernel(const float* __restrict__ A_log)
{
    int g = blockIdx.x * 256 + threadIdx.x;            // 0 .. B*INNER*8-1
    int i = g & 7;
    int t = g >> 3;
    int b = t / INNER;
    int d = t - b * INNER;
    float Ar0 = -expf(A_log[d * STATE + 2 * i]);
    float Ar1 = -expf(A_log[d * STATE + 2 * i + 1]);
    float h0 = 0.f, h1 = 0.f;
    for (int c = 0; c < NC; ++c) {
        size_t hb = (size_t)(b * NC + c) * STATE * INNER + d;
        g_H0[hb + (size_t)(2 * i) * INNER]     = h0;
        g_H0[hb + (size_t)(2 * i + 1) * INNER] = h1;
        float ds = g_dts[(size_t)(b * NC + c) * INNER + d];
        uint32_t sv = g_S2[(size_t)(b * NC + c) * 8 * INNER + (size_t)i * INNER + d];
        float2 svf = __half22float2(*reinterpret_cast<__half2*>(&sv));
        h0 = __expf(Ar0 * ds) * h0 + svf.x;
        h1 = __expf(Ar1 * ds) * h1 + svf.y;
    }
}

__global__ void __launch_bounds__(128) scanC_kernel(
    const float* __restrict__ A_log, const float* __restrict__ Dv)
{
    __shared__ uint32_t sBh[LC * 8];
    __shared__ uint32_t sCh[LC * 8];
    const int d = blockIdx.x * 128 + threadIdx.x;
    const int c = blockIdx.y;
    const int b = blockIdx.z;
    const int base_l = c * LC;
    for (int i = threadIdx.x; i < LC * 8; i += 128) {
        const float2 vb = *reinterpret_cast<const float2*>(
            &g_Bm[(size_t)(b * LEN + base_l) * STATE + 2 * i]);
        const float2 vc = *reinterpret_cast<const float2*>(
            &g_Cm[(size_t)(b * LEN + base_l) * STATE + 2 * i]);
        __half2 hb = __floats2half2_rn(vb.x, vb.y);
        __half2 hc = __floats2half2_rn(vc.x, vc.y);
        sBh[i] = *reinterpret_cast<uint32_t*>(&hb);
        sCh[i] = *reinterpret_cast<uint32_t*>(&hc);
    }
    __syncthreads();
    __half2 Ar2[8];
#pragma unroll
    for (int i = 0; i < 8; i++)
        Ar2[i] = __floats2half2_rn(-expf(A_log[d * STATE + 2 * i]) * LOG2E,
                                   -expf(A_log[d * STATE + 2 * i + 1]) * LOG2E);
    const float Dd = Dv[d];
    __half2 h2[8];
    size_t ob = (size_t)(b * NC + c) * STATE * INNER + d;
#pragma unroll
    for (int i = 0; i < 8; i++)
        h2[i] = __floats2half2_rn(g_H0[ob + (size_t)(2 * i) * INNER],
                                  g_H0[ob + (size_t)(2 * i + 1) * INNER]);
    const __half* dtp = g_dth + (size_t)(b * LEN + base_l) * INNER + d;
    const __half* xcp = g_xch + (size_t)(b * LEN + base_l) * INNER + d;
    const __half* zp  = g_zh  + (size_t)(b * LEN + base_l) * INNER + d;
    __half* y0p = g_y0h + (size_t)(b * LEN + base_l) * INNER + d;
    for (int l = 0; l < LC; ++l) {
        __half dtv = dtp[(size_t)l * INNER];
        __half xv  = xcp[(size_t)l * INNER];
        float zv   = __half2float(zp[(size_t)l * INNER]);
        __half2 dt2  = __half2half2(dtv);
        __half2 dtx2 = __half2half2(__hmul(dtv, xv));
        __half2 acc2 = __floats2half2_rn(0.f, 0.f);
#pragma unroll
        for (int i = 0; i < 8; i++) {
            __half2 dA  = hexp2_x2(__hmul2(dt2, Ar2[i]));
            __half2 inc = __hmul2(*reinterpret_cast<const __half2*>(&sBh[l * 8 + i]), dtx2);
            h2[i] = __hfma2(dA, h2[i], inc);
            acc2  = __hfma2(*reinterpret_cast<const __half2*>(&sCh[l * 8 + i]), h2[i], acc2);
        }
        float acc = __low2float(acc2) + __high2float(acc2) + Dd * __half2float(xv);
        y0p[(size_t)l * INNER] = __float2half_rn(acc * siluf(zv));
    }
}

// ---------------- launch ----------------
extern "C" void kernel_launch(void* const* d_in, const int* in_sizes, int n_in,
                              void* d_out, int out_size)
{
    const float* x      = (const float*)d_in[0];
    const float* in_w   = (const float*)d_in[1];
    const float* in_b   = (const float*)d_in[2];
    const float* conv_w = (const float*)d_in[3];
    const float* conv_b = (const float*)d_in[4];
    const float* dt_w   = (const float*)d_in[5];
    const float* dt_b   = (const float*)d_in[6];
    const float* A_log  = (const float*)d_in[7];
    const float* B_w    = (const float*)d_in[8];
    const float* B_b    = (const float*)d_in[9];
    const float* C_w    = (const float*)d_in[10];
    const float* C_b    = (const float*)d_in[11];
    const float* Dv     = (const float*)d_in[12];
    const float* out_w  = (const float*)d_in[13];
    const float* out_b  = (const float*)d_in[14];
    float* out = (float*)d_out;

    __half *x0h, *wh, *dtwh, *xch, *y0h, *owh, *wbch, *zh, *dth, *xph;
    cudaGetSymbolAddress((void**)&xph, g_xph);
    cudaGetSymbolAddress((void**)&x0h, g_x0h);
    cudaGetSymbolAddress((void**)&wh, g_wh);
    cudaGetSymbolAddress((void**)&dtwh, g_dtwh);
    cudaGetSymbolAddress((void**)&xch, g_xch);
    cudaGetSymbolAddress((void**)&y0h, g_y0h);
    cudaGetSymbolAddress((void**)&owh, g_owh);
    cudaGetSymbolAddress((void**)&wbch, g_wbch);
    cudaGetSymbolAddress((void**)&zh, g_zh);
    cudaGetSymbolAddress((void**)&dth, g_dth);

    cudaFuncSetAttribute(gemm_mma<1>, cudaFuncAttributeMaxDynamicSharedMemorySize, GSMEM);
    cudaFuncSetAttribute(gemm_mma<0>, cudaFuncAttributeMaxDynamicSharedMemorySize, GSMEM);
    cudaFuncSetAttribute(gemm_mma<2>, cudaFuncAttributeMaxDynamicSharedMemorySize, GSMEM);
    cudaFuncSetAttribute(bc_mma, cudaFuncAttributeMaxDynamicSharedMemorySize, BCSMEM);

    static cudaStream_t s1 = nullptr;
    static cudaEvent_t evA = nullptr, evZ = nullptr, evC = nullptr, evB = nullptr;
    if (s1 == nullptr) {
        cudaStreamCreateWithFlags(&s1, cudaStreamNonBlocking);
        cudaEventCreateWithFlags(&evA, cudaEventDisableTiming);
        cudaEventCreateWithFlags(&evZ, cudaEventDisableTiming);
        cudaEventCreateWithFlags(&evC, cudaEventDisableTiming);
        cudaEventCreateWithFlags(&evB, cudaEventDisableTiming);
    }

    // 0) all fp16 conversions in one launch
    cvtall_kernel<<<2048, 256>>>(x, in_w, dt_w, out_w, B_w, C_w,
                                 x0h, wh, dtwh, owh, wbch);
    cudaEventRecord(evA, 0);

    // fork: z half of in-proj on s1
    cudaStreamWaitEvent(s1, evA, 0);
    gemm_mma<2><<<dim3(INNER / GBN, M_TOT / GBM), 256, GSMEM, s1>>>(
        x0h, wh + (size_t)INNER * HID, in_b + INNER, zh, INNER, HID);
    cudaEventRecord(evZ, s1);

    // 1) in-proj x_part half -> fp16                       (16384 x 2048 x 1024)
    gemm_mma<2><<<dim3(INNER / GBN, M_TOT / GBM), 256, GSMEM>>>(
        x0h, wh, in_b, xph, INNER, HID);

    // 2) conv + silu (half2 vectorized)
    conv_silu_kernel<<<dim3(INNER / 256, LEN / 128, B_SZ), 128>>>(conv_w, conv_b);
    cudaEventRecord(evC, 0);

    // 3) B/C projections on s1, truly co-residing with the dt GEMM (24KB CTAs)
    cudaStreamWaitEvent(s1, evC, 0);
    bc_mma<<<M_TOT / 64, 128, BCSMEM, s1>>>(xch, wbch, B_b, C_b);
    cudaEventRecord(evB, s1);

    // 4) dt = softplus(xconv @ dt_w^T + dt_b) -> fp16      (16384 x 2048 x 2048)
    gemm_mma<1><<<dim3(INNER / GBN, M_TOT / GBM), 256, GSMEM>>>(
        xch, dtwh, dt_b, dth, INNER, INNER);

    // 5) chunked selective scan + gating
    cudaStreamWaitEvent(0, evB, 0);   // Bm/Cm ready
    scanA_kernel<<<dim3(INNER / 128, NC, B_SZ), 128>>>(A_log);
    scanB_kernel<<<(B_SZ * INNER * 8) / 256, 256>>>(A_log);
    cudaStreamWaitEvent(0, evZ, 0);   // z ready
    scanC_kernel<<<dim3(INNER / 128, NC, B_SZ), 128>>>(A_log, Dv);

    // 6) out-proj: out = y @ out_w^T + out_b               (16384 x 1024 x 2048)
    gemm_mma<0><<<dim3(HID / GBN, M_TOT / GBM), 256, GSMEM>>>(
        y0h, owh, out_b, out, HID, INNER);
}

// round 16
// speedup vs baseline: 5.9303x; 1.0008x over previous
#include <cuda_runtime.h>
#include <cuda_fp16.h>
#include <math.h>
#include <stdint.h>

#define B_SZ   4
#define LEN    4096
#define HID    1024
#define STATE  16
#define INNER  2048
#define M_TOT  (B_SZ * LEN)
#define NC     16
#define LC     256
#define LOG2E  1.4426950408889634f

// ---------------- scratch ----------------
__device__ __align__(1024) float    g_Bm  [(size_t)M_TOT * STATE];
__device__ __align__(1024) float    g_Cm  [(size_t)M_TOT * STATE];
__device__ __align__(1024) uint32_t g_S2  [(size_t)B_SZ * NC * 8 * INNER];
__device__ __align__(1024) float    g_dts [(size_t)B_SZ * NC * INNER];
__device__ __align__(1024) float    g_H0  [(size_t)B_SZ * NC * STATE * INNER];
__device__ __align__(1024) __half   g_xph [(size_t)M_TOT * INNER];
__device__ __align__(1024) __half   g_zh  [(size_t)M_TOT * INNER];
__device__ __align__(1024) __half   g_dth [(size_t)M_TOT * INNER];
__device__ __align__(1024) __half   g_x0h [(size_t)M_TOT * HID];
__device__ __align__(1024) __half   g_wh  [(size_t)2 * INNER * HID];
__device__ __align__(1024) __half   g_dtwh[(size_t)INNER * INNER];
__device__ __align__(1024) __half   g_xch [(size_t)M_TOT * INNER];
__device__ __align__(1024) __half   g_y0h [(size_t)M_TOT * INNER];
__device__ __align__(1024) __half   g_owh [(size_t)HID * INNER];
__device__ __align__(1024) __half   g_wbch[32 * INNER];

// ---------------- PTX helpers ----------------
__device__ __forceinline__ uint32_t smem_u32(const void* p) {
    uint32_t a;
    asm("{ .reg .u64 t; cvta.to.shared.u64 t, %1; cvt.u32.u64 %0, t; }" : "=r"(a) : "l"(p));
    return a;
}
__device__ __forceinline__ void cp_async16(uint32_t dst, const void* src) {
    asm volatile("cp.async.cg.shared.global [%0], [%1], 16;" :: "r"(dst), "l"(src) : "memory");
}
#define CP_COMMIT() asm volatile("cp.async.commit_group;" ::: "memory")
#define CP_WAIT1()  asm volatile("cp.async.wait_group 1;" ::: "memory")

__device__ __forceinline__ void ldm_x4(uint32_t* r, uint32_t addr) {
    asm volatile("ldmatrix.sync.aligned.m8n8.x4.shared.b16 {%0,%1,%2,%3}, [%4];"
        : "=r"(r[0]), "=r"(r[1]), "=r"(r[2]), "=r"(r[3]) : "r"(addr));
}
__device__ __forceinline__ void mma16816h(float* d, const uint32_t* a, const uint32_t* b) {
    asm volatile("mma.sync.aligned.m16n8k16.row.col.f32.f16.f16.f32 "
        "{%0,%1,%2,%3}, {%4,%5,%6,%7}, {%8,%9}, {%0,%1,%2,%3};"
        : "+f"(d[0]), "+f"(d[1]), "+f"(d[2]), "+f"(d[3])
        : "r"(a[0]), "r"(a[1]), "r"(a[2]), "r"(a[3]), "r"(b[0]), "r"(b[1]));
}
__device__ __forceinline__ __half2 hexp2_x2(__half2 x) {
    __half2 r;
    asm("ex2.approx.f16x2 %0, %1;" : "=r"(*(uint32_t*)&r) : "r"(*(uint32_t*)&x));
    return r;
}
__device__ __forceinline__ float softplusf(float v) { return v > 20.f ? v : log1pf(__expf(v)); }
__device__ __forceinline__ float siluf(float v)     { return v / (1.f + __expf(-v)); }

// ---------------- fp16 mma.sync GEMM, 2 CTAs/SM tiling ----------------
#define GBM 128
#define GBN 128
#define GAST (GBM * 128)
#define GSTG (GAST + GBN * 128)
#define GSMEM (3 * GSTG)

template <int EPI>   // 0 = fp32 bias, 1 = fp16 softplus, 2 = fp16 bias
__global__ void __launch_bounds__(256, 2) gemm_mma(
    const __half* __restrict__ Ap, const __half* __restrict__ Bp,
    const float* __restrict__ bias, void* __restrict__ Cv, int Cstride, int K)
{
    extern __shared__ char smraw[];
    const uint32_t sbase = smem_u32(smraw);
    const int tid  = threadIdx.x;
    const int wid  = tid >> 5;
    const int lane = tid & 31;
    const int bm0  = blockIdx.y * GBM;
    const int bn0  = blockIdx.x * GBN;

    const int KTT = K >> 6;
    const size_t lda = (size_t)K * 2;

    auto load_stage = [&](int kt, int s) {
        const uint32_t sa = sbase + s * GSTG;
        const uint32_t sb = sa + GAST;
#pragma unroll
        for (int i = 0; i < 4; ++i) {
            int idx = tid + i * 256, r = idx >> 3, c = idx & 7;
            cp_async16(sa + r * 128 + ((c ^ (r & 7)) << 4),
                       (const char*)Ap + (size_t)(bm0 + r) * lda + (size_t)kt * 128 + c * 16);
        }
#pragma unroll
        for (int i = 0; i < 4; ++i) {
            int idx = tid + i * 256, r = idx >> 3, c = idx & 7;
            cp_async16(sb + r * 128 + ((c ^ (r & 7)) << 4),
                       (const char*)Bp + (size_t)(bn0 + r) * lda + (size_t)kt * 128 + c * 16);
        }
    };

    float acc[4][4][4];
#pragma unroll
    for (int mt = 0; mt < 4; ++mt)
#pragma unroll
        for (int nt = 0; nt < 4; ++nt)
#pragma unroll
            for (int q = 0; q < 4; ++q) acc[mt][nt][q] = 0.f;

    load_stage(0, 0); CP_COMMIT();
    load_stage(1, 1); CP_COMMIT();

    const int wm0 = (wid >> 2) * 64;
    const int wn0 = (wid & 3) * 32;
    const int aRow = wm0 + ((lane >> 3) & 1) * 8 + (lane & 7);
    const int bRow = wn0 + ((lane >> 4) & 1) * 8 + (lane & 7);
    const int swzX = (lane & 7) << 4;
    const int aKs  = (lane >> 4) << 4;
    const int bKs  = ((lane >> 3) & 1) << 4;

    for (int kt = 0; kt < KTT; ++kt) {
        const int s = kt % 3;
        CP_WAIT1();
        __syncthreads();
        if (kt + 2 < KTT) { load_stage(kt + 2, (kt + 2) % 3); CP_COMMIT(); }

        const uint32_t Ab = sbase + s * GSTG;
        const uint32_t Bb = Ab + GAST;
#pragma unroll
        for (int ks = 0; ks < 4; ++ks) {
            const int swA = (ks * 32 + aKs) ^ swzX;
            const int swB = (ks * 32 + bKs) ^ swzX;
            uint32_t a[4][4], b[2][4];
#pragma unroll
            for (int mt = 0; mt < 4; ++mt) ldm_x4(a[mt], Ab + (aRow + mt * 16) * 128 + swA);
#pragma unroll
            for (int np = 0; np < 2; ++np) ldm_x4(b[np], Bb + (bRow + np * 16) * 128 + swB);
#pragma unroll
            for (int mt = 0; mt < 4; ++mt)
#pragma unroll
                for (int nt = 0; nt < 4; ++nt)
                    mma16816h(acc[mt][nt], a[mt], &b[nt >> 1][(nt & 1) * 2]);
        }
    }

#pragma unroll
    for (int nt = 0; nt < 4; ++nt) {
        const int col = bn0 + wn0 + nt * 8 + (lane & 3) * 2;
        const float b0v = bias[col], b1v = bias[col + 1];
#pragma unroll
        for (int mt = 0; mt < 4; ++mt) {
            const int row = bm0 + wm0 + mt * 16 + (lane >> 2);
            float v0 = acc[mt][nt][0] + b0v, v1 = acc[mt][nt][1] + b1v;
            float v2 = acc[mt][nt][2] + b0v, v3 = acc[mt][nt][3] + b1v;
            if (EPI == 1) {
                v0 = softplusf(v0); v1 = softplusf(v1);
                v2 = softplusf(v2); v3 = softplusf(v3);
            }
            if (EPI == 0) {
                float* C = (float*)Cv;
                *reinterpret_cast<float2*>(&C[(size_t)row * Cstride + col])       = make_float2(v0, v1);
                *reinterpret_cast<float2*>(&C[(size_t)(row + 8) * Cstride + col]) = make_float2(v2, v3);
            } else {
                __half* C = (__half*)Cv;
                *reinterpret_cast<__half2*>(&C[(size_t)row * Cstride + col])       = __floats2half2_rn(v0, v1);
                *reinterpret_cast<__half2*>(&C[(size_t)(row + 8) * Cstride + col]) = __floats2half2_rn(v2, v3);
            }
        }
    }
}

// ---------------- B/C projection: BM=64, 128 threads, 2 stages x 12KB = 24KB ----------------
#define BCAST (64 * 128)
#define BCSTG (BCAST + 32 * 128)
#define BCSMEM (2 * BCSTG)
__global__ void __launch_bounds__(128, 1) bc_mma(
    const __half* __restrict__ A, const __half* __restrict__ W,
    const float* __restrict__ Bb, const float* __restrict__ Cb)
{
    extern __shared__ char smraw[];
    const uint32_t sbase = smem_u32(smraw);
    const int tid  = threadIdx.x;
    const int wid  = tid >> 5;
    const int lane = tid & 31;
    const int bm0  = blockIdx.x * 64;
    const size_t lda = (size_t)INNER * 2;

    auto load_stage = [&](int kt, int s) {
        const uint32_t sa = sbase + s * BCSTG;
        const uint32_t sb = sa + BCAST;
#pragma unroll
        for (int i = 0; i < 4; ++i) {
            int idx = tid + i * 128, r = idx >> 3, c = idx & 7;
            cp_async16(sa + r * 128 + ((c ^ (r & 7)) << 4),
                       (const char*)A + (size_t)(bm0 + r) * lda + (size_t)kt * 128 + c * 16);
        }
#pragma unroll
        for (int i = 0; i < 2; ++i) {
            int idx = tid + i * 128, r = idx >> 3, c = idx & 7;
            cp_async16(sb + r * 128 + ((c ^ (r & 7)) << 4),
                       (const char*)W + (size_t)r * lda + (size_t)kt * 128 + c * 16);
        }
    };

    float acc[4][4];
#pragma unroll
    for (int nt = 0; nt < 4; ++nt)
#pragma unroll
        for (int q = 0; q < 4; ++q) acc[nt][q] = 0.f;

    load_stage(0, 0); CP_COMMIT();
    load_stage(1, 1); CP_COMMIT();

    const int aRow = wid * 16 + ((lane >> 3) & 1) * 8 + (lane & 7);
    const int bRow = ((lane >> 4) & 1) * 8 + (lane & 7);
    const int swzX = (lane & 7) << 4;
    const int aKs  = (lane >> 4) << 4;
    const int bKs  = ((lane >> 3) & 1) << 4;

    const int KT = INNER / 64;
    for (int kt = 0; kt < KT; ++kt) {
        const int s = kt & 1;
        CP_WAIT1();
        __syncthreads();

        const uint32_t Ab = sbase + s * BCSTG;
        const uint32_t Bb_ = Ab + BCAST;
#pragma unroll
        for (int ks = 0; ks < 4; ++ks) {
            const int swA = (ks * 32 + aKs) ^ swzX;
            const int swB = (ks * 32 + bKs) ^ swzX;
            uint32_t a[4], b[2][4];
            ldm_x4(a, Ab + aRow * 128 + swA);
#pragma unroll
            for (int np = 0; np < 2; ++np) ldm_x4(b[np], Bb_ + (bRow + np * 16) * 128 + swB);
#pragma unroll
            for (int nt = 0; nt < 4; ++nt)
                mma16816h(acc[nt], a, &b[nt >> 1][(nt & 1) * 2]);
        }
        __syncthreads();
        if (kt + 2 < KT) { load_stage(kt + 2, s); CP_COMMIT(); }
    }

#pragma unroll
    for (int nt = 0; nt < 4; ++nt) {
        const int col = nt * 8 + (lane & 3) * 2;
        const int row = bm0 + wid * 16 + (lane >> 2);
        if (col < 16) {
            const float c0 = Bb[col], c1 = Bb[col + 1];
            *reinterpret_cast<float2*>(&g_Bm[(size_t)row * 16 + col]) =
                make_float2(acc[nt][0] + c0, acc[nt][1] + c1);
            *reinterpret_cast<float2*>(&g_Bm[(size_t)(row + 8) * 16 + col]) =
                make_float2(acc[nt][2] + c0, acc[nt][3] + c1);
        } else {
            const int cc = col - 16;
            const float c0 = Cb[cc], c1 = Cb[cc + 1];
            *reinterpret_cast<float2*>(&g_Cm[(size_t)row * 16 + cc]) =
                make_float2(acc[nt][0] + c0, acc[nt][1] + c1);
            *reinterpret_cast<float2*>(&g_Cm[(size_t)(row + 8) * 16 + cc]) =
                make_float2(acc[nt][2] + c0, acc[nt][3] + c1);
        }
    }
}

// ---------------- conversions: x + all weights in ONE launch ----------------
__global__ void __launch_bounds__(256) cvtall_kernel(
    const float* __restrict__ xs, const float* __restrict__ w1, const float* __restrict__ w2,
    const float* __restrict__ w3, const float* __restrict__ w4, const float* __restrict__ w5,
    __half* __restrict__ ox, __half* __restrict__ o1, __half* __restrict__ o2,
    __half* __restrict__ o3, __half* __restrict__ o4)
{
    const size_t n0 = (size_t)M_TOT * HID / 4;
    const size_t n1 = (size_t)2 * INNER * HID / 4;
    const size_t n2 = (size_t)INNER * INNER / 4;
    const size_t n3 = (size_t)HID * INNER / 4;
    const size_t n4 = (size_t)16 * INNER / 4;
    const size_t nt = n0 + n1 + n2 + n3 + 2 * n4;
    for (size_t i = (size_t)blockIdx.x * 256 + threadIdx.x; i < nt;
         i += (size_t)gridDim.x * 256) {
        const float* src; __half* dst; size_t j;
        if (i < n0)                      { src = xs; dst = ox; j = i; }
        else if (i < n0 + n1)            { src = w1; dst = o1; j = i - n0; }
        else if (i < n0 + n1 + n2)       { src = w2; dst = o2; j = i - n0 - n1; }
        else if (i < n0 + n1 + n2 + n3)  { src = w3; dst = o3; j = i - n0 - n1 - n2; }
        else if (i < n0 + n1 + n2 + n3 + n4) { src = w4; dst = o4; j = i - n0 - n1 - n2 - n3; }
        else { src = w5; dst = o4 + (size_t)16 * INNER; j = i - n0 - n1 - n2 - n3 - n4; }
        float4 v = reinterpret_cast<const float4*>(src)[j];
        ((ushort4*)dst)[j] = make_ushort4(
            __half_as_ushort(__float2half_rn(v.x)), __half_as_ushort(__float2half_rn(v.y)),
            __half_as_ushort(__float2half_rn(v.z)), __half_as_ushort(__float2half_rn(v.w)));
    }
}

// ---------------- causal depthwise conv (K=4) + SiLU, 8 channels/thread ----------------
// block 256 threads (cover INNER=2048 channels), grid (LEN/64, B); 64 rows per CTA.
__global__ void __launch_bounds__(256) conv_silu_kernel(
    const float* __restrict__ conv_w, const float* __restrict__ conv_b)
{
    const int g8 = threadIdx.x;                 // channel group: 8 channels
    const int l0 = blockIdx.x * 64;
    const int b  = blockIdx.y;
    const int d  = g8 * 8;

    float w[4][8], cb[8];
#pragma unroll
    for (int j = 0; j < 8; ++j) {
        w[0][j] = conv_w[(d + j) * 4 + 0];
        w[1][j] = conv_w[(d + j) * 4 + 1];
        w[2][j] = conv_w[(d + j) * 4 + 2];
        w[3][j] = conv_w[(d + j) * 4 + 3];
        cb[j]   = conv_b[d + j];
    }

    const uint4* xp = (const uint4*)g_xph + (size_t)(b * LEN) * (INNER / 8) + g8;
    uint4*       xo = (uint4*)g_xch       + (size_t)(b * LEN) * (INNER / 8) + g8;

    float m[3][8];
#pragma unroll
    for (int t = 0; t < 3; ++t) {
        if (l0 == 0) {
#pragma unroll
            for (int j = 0; j < 8; ++j) m[t][j] = 0.f;
        } else {
            uint4 v = xp[(size_t)(l0 - 3 + t) * (INNER / 8)];
            const __half2* h = (const __half2*)&v;
#pragma unroll
            for (int p = 0; p < 4; ++p) {
                float2 f = __half22float2(h[p]);
                m[t][2 * p] = f.x; m[t][2 * p + 1] = f.y;
            }
        }
    }

    for (int i = 0; i < 64; ++i) {
        uint4 v = xp[(size_t)(l0 + i) * (INNER / 8)];
        const __half2* h = (const __half2*)&v;
        float cur[8];
#pragma unroll
        for (int p = 0; p < 4; ++p) {
            float2 f = __half22float2(h[p]);
            cur[2 * p] = f.x; cur[2 * p + 1] = f.y;
        }
        uint4 o;
        __half2* oh = (__half2*)&o;
#pragma unroll
        for (int p = 0; p < 4; ++p) {
            int j0 = 2 * p, j1 = 2 * p + 1;
            float v0 = w[0][j0] * m[0][j0] + w[1][j0] * m[1][j0] + w[2][j0] * m[2][j0]
                     + w[3][j0] * cur[j0] + cb[j0];
            float v1 = w[0][j1] * m[0][j1] + w[1][j1] * m[1][j1] + w[2][j1] * m[2][j1]
                     + w[3][j1] * cur[j1] + cb[j1];
            oh[p] = __floats2half2_rn(siluf(v0), siluf(v1));
        }
        xo[(size_t)(l0 + i) * (INNER / 8)] = o;
#pragma unroll
        for (int j = 0; j < 8; ++j) { m[0][j] = m[1][j]; m[1][j] = m[2][j]; m[2][j] = cur[j]; }
    }
}

// ---------------- chunked selective scan ----------------
__global__ void __launch_bounds__(128) scanA_kernel(const float* __restrict__ A_log)
{
    __shared__ uint32_t sBh[LC * 8];
    const int d = blockIdx.x * 128 + threadIdx.x;
    const int c = blockIdx.y;
    const int b = blockIdx.z;
    const int base_l = c * LC;
    for (int i = threadIdx.x; i < LC * 8; i += 128) {
        const float2 v = *reinterpret_cast<const float2*>(
            &g_Bm[(size_t)(b * LEN + base_l) * STATE + 2 * i]);
        __half2 hh = __floats2half2_rn(v.x, v.y);
        sBh[i] = *reinterpret_cast<uint32_t*>(&hh);
    }
    __syncthreads();
    __half2 Ar2[8];
#pragma unroll
    for (int i = 0; i < 8; i++)
        Ar2[i] = __floats2half2_rn(-expf(A_log[d * STATE + 2 * i]) * LOG2E,
                                   -expf(A_log[d * STATE + 2 * i + 1]) * LOG2E);
    __half2 h2[8];
#pragma unroll
    for (int i = 0; i < 8; i++) h2[i] = __floats2half2_rn(0.f, 0.f);
    float dtsum = 0.f;
    const __half* dtp = g_dth + (size_t)(b * LEN + base_l) * INNER + d;
    const __half* xcp = g_xch + (size_t)(b * LEN + base_l) * INNER + d;
    for (int l = 0; l < LC; ++l) {
        __half dtv = dtp[(size_t)l * INNER];
        __half xv  = xcp[(size_t)l * INNER];
        dtsum += __half2float(dtv);
        __half2 dt2  = __half2half2(dtv);
        __half2 dtx2 = __half2half2(__hmul(dtv, xv));
#pragma unroll
        for (int i = 0; i < 8; i++) {
            __half2 dA  = hexp2_x2(__hmul2(dt2, Ar2[i]));
            __half2 inc = __hmul2(*reinterpret_cast<const __half2*>(&sBh[l * 8 + i]), dtx2);
            h2[i] = __hfma2(dA, h2[i], inc);
        }
    }
    size_t sb2 = (size_t)(b * NC + c) * 8 * INNER + d;
#pragma unroll
    for (int i = 0; i < 8; i++)
        g_S2[sb2 + (size_t)i * INNER] = *reinterpret_cast<uint32_t*>(&h2[i]);
    g_dts[(size_t)(b * NC + c) * INNER + d] = dtsum;
}

__global__ void __launch_bounds__(256) scanB_kernel(const float* __restrict__ A_log)
{
    int g = blockIdx.x * 256 + threadIdx.x;
    int i = g & 7;
    int t = g >> 3;
    int b = t / INNER;
    int d = t - b * INNER;
    float Ar0 = -expf(A_log[d * STATE + 2 * i]);
    float Ar1 = -expf(A_log[d * STATE + 2 * i + 1]);
    float h0 = 0.f, h1 = 0.f;
    for (int c = 0; c < NC; ++c) {
        size_t hb = (size_t)(b * NC + c) * STATE * INNER + d;
        g_H0[hb + (size_t)(2 * i) * INNER]     = h0;
        g_H0[hb + (size_t)(2 * i + 1) * INNER] = h1;
        float ds = g_dts[(size_t)(b * NC + c) * INNER + d];
        uint32_t sv = g_S2[(size_t)(b * NC + c) * 8 * INNER + (size_t)i * INNER + d];
        float2 svf = __half22float2(*reinterpret_cast<__half2*>(&sv));
        h0 = __expf(Ar0 * ds) * h0 + svf.x;
        h1 = __expf(Ar1 * ds) * h1 + svf.y;
    }
}

__global__ void __launch_bounds__(128) scanC_kernel(
    const float* __restrict__ A_log, const float* __restrict__ Dv)
{
    __shared__ uint32_t sBh[LC * 8];
    __shared__ uint32_t sCh[LC * 8];
    const int d = blockIdx.x * 128 + threadIdx.x;
    const int c = blockIdx.y;
    const int b = blockIdx.z;
    const int base_l = c * LC;
    for (int i = threadIdx.x; i < LC * 8; i += 128) {
        const float2 vb = *reinterpret_cast<const float2*>(
            &g_Bm[(size_t)(b * LEN + base_l) * STATE + 2 * i]);
        const float2 vc = *reinterpret_cast<const float2*>(
            &g_Cm[(size_t)(b * LEN + base_l) * STATE + 2 * i]);
        __half2 hb = __floats2half2_rn(vb.x, vb.y);
        __half2 hc = __floats2half2_rn(vc.x, vc.y);
        sBh[i] = *reinterpret_cast<uint32_t*>(&hb);
        sCh[i] = *reinterpret_cast<uint32_t*>(&hc);
    }
    __syncthreads();
    __half2 Ar2[8];
#pragma unroll
    for (int i = 0; i < 8; i++)
        Ar2[i] = __floats2half2_rn(-expf(A_log[d * STATE + 2 * i]) * LOG2E,
                                   -expf(A_log[d * STATE + 2 * i + 1]) * LOG2E);
    const float Dd = Dv[d];
    __half2 h2[8];
    size_t ob = (size_t)(b * NC + c) * STATE * INNER + d;
#pragma unroll
    for (int i = 0; i < 8; i++)
        h2[i] = __floats2half2_rn(g_H0[ob + (size_t)(2 * i) * INNER],
                                  g_H0[ob + (size_t)(2 * i + 1) * INNER]);
    const __half* dtp = g_dth + (size_t)(b * LEN + base_l) * INNER + d;
    const __half* xcp = g_xch + (size_t)(b * LEN + base_l) * INNER + d;
    const __half* zp  = g_zh  + (size_t)(b * LEN + base_l) * INNER + d;
    __half* y0p = g_y0h + (size_t)(b * LEN + base_l) * INNER + d;
    for (int l = 0; l < LC; ++l) {
        __half dtv = dtp[(size_t)l * INNER];
        __half xv  = xcp[(size_t)l * INNER];
        float zv   = __half2float(zp[(size_t)l * INNER]);
        __half2 dt2  = __half2half2(dtv);
        __half2 dtx2 = __half2half2(__hmul(dtv, xv));
        __half2 acc2 = __floats2half2_rn(0.f, 0.f);
#pragma unroll
        for (int i = 0; i < 8; i++) {
            __half2 dA  = hexp2_x2(__hmul2(dt2, Ar2[i]));
            __half2 inc = __hmul2(*reinterpret_cast<const __half2*>(&sBh[l * 8 + i]), dtx2);
            h2[i] = __hfma2(dA, h2[i], inc);
            acc2  = __hfma2(*reinterpret_cast<const __half2*>(&sCh[l * 8 + i]), h2[i], acc2);
        }
        float acc = __low2float(acc2) + __high2float(acc2) + Dd * __half2float(xv);
        y0p[(size_t)l * INNER] = __float2half_rn(acc * siluf(zv));
    }
}

// ---------------- launch ----------------
extern "C" void kernel_launch(void* const* d_in, const int* in_sizes, int n_in,
                              void* d_out, int out_size)
{
    const float* x      = (const float*)d_in[0];
    const float* in_w   = (const float*)d_in[1];
    const float* in_b   = (const float*)d_in[2];
    const float* conv_w = (const float*)d_in[3];
    const float* conv_b = (const float*)d_in[4];
    const float* dt_w   = (const float*)d_in[5];
    const float* dt_b   = (const float*)d_in[6];
    const float* A_log  = (const float*)d_in[7];
    const float* B_w    = (const float*)d_in[8];
    const float* B_b    = (const float*)d_in[9];
    const float* C_w    = (const float*)d_in[10];
    const float* C_b    = (const float*)d_in[11];
    const float* Dv     = (const float*)d_in[12];
    const float* out_w  = (const float*)d_in[13];
    const float* out_b  = (const float*)d_in[14];
    float* out = (float*)d_out;

    __half *x0h, *wh, *dtwh, *xch, *y0h, *owh, *wbch, *zh, *dth, *xph;
    cudaGetSymbolAddress((void**)&xph, g_xph);
    cudaGetSymbolAddress((void**)&x0h, g_x0h);
    cudaGetSymbolAddress((void**)&wh, g_wh);
    cudaGetSymbolAddress((void**)&dtwh, g_dtwh);
    cudaGetSymbolAddress((void**)&xch, g_xch);
    cudaGetSymbolAddress((void**)&y0h, g_y0h);
    cudaGetSymbolAddress((void**)&owh, g_owh);
    cudaGetSymbolAddress((void**)&wbch, g_wbch);
    cudaGetSymbolAddress((void**)&zh, g_zh);
    cudaGetSymbolAddress((void**)&dth, g_dth);

    cudaFuncSetAttribute(gemm_mma<1>, cudaFuncAttributeMaxDynamicSharedMemorySize, GSMEM);
    cudaFuncSetAttribute(gemm_mma<0>, cudaFuncAttributeMaxDynamicSharedMemorySize, GSMEM);
    cudaFuncSetAttribute(gemm_mma<2>, cudaFuncAttributeMaxDynamicSharedMemorySize, GSMEM);
    cudaFuncSetAttribute(bc_mma, cudaFuncAttributeMaxDynamicSharedMemorySize, BCSMEM);

    static cudaStream_t s1 = nullptr;
    static cudaEvent_t evA = nullptr, evZ = nullptr, evC = nullptr, evB = nullptr;
    if (s1 == nullptr) {
        cudaStreamCreateWithFlags(&s1, cudaStreamNonBlocking);
        cudaEventCreateWithFlags(&evA, cudaEventDisableTiming);
        cudaEventCreateWithFlags(&evZ, cudaEventDisableTiming);
        cudaEventCreateWithFlags(&evC, cudaEventDisableTiming);
        cudaEventCreateWithFlags(&evB, cudaEventDisableTiming);
    }

    // 0) all fp16 conversions in one launch
    cvtall_kernel<<<2048, 256>>>(x, in_w, dt_w, out_w, B_w, C_w,
                                 x0h, wh, dtwh, owh, wbch);
    cudaEventRecord(evA, 0);

    // fork: z half of in-proj on s1
    cudaStreamWaitEvent(s1, evA, 0);
    gemm_mma<2><<<dim3(INNER / GBN, M_TOT / GBM), 256, GSMEM, s1>>>(
        x0h, wh + (size_t)INNER * HID, in_b + INNER, zh, INNER, HID);
    cudaEventRecord(evZ, s1);

    // 1) in-proj x_part half -> fp16                       (16384 x 2048 x 1024)
    gemm_mma<2><<<dim3(INNER / GBN, M_TOT / GBM), 256, GSMEM>>>(
        x0h, wh, in_b, xph, INNER, HID);

    // 2) conv + silu (uint4 vectorized, 8 ch/thread)
    conv_silu_kernel<<<dim3(LEN / 64, B_SZ), 256>>>(conv_w, conv_b);
    cudaEventRecord(evC, 0);

    // 3) B/C projections on s1, co-residing with the dt GEMM (24KB CTAs)
    cudaStreamWaitEvent(s1, evC, 0);
    bc_mma<<<M_TOT / 64, 128, BCSMEM, s1>>>(xch, wbch, B_b, C_b);
    cudaEventRecord(evB, s1);

    // 4) dt = softplus(xconv @ dt_w^T + dt_b) -> fp16      (16384 x 2048 x 2048)
    gemm_mma<1><<<dim3(INNER / GBN, M_TOT / GBM), 256, GSMEM>>>(
        xch, dtwh, dt_b, dth, INNER, INNER);

    // 5) chunked selective scan + gating
    cudaStreamWaitEvent(0, evB, 0);
    scanA_kernel<<<dim3(INNER / 128, NC, B_SZ), 128>>>(A_log);
    scanB_kernel<<<(B_SZ * INNER * 8) / 256, 256>>>(A_log);
    cudaStreamWaitEvent(0, evZ, 0);
    scanC_kernel<<<dim3(INNER / 128, NC, B_SZ), 128>>>(A_log, Dv);

    // 6) out-proj: out = y @ out_w^T + out_b               (16384 x 1024 x 2048)
    gemm_mma<0><<<dim3(HID / GBN, M_TOT / GBM), 256, GSMEM>>>(
        y0h, owh, out_b, out, HID, INNER);
}